// round 9
// baseline (speedup 1.0000x reference)
#include <cuda_runtime.h>
#include <cuda_bf16.h>
#include <math.h>
#include <cstdint>

#define HW      16384
#define BATCH   4
#define MTOK    256
#define HD      256
#define INNER   128
#define DH      64

#define TWO_PI 6.2831853071795864769f

typedef unsigned long long u64;

// ---- packed f32x2 helpers (sm_100+) ---------------------------------------
__device__ __forceinline__ u64 pack1(float v) {
    u64 r; asm("mov.b64 %0, {%1, %2};" : "=l"(r) : "f"(v), "f"(v)); return r;
}
__device__ __forceinline__ u64 ffma2(u64 a, u64 b, u64 c) {
    u64 d; asm("fma.rn.f32x2 %0, %1, %2, %3;" : "=l"(d) : "l"(a), "l"(b), "l"(c)); return d;
}
__device__ __forceinline__ u64 fmul2(u64 a, u64 b) {
    u64 d; asm("mul.rn.f32x2 %0, %1, %2;" : "=l"(d) : "l"(a), "l"(b)); return d;
}
__device__ __forceinline__ u64 fadd2(u64 a, u64 b) {
    u64 d; asm("add.rn.f32x2 %0, %1, %2;" : "=l"(d) : "l"(a), "l"(b)); return d;
}
__device__ __forceinline__ float2 unpack2(u64 v) {
    float2 f; asm("mov.b64 {%0, %1}, %2;" : "=f"(f.x), "=f"(f.y) : "l"(v)); return f;
}

// ---- cp.async helpers ------------------------------------------------------
__device__ __forceinline__ void cpa16(void* dst, const void* src) {
    unsigned d = (unsigned)__cvta_generic_to_shared(dst);
    asm volatile("cp.async.ca.shared.global [%0], [%1], 16;" :: "r"(d), "l"(src));
}
#define CPA_COMMIT() asm volatile("cp.async.commit_group;" ::: "memory")
#define CPA_WAIT0()  asm volatile("cp.async.wait_group 0;"  ::: "memory")
#define CPA_WAIT1()  asm volatile("cp.async.wait_group 1;"  ::: "memory")

// ---- mma.sync / ldmatrix helpers (baseline PTX, sm_80+) --------------------
__device__ __forceinline__ uint32_t smem_to_u32(const void* p) {
    uint32_t a;
    asm("{ .reg .u64 t; cvta.to.shared.u64 t, %1; cvt.u32.u64 %0, t; }" : "=r"(a) : "l"(p));
    return a;
}
__device__ __forceinline__ void ldsm4(uint32_t* r, uint32_t addr) {
    asm volatile("ldmatrix.sync.aligned.m8n8.x4.shared.b16 {%0,%1,%2,%3}, [%4];"
        : "=r"(r[0]), "=r"(r[1]), "=r"(r[2]), "=r"(r[3]) : "r"(addr));
}
__device__ __forceinline__ void ldsm2(uint32_t* r, uint32_t addr) {
    asm volatile("ldmatrix.sync.aligned.m8n8.x2.shared.b16 {%0,%1}, [%2];"
        : "=r"(r[0]), "=r"(r[1]) : "r"(addr));
}
__device__ __forceinline__ void mma16816(float* d, const uint32_t* a, const uint32_t* b) {
    asm volatile("mma.sync.aligned.m16n8k16.row.col.f32.bf16.bf16.f32 "
        "{%0,%1,%2,%3}, {%4,%5,%6,%7}, {%8,%9}, {%0,%1,%2,%3};"
        : "+f"(d[0]), "+f"(d[1]), "+f"(d[2]), "+f"(d[3])
        : "r"(a[0]), "r"(a[1]), "r"(a[2]), "r"(a[3]), "r"(b[0]), "r"(b[1]));
}

__device__ __forceinline__ int swz(int b) { return b ^ ((b >> 3) & 0x70); }

__device__ __forceinline__ void split2(float v0, float v1, uint32_t& hi, uint32_t& lo) {
    __nv_bfloat16 h0 = __float2bfloat16(v0), h1 = __float2bfloat16(v1);
    float r0 = v0 - __bfloat162float(h0);
    float r1 = v1 - __bfloat162float(h1);
    __nv_bfloat16 l0 = __float2bfloat16(r0), l1 = __float2bfloat16(r1);
    hi = ((uint32_t)__bfloat16_as_ushort(h1) << 16) | __bfloat16_as_ushort(h0);
    lo = ((uint32_t)__bfloat16_as_ushort(l1) << 16) | __bfloat16_as_ushort(l0);
}
__device__ __forceinline__ float bfu(unsigned short u) {
    __nv_bfloat16_raw r; r.x = u;
    return __bfloat162float(__nv_bfloat16(r));
}

// ---------------- scratch ---------------------------------------------------
__device__ float g_q  [HW * INNER];
__device__ float g_h0 [HW * HD];
__device__ float g_h1 [HW * HD];
__device__ float g_t  [HW];
__device__ float g_k  [BATCH * 2 * MTOK * DH];
__device__ float g_v  [BATCH * 2 * MTOK * DH];
__device__ float g_o  [BATCH * HW * INNER];
// pre-split, pre-swizzled bf16 weight images:
// 14 k-chunks (tooW:2, modW0:4, modW1:4, hvW0:4) x 2 n-halves x 32KB (hi16K+lo16K)
__device__ __align__(128) uint8_t g_WB[14 * 2 * 32768];

// ============================================================================
// K0: prep weights -> split bf16 [n][k] chunk images with SW128 swizzle.
// ============================================================================
__global__ void k0_prepw(const float* __restrict__ tooW,
                         const float* __restrict__ modW0,
                         const float* __restrict__ modW1,
                         const float* __restrict__ hvW0)
{
    int m = blockIdx.y;           // matrix 0..3
    int k = blockIdx.x;           // 0..255
    int n = threadIdx.x;          // 0..255
    int Km = (m == 0) ? 128 : 256;
    if (k >= Km) return;
    const float* W = (m == 0) ? tooW : (m == 1) ? modW0 : (m == 2) ? modW1 : hvW0;
    float v = W[k * 256 + n];
    __nv_bfloat16 h = __float2bfloat16(v);
    float rres = v - __bfloat162float(h);
    __nv_bfloat16 l = __float2bfloat16(rres);
    const int mstart = (m == 0) ? 0 : (m == 1) ? 2 : (m == 2) ? 6 : 10;
    uint8_t* img = g_WB + ((size_t)(mstart + (k >> 6)) * 2 + (n >> 7)) * 32768;
    int b  = (n & 127) * 128 + (k & 63) * 2;
    int sw = swz(b);
    *(__nv_bfloat16*)(img + sw)         = h;
    *(__nv_bfloat16*)(img + 16384 + sw) = l;
}

// ============================================================================
// K1: grid-shared features. 16 rows / block, 256 threads.
// ============================================================================
__global__ void k1_grid(const float* __restrict__ coords,
                        const float* __restrict__ Bq,
                        const float* __restrict__ Bl0,
                        const float* __restrict__ Bl1,
                        const float* __restrict__ qW,  const float* __restrict__ qb,
                        const float* __restrict__ toqW,
                        const float* __restrict__ bwW0, const float* __restrict__ bwb0,
                        const float* __restrict__ bwW1, const float* __restrict__ bwb1)
{
    __shared__ float four[3][16][64];
    __shared__ float xq[16][256];
    const int tid  = threadIdx.x;
    const int base = blockIdx.x * 16;

    for (int it = tid; it < 3 * 16 * 32; it += 256) {
        int mat = it >> 9;
        int rem = it & 511;
        int r   = rem >> 5;
        int i   = rem & 31;
        float x = coords[(base + r) * 2 + 0];
        float y = coords[(base + r) * 2 + 1];
        const float* Bm = (mat == 0) ? Bq : (mat == 1 ? Bl0 : Bl1);
        float proj = TWO_PI * (x * Bm[i * 2] + y * Bm[i * 2 + 1]);
        float s, c;
        sincosf(proj, &s, &c);
        four[mat][r][i]      = c;
        four[mat][r][i + 32] = s;
    }
    if (tid < 16) {
        float x = coords[(base + tid) * 2 + 0];
        float y = coords[(base + tid) * 2 + 1];
        int row = (int)(x * 16.0f); row = min(max(row, 0), 15);
        int col = (int)(y * 16.0f); col = min(max(col, 0), 15);
        g_t[base + tid] = (float)(row * 16 + col) * (1.0f / 256.0f);
    }
    __syncthreads();

    {
        const int j = tid;
        float acc[16];
#pragma unroll
        for (int r = 0; r < 16; r++) acc[r] = 0.f;
        for (int k = 0; k < 64; k++) {
            float w = qW[k * 256 + j];
#pragma unroll
            for (int r = 0; r < 16; r++) acc[r] = fmaf(four[0][r][k], w, acc[r]);
        }
        float b = qb[j];
#pragma unroll
        for (int r = 0; r < 16; r++) xq[r][j] = fmaxf(acc[r] + b, 0.f);
    }
    __syncthreads();

    {
        const int j    = tid & 127;
        const int half = tid >> 7;
        float acc[8];
#pragma unroll
        for (int r = 0; r < 8; r++) acc[r] = 0.f;
        for (int k = 0; k < 256; k++) {
            float w = toqW[k * 128 + j];
#pragma unroll
            for (int r = 0; r < 8; r++) acc[r] = fmaf(xq[half * 8 + r][k], w, acc[r]);
        }
#pragma unroll
        for (int r = 0; r < 8; r++) g_q[(base + half * 8 + r) * 128 + j] = acc[r];
    }

    {
        const int j = tid;
        float a0[16], a1[16];
#pragma unroll
        for (int r = 0; r < 16; r++) { a0[r] = 0.f; a1[r] = 0.f; }
        for (int k = 0; k < 64; k++) {
            float w0 = bwW0[k * 256 + j];
            float w1 = bwW1[k * 256 + j];
#pragma unroll
            for (int r = 0; r < 16; r++) {
                a0[r] = fmaf(four[1][r][k], w0, a0[r]);
                a1[r] = fmaf(four[2][r][k], w1, a1[r]);
            }
        }
        float b0 = bwb0[j], b1 = bwb1[j];
#pragma unroll
        for (int r = 0; r < 16; r++) {
            g_h0[(base + r) * 256 + j] = fmaxf(a0[r] + b0, 0.f);
            g_h1[(base + r) * 256 + j] = fmaxf(a1[r] + b1, 0.f);
        }
    }
}

// ============================================================================
// K2: kv = tokens @ tokvW -> per-head k / v.
// ============================================================================
__global__ void k2_kv(const float* __restrict__ tokens,
                      const float* __restrict__ tokvW)
{
    __shared__ float tok[16][256];
    const int tile = blockIdx.x;
    const int b    = blockIdx.y;
    const int tid  = threadIdx.x;

    const float* tb = tokens + (b * MTOK + tile * 16) * 256;
    for (int i = tid; i < 16 * 256; i += 256) tok[i >> 8][i & 255] = tb[i];
    __syncthreads();

    const int j = tid;
    float acc[16];
#pragma unroll
    for (int r = 0; r < 16; r++) acc[r] = 0.f;
    for (int k = 0; k < 256; k++) {
        float w = tokvW[k * 256 + j];
#pragma unroll
        for (int r = 0; r < 16; r++) acc[r] = fmaf(tok[r][k], w, acc[r]);
    }
#pragma unroll
    for (int r = 0; r < 16; r++) {
        int m = tile * 16 + r;
        if (j < 128) {
            int h = j >> 6, d = j & 63;
            g_k[((b * 2 + h) * MTOK + m) * DH + d] = acc[r];
        } else {
            int j2 = j - 128;
            int h = j2 >> 6, d = j2 & 63;
            g_v[((b * 2 + h) * MTOK + m) * DH + d] = acc[r];
        }
    }
}

// ============================================================================
// K3: attention. 512 threads/block (16 warps); 2 lanes per query row
// (32 dims each), shfl_xor combines the QK partial. q pre-scaled by 1/8.
// ============================================================================
__global__ void __launch_bounds__(512) k3_attn()
{
    extern __shared__ float sm[];
    float* ks = sm;                 // [256][64]
    float* vs = sm + MTOK * DH;

    const int h   = blockIdx.y;
    const int b   = blockIdx.z;
    const int tid = threadIdx.x;

    const float* kg = g_k + (b * 2 + h) * MTOK * DH;
    const float* vg = g_v + (b * 2 + h) * MTOK * DH;
    for (int i = tid * 4; i < MTOK * DH; i += 512 * 4) {
        *(float4*)&ks[i] = *(const float4*)&kg[i];
        *(float4*)&vs[i] = *(const float4*)&vg[i];
    }
    __syncthreads();

    const int pair = tid & 1;               // which 32-dim half
    const int row  = blockIdx.x * 256 + (tid >> 1);
    const int dofs = pair * 32;

    u64 q2[16];
    {
        const u64 scale = pack1(0.125f);
        const ulonglong2* qp = (const ulonglong2*)(g_q + row * 128 + h * 64 + dofs);
#pragma unroll
        for (int i = 0; i < 8; i++) {
            ulonglong2 t = qp[i];
            q2[2*i]   = fmul2(t.x, scale);
            q2[2*i+1] = fmul2(t.y, scale);
        }
    }
    const float tt = g_t[row];

    u64 acc[16];
#pragma unroll
    for (int i = 0; i < 16; i++) acc[i] = 0ULL;
    float Mx = -1e30f, S = 0.f;

    for (int m = 0; m < 256; m++) {
        const ulonglong2* kp = (const ulonglong2*)&ks[m * 64 + dofs];
        u64 sA = 0, sB = 0, sC = 0, sD = 0;
#pragma unroll
        for (int i = 0; i < 8; i += 2) {
            ulonglong2 k0 = kp[i];
            ulonglong2 k1 = kp[i + 1];
            sA = ffma2(q2[2*i    ], k0.x, sA);
            sB = ffma2(q2[2*i + 1], k0.y, sB);
            sC = ffma2(q2[2*i + 2], k1.x, sC);
            sD = ffma2(q2[2*i + 3], k1.y, sD);
        }
        float2 sf = unpack2(fadd2(fadd2(sA, sB), fadd2(sC, sD)));
        float part = sf.x + sf.y;
        part += __shfl_xor_sync(0xffffffffu, part, 1);
        float pos  = ((float)m + 0.5f) * (1.0f / 256.0f);
        float diff = tt - pos;
        float s = part - 10.0f * diff * diff;

        if (s > Mx) {
            float corr = __expf(Mx - s);
            S *= corr;
            u64 cp = pack1(corr);
#pragma unroll
            for (int i = 0; i < 16; i++) acc[i] = fmul2(acc[i], cp);
            Mx = s;
        }
        float p = __expf(s - Mx);
        S += p;
        u64 pp = pack1(p);
        const ulonglong2* vp = (const ulonglong2*)&vs[m * 64 + dofs];
#pragma unroll
        for (int i = 0; i < 8; i++) {
            ulonglong2 v0 = vp[i];
            acc[2*i    ] = ffma2(pp, v0.x, acc[2*i    ]);
            acc[2*i + 1] = ffma2(pp, v0.y, acc[2*i + 1]);
        }
    }

    float inv = 1.0f / S;
    float* og = g_o + ((size_t)b * HW + row) * 128 + h * 64 + dofs;
#pragma unroll
    for (int i = 0; i < 16; i++) {
        float2 f = unpack2(acc[i]);
        float2 o2; o2.x = f.x * inv; o2.y = f.y * inv;
        *(float2*)&og[2 * i] = o2;
    }
}

// ============================================================================
// K5 mma.sync: fused MLP chain via split-bf16 tensor-core GEMMs.
// CTA = 64 rows, 256 threads (8 warps = 2M x 4N). Warp tile 32x32 per N-pass.
// ============================================================================
// smem layout (bytes)
#define SMB_MOD   0          // A buffer: mod (hi 32K @0, lo 32K @32768)
#define SMB_X     65536      // A buffer: o, then m0/x
#define SMB_B     131072     // 2 x 32KB B chunk buffers (hi 16K + lo 16K each)
#define SMB_CONST 196608     // toob|modb0|modb1|hvb0|OW0|OW1 (2560 floats)
#define SMB_PSM   206848     // 64 x 3 fp32 projection accum
#define SMB_TOTAL 207616

__device__ __forceinline__ void run_gemm(char* smem, uint32_t sb, int Aoff,
                                         int mstart, int nch, int pass,
                                         int m0w, int n0p, int tid, int l,
                                         float* acc)
{
    {
        const uint8_t* src = g_WB + ((size_t)mstart * 2 + pass) * 32768;
        char* dst = smem + SMB_B;
#pragma unroll
        for (int it = 0; it < 8; it++) {
            int i = (it * 256 + tid) * 16;
            cpa16(dst + i, src + i);
        }
        CPA_COMMIT();
    }
    for (int c = 0; c < nch; c++) {
        if (c + 1 < nch) {
            const uint8_t* src = g_WB + ((size_t)(mstart + c + 1) * 2 + pass) * 32768;
            char* dst = smem + SMB_B + ((c + 1) & 1) * 32768;
#pragma unroll
            for (int it = 0; it < 8; it++) {
                int i = (it * 256 + tid) * 16;
                cpa16(dst + i, src + i);
            }
            CPA_COMMIT();
            CPA_WAIT1();
        } else {
            CPA_WAIT0();
        }
        __syncthreads();

        const uint32_t bB   = sb + SMB_B + (c & 1) * 32768;
        const uint32_t bAhi = sb + Aoff + c * 8192;
        const uint32_t bAlo = bAhi + 32768;

#pragma unroll
        for (int t4 = 0; t4 < 4; t4++) {
            uint32_t ahi[2][4], alo[2][4];
            const int arow = l & 15;
            const int akb  = t4 * 32 + (l >> 4) * 16;
#pragma unroll
            for (int mt = 0; mt < 2; mt++) {
                int ab = (m0w + mt * 16 + arow) * 128 + akb;
                int sw = swz(ab);
                ldsm4(ahi[mt], bAhi + sw);
                ldsm4(alo[mt], bAlo + sw);
            }
#pragma unroll
            for (int nt = 0; nt < 4; nt++) {
                const int nrow = n0p + nt * 8 + (l & 7);
                int bb = nrow * 128 + t4 * 32 + ((l >> 3) & 1) * 16;
                int sw = swz(bb);
                uint32_t bhi[2], blo[2];
                ldsm2(bhi, bB + sw);
                ldsm2(blo, bB + 16384 + sw);
                float* a0 = acc + (0 * 4 + nt) * 4;
                float* a1 = acc + (1 * 4 + nt) * 4;
                mma16816(a0, ahi[0], bhi);
                mma16816(a1, ahi[1], bhi);
                mma16816(a0, ahi[0], blo);
                mma16816(a1, ahi[1], blo);
                mma16816(a0, alo[0], bhi);
                mma16816(a1, alo[1], bhi);
            }
        }
        __syncthreads();
    }
}

__global__ void __launch_bounds__(256, 1) k5_mma(
    const float* __restrict__ toob,
    const float* __restrict__ modb0, const float* __restrict__ modb1,
    const float* __restrict__ hvb0,
    const float* __restrict__ outW0, const float* __restrict__ outb0,
    const float* __restrict__ outW1, const float* __restrict__ outb1,
    float* __restrict__ out)
{
    extern __shared__ char smem[];
    const uint32_t sb = smem_to_u32(smem);
    const int tid  = threadIdx.x;
    const int w    = tid >> 5;
    const int l    = tid & 31;
    const int m0w  = 32 * (w & 1);
    const int n0p  = 32 * (w >> 1);
    const int base = blockIdx.x * 64;
    const int hb   = base & (HW - 1);

    float* sC    = (float*)(smem + SMB_CONST);
    float* sToob = sC;
    float* sMb0  = sC + 256;
    float* sMb1  = sC + 512;
    float* sHvb  = sC + 768;
    float* sOW0  = sC + 1024;
    float* sOW1  = sC + 1792;
    float* pSM   = (float*)(smem + SMB_PSM);

    for (int i = tid; i < 256; i += 256) {
        sToob[i] = toob[i];
        sMb0[i]  = modb0[i];
        sMb1[i]  = modb1[i];
        sHvb[i]  = hvb0[i];
    }
    for (int i = tid; i < 768; i += 256) {
        sOW0[i] = outW0[i];
        sOW1[i] = outW1[i];
    }
    for (int i = tid; i < 192; i += 256) pSM[i] = 0.f;

    for (int i = tid; i < 64 * 64; i += 256) {
        int r  = i >> 6;
        int kp = i & 63;
        int k  = kp * 2;
        float2 v = *(const float2*)&g_o[((size_t)(base + r)) * 128 + k];
        uint32_t hi, lo;
        split2(v.x, v.y, hi, lo);
        int kc = k >> 6;
        int b  = r * 128 + (k & 63) * 2;
        int sw = swz(b);
        *(uint32_t*)(smem + SMB_X + kc * 8192 + sw)         = hi;
        *(uint32_t*)(smem + SMB_X + 32768 + kc * 8192 + sw) = lo;
    }
    __syncthreads();

    float acc[32];
    float p[12];
#pragma unroll
    for (int i = 0; i < 12; i++) p[i] = 0.f;

    // ================= stage 0: mod = o @ tooW + toob -> SMB_MOD =============
#pragma unroll 1
    for (int pass = 0; pass < 2; pass++) {
#pragma unroll
        for (int i = 0; i < 32; i++) acc[i] = 0.f;
        run_gemm(smem, sb, SMB_X, 0, 2, pass, m0w, n0p, tid, l, acc);
#pragma unroll
        for (int mt = 0; mt < 2; mt++)
#pragma unroll
        for (int nt = 0; nt < 4; nt++) {
            float* a = acc + (mt * 4 + nt) * 4;
            int c0 = pass * 128 + n0p + nt * 8 + (l & 3) * 2;
            int rA = m0w + mt * 16 + (l >> 2);
            float b0 = sToob[c0], b1 = sToob[c0 + 1];
            int kc = c0 >> 6;
            int bby = (c0 & 63) * 2;
            uint32_t hi, lo;
            split2(a[0] + b0, a[1] + b1, hi, lo);
            int sw = swz(rA * 128 + bby);
            *(uint32_t*)(smem + SMB_MOD + kc * 8192 + sw)         = hi;
            *(uint32_t*)(smem + SMB_MOD + 32768 + kc * 8192 + sw) = lo;
            split2(a[2] + b0, a[3] + b1, hi, lo);
            sw = swz((rA + 8) * 128 + bby);
            *(uint32_t*)(smem + SMB_MOD + kc * 8192 + sw)         = hi;
            *(uint32_t*)(smem + SMB_MOD + 32768 + kc * 8192 + sw) = lo;
        }
    }
    __syncthreads();

    // ================= stage 1: m0 = relu(h0 + mod@modW0 + b) -> SMB_X =======
#pragma unroll 1
    for (int pass = 0; pass < 2; pass++) {
#pragma unroll
        for (int i = 0; i < 32; i++) acc[i] = 0.f;
        run_gemm(smem, sb, SMB_MOD, 2, 4, pass, m0w, n0p, tid, l, acc);
#pragma unroll
        for (int mt = 0; mt < 2; mt++)
#pragma unroll
        for (int nt = 0; nt < 4; nt++) {
            float* a = acc + (mt * 4 + nt) * 4;
            int c0 = pass * 128 + n0p + nt * 8 + (l & 3) * 2;
            int rA = m0w + mt * 16 + (l >> 2);
            float b0 = sMb0[c0], b1 = sMb0[c0 + 1];
            int kc = c0 >> 6;
            int bby = (c0 & 63) * 2;
#pragma unroll
            for (int half = 0; half < 2; half++) {
                int r = rA + half * 8;
                float2 h0 = *(const float2*)&g_h0[((size_t)(hb + r)) * 256 + c0];
                float v0 = fmaxf(h0.x + a[half * 2 + 0] + b0, 0.f);
                float v1 = fmaxf(h0.y + a[half * 2 + 1] + b1, 0.f);
                int slot = mt * 2 + half;
                p[slot * 3 + 0] = fmaf(v0, sOW0[c0 * 3 + 0], fmaf(v1, sOW0[c0 * 3 + 3], p[slot * 3 + 0]));
                p[slot * 3 + 1] = fmaf(v0, sOW0[c0 * 3 + 1], fmaf(v1, sOW0[c0 * 3 + 4], p[slot * 3 + 1]));
                p[slot * 3 + 2] = fmaf(v0, sOW0[c0 * 3 + 2], fmaf(v1, sOW0[c0 * 3 + 5], p[slot * 3 + 2]));
                uint32_t hi, lo;
                split2(v0, v1, hi, lo);
                int sw = swz(r * 128 + bby);
                *(uint32_t*)(smem + SMB_X + kc * 8192 + sw)         = hi;
                *(uint32_t*)(smem + SMB_X + 32768 + kc * 8192 + sw) = lo;
            }
        }
    }
    __syncthreads();

    // ================= stage 2: x = m0 + relu(h1 + mod@modW1 + b) -> SMB_X ===
#pragma unroll 1
    for (int pass = 0; pass < 2; pass++) {
#pragma unroll
        for (int i = 0; i < 32; i++) acc[i] = 0.f;
        run_gemm(smem, sb, SMB_MOD, 6, 4, pass, m0w, n0p, tid, l, acc);
#pragma unroll
        for (int mt = 0; mt < 2; mt++)
#pragma unroll
        for (int nt = 0; nt < 4; nt++) {
            float* a = acc + (mt * 4 + nt) * 4;
            int c0 = pass * 128 + n0p + nt * 8 + (l & 3) * 2;
            int rA = m0w + mt * 16 + (l >> 2);
            float b0 = sMb1[c0], b1 = sMb1[c0 + 1];
            int kc = c0 >> 6;
            int bby = (c0 & 63) * 2;
#pragma unroll
            for (int half = 0; half < 2; half++) {
                int r = rA + half * 8;
                float2 h1 = *(const float2*)&g_h1[((size_t)(hb + r)) * 256 + c0];
                float m10 = fmaxf(h1.x + a[half * 2 + 0] + b0, 0.f);
                float m11 = fmaxf(h1.y + a[half * 2 + 1] + b1, 0.f);
                int sw = swz(r * 128 + bby);
                uint32_t mh = *(uint32_t*)(smem + SMB_X + kc * 8192 + sw);
                uint32_t ml = *(uint32_t*)(smem + SMB_X + 32768 + kc * 8192 + sw);
                float x0 = bfu((unsigned short)(mh & 0xffff)) + bfu((unsigned short)(ml & 0xffff)) + m10;
                float x1 = bfu((unsigned short)(mh >> 16))    + bfu((unsigned short)(ml >> 16))    + m11;
                uint32_t hi, lo;
                split2(x0, x1, hi, lo);
                *(uint32_t*)(smem + SMB_X + kc * 8192 + sw)         = hi;
                *(uint32_t*)(smem + SMB_X + 32768 + kc * 8192 + sw) = lo;
            }
        }
    }
    __syncthreads();

    // ================= stage 3: hv1 = relu(x@hvW0 + b); project ===============
#pragma unroll 1
    for (int pass = 0; pass < 2; pass++) {
#pragma unroll
        for (int i = 0; i < 32; i++) acc[i] = 0.f;
        run_gemm(smem, sb, SMB_X, 10, 4, pass, m0w, n0p, tid, l, acc);
#pragma unroll
        for (int mt = 0; mt < 2; mt++)
#pragma unroll
        for (int nt = 0; nt < 4; nt++) {
            float* a = acc + (mt * 4 + nt) * 4;
            int c0 = pass * 128 + n0p + nt * 8 + (l & 3) * 2;
            float b0 = sHvb[c0], b1 = sHvb[c0 + 1];
#pragma unroll
            for (int half = 0; half < 2; half++) {
                float v0 = fmaxf(a[half * 2 + 0] + b0, 0.f);
                float v1 = fmaxf(a[half * 2 + 1] + b1, 0.f);
                int slot = mt * 2 + half;
                p[slot * 3 + 0] = fmaf(v0, sOW1[c0 * 3 + 0], fmaf(v1, sOW1[c0 * 3 + 3], p[slot * 3 + 0]));
                p[slot * 3 + 1] = fmaf(v0, sOW1[c0 * 3 + 1], fmaf(v1, sOW1[c0 * 3 + 4], p[slot * 3 + 1]));
                p[slot * 3 + 2] = fmaf(v0, sOW1[c0 * 3 + 2], fmaf(v1, sOW1[c0 * 3 + 5], p[slot * 3 + 2]));
            }
        }
    }

    // ---- reduce projections: quad shfl, then smem atomics ----
#pragma unroll
    for (int slot = 0; slot < 4; slot++) {
        int r = m0w + (slot >> 1) * 16 + (l >> 2) + (slot & 1) * 8;
#pragma unroll
        for (int j = 0; j < 3; j++) {
            float v = p[slot * 3 + j];
            v += __shfl_xor_sync(0xffffffffu, v, 1);
            v += __shfl_xor_sync(0xffffffffu, v, 2);
            if ((l & 3) == 0) atomicAdd(&pSM[r * 3 + j], v);
        }
    }
    __syncthreads();

    for (int i = tid; i < 192; i += 256) {
        int r = i / 3, j = i - r * 3;
        out[((size_t)(base + r)) * 3 + j] = pSM[i] + outb0[j] + outb1[j];
    }
}

// ============================================================================
extern "C" void kernel_launch(void* const* d_in, const int* in_sizes, int n_in,
                              void* d_out, int out_size)
{
    const float* coords = (const float*)d_in[0];
    const float* tokens = (const float*)d_in[1];
    const float* B_q    = (const float*)d_in[2];
    const float* B_l0   = (const float*)d_in[3];
    const float* B_l1   = (const float*)d_in[4];
    const float* qW     = (const float*)d_in[5];
    const float* qb     = (const float*)d_in[6];
    const float* toqW   = (const float*)d_in[7];
    const float* tokvW  = (const float*)d_in[8];
    const float* tooW   = (const float*)d_in[9];
    const float* toob   = (const float*)d_in[10];
    const float* bwW0   = (const float*)d_in[11];
    const float* bwb0   = (const float*)d_in[12];
    const float* bwW1   = (const float*)d_in[13];
    const float* bwb1   = (const float*)d_in[14];
    const float* modW0  = (const float*)d_in[15];
    const float* modb0  = (const float*)d_in[16];
    const float* modW1  = (const float*)d_in[17];
    const float* modb1  = (const float*)d_in[18];
    const float* hvW0   = (const float*)d_in[19];
    const float* hvb0   = (const float*)d_in[20];
    const float* outW0  = (const float*)d_in[21];
    const float* outb0  = (const float*)d_in[22];
    const float* outW1  = (const float*)d_in[23];
    const float* outb1  = (const float*)d_in[24];
    float* out = (float*)d_out;

    cudaFuncSetAttribute(k3_attn, cudaFuncAttributeMaxDynamicSharedMemorySize, 131072);
    cudaFuncSetAttribute(k5_mma,  cudaFuncAttributeMaxDynamicSharedMemorySize, SMB_TOTAL);

    k0_prepw<<<dim3(256, 4), 256>>>(tooW, modW0, modW1, hvW0);
    k1_grid<<<HW / 16, 256>>>(coords, B_q, B_l0, B_l1, qW, qb, toqW,
                              bwW0, bwb0, bwW1, bwb1);
    k2_kv<<<dim3(MTOK / 16, BATCH), 256>>>(tokens, tokvW);
    k3_attn<<<dim3(HW / 256, 2, BATCH), 512, 131072>>>();
    k5_mma<<<(BATCH * HW) / 64, 256, SMB_TOTAL>>>(toob, modb0, modb1, hvb0,
                                                  outW0, outb0, outW1, outb1,
                                                  out);
}

// round 10
// speedup vs baseline: 1.2902x; 1.2902x over previous
#include <cuda_runtime.h>
#include <cuda_bf16.h>
#include <math.h>
#include <cstdint>

#define HW      16384
#define BATCH   4
#define MTOK    256
#define HD      256
#define INNER   128
#define DH      64

#define TWO_PI 6.2831853071795864769f

typedef unsigned long long u64;

// ---- packed f32x2 helpers (sm_100+) ---------------------------------------
__device__ __forceinline__ u64 pack1(float v) {
    u64 r; asm("mov.b64 %0, {%1, %2};" : "=l"(r) : "f"(v), "f"(v)); return r;
}
__device__ __forceinline__ u64 ffma2(u64 a, u64 b, u64 c) {
    u64 d; asm("fma.rn.f32x2 %0, %1, %2, %3;" : "=l"(d) : "l"(a), "l"(b), "l"(c)); return d;
}
__device__ __forceinline__ u64 fmul2(u64 a, u64 b) {
    u64 d; asm("mul.rn.f32x2 %0, %1, %2;" : "=l"(d) : "l"(a), "l"(b)); return d;
}
__device__ __forceinline__ u64 fadd2(u64 a, u64 b) {
    u64 d; asm("add.rn.f32x2 %0, %1, %2;" : "=l"(d) : "l"(a), "l"(b)); return d;
}
__device__ __forceinline__ float2 unpack2(u64 v) {
    float2 f; asm("mov.b64 {%0, %1}, %2;" : "=f"(f.x), "=f"(f.y) : "l"(v)); return f;
}

// ---- cp.async helpers ------------------------------------------------------
__device__ __forceinline__ void cpa16(void* dst, const void* src) {
    unsigned d = (unsigned)__cvta_generic_to_shared(dst);
    asm volatile("cp.async.ca.shared.global [%0], [%1], 16;" :: "r"(d), "l"(src));
}
#define CPA_COMMIT() asm volatile("cp.async.commit_group;" ::: "memory")
#define CPA_WAIT0()  asm volatile("cp.async.wait_group 0;"  ::: "memory")
#define CPA_WAIT1()  asm volatile("cp.async.wait_group 1;"  ::: "memory")

// ---- mma.sync / ldmatrix helpers (baseline PTX, sm_80+) --------------------
__device__ __forceinline__ uint32_t smem_to_u32(const void* p) {
    uint32_t a;
    asm("{ .reg .u64 t; cvta.to.shared.u64 t, %1; cvt.u32.u64 %0, t; }" : "=r"(a) : "l"(p));
    return a;
}
__device__ __forceinline__ void ldsm4(uint32_t* r, uint32_t addr) {
    asm volatile("ldmatrix.sync.aligned.m8n8.x4.shared.b16 {%0,%1,%2,%3}, [%4];"
        : "=r"(r[0]), "=r"(r[1]), "=r"(r[2]), "=r"(r[3]) : "r"(addr));
}
__device__ __forceinline__ void ldsm2(uint32_t* r, uint32_t addr) {
    asm volatile("ldmatrix.sync.aligned.m8n8.x2.shared.b16 {%0,%1}, [%2];"
        : "=r"(r[0]), "=r"(r[1]) : "r"(addr));
}
__device__ __forceinline__ void mma16816(float* d, const uint32_t* a, const uint32_t* b) {
    asm volatile("mma.sync.aligned.m16n8k16.row.col.f32.bf16.bf16.f32 "
        "{%0,%1,%2,%3}, {%4,%5,%6,%7}, {%8,%9}, {%0,%1,%2,%3};"
        : "+f"(d[0]), "+f"(d[1]), "+f"(d[2]), "+f"(d[3])
        : "r"(a[0]), "r"(a[1]), "r"(a[2]), "r"(a[3]), "r"(b[0]), "r"(b[1]));
}

__device__ __forceinline__ int swz(int b) { return b ^ ((b >> 3) & 0x70); }

__device__ __forceinline__ void split2(float v0, float v1, uint32_t& hi, uint32_t& lo) {
    __nv_bfloat16 h0 = __float2bfloat16(v0), h1 = __float2bfloat16(v1);
    float r0 = v0 - __bfloat162float(h0);
    float r1 = v1 - __bfloat162float(h1);
    __nv_bfloat16 l0 = __float2bfloat16(r0), l1 = __float2bfloat16(r1);
    hi = ((uint32_t)__bfloat16_as_ushort(h1) << 16) | __bfloat16_as_ushort(h0);
    lo = ((uint32_t)__bfloat16_as_ushort(l1) << 16) | __bfloat16_as_ushort(l0);
}
__device__ __forceinline__ float bfu(unsigned short u) {
    __nv_bfloat16_raw r; r.x = u;
    return __bfloat162float(__nv_bfloat16(r));
}

// ---------------- scratch ---------------------------------------------------
__device__ float g_q  [HW * INNER];
__device__ float g_h0 [HW * HD];
__device__ float g_h1 [HW * HD];
__device__ float g_t  [HW];
__device__ float g_k  [BATCH * 2 * MTOK * DH];
__device__ float g_v  [BATCH * 2 * MTOK * DH];
__device__ float g_o  [BATCH * HW * INNER];
// pre-split, pre-swizzled bf16 weight images:
// 14 k-chunks (tooW:2, modW0:4, modW1:4, hvW0:4) x 2 n-halves x 32KB (hi16K+lo16K)
__device__ __align__(128) uint8_t g_WB[14 * 2 * 32768];

// ============================================================================
// K0: prep weights -> split bf16 [n][k] chunk images with SW128 swizzle.
// ============================================================================
__global__ void k0_prepw(const float* __restrict__ tooW,
                         const float* __restrict__ modW0,
                         const float* __restrict__ modW1,
                         const float* __restrict__ hvW0)
{
    int m = blockIdx.y;           // matrix 0..3
    int k = blockIdx.x;           // 0..255
    int n = threadIdx.x;          // 0..255
    int Km = (m == 0) ? 128 : 256;
    if (k >= Km) return;
    const float* W = (m == 0) ? tooW : (m == 1) ? modW0 : (m == 2) ? modW1 : hvW0;
    float v = W[k * 256 + n];
    __nv_bfloat16 h = __float2bfloat16(v);
    float rres = v - __bfloat162float(h);
    __nv_bfloat16 l = __float2bfloat16(rres);
    const int mstart = (m == 0) ? 0 : (m == 1) ? 2 : (m == 2) ? 6 : 10;
    uint8_t* img = g_WB + ((size_t)(mstart + (k >> 6)) * 2 + (n >> 7)) * 32768;
    int b  = (n & 127) * 128 + (k & 63) * 2;
    int sw = swz(b);
    *(__nv_bfloat16*)(img + sw)         = h;
    *(__nv_bfloat16*)(img + 16384 + sw) = l;
}

// ============================================================================
// K1: grid-shared features. 16 rows / block, 256 threads.
// ============================================================================
__global__ void k1_grid(const float* __restrict__ coords,
                        const float* __restrict__ Bq,
                        const float* __restrict__ Bl0,
                        const float* __restrict__ Bl1,
                        const float* __restrict__ qW,  const float* __restrict__ qb,
                        const float* __restrict__ toqW,
                        const float* __restrict__ bwW0, const float* __restrict__ bwb0,
                        const float* __restrict__ bwW1, const float* __restrict__ bwb1)
{
    __shared__ float four[3][16][64];
    __shared__ float xq[16][256];
    const int tid  = threadIdx.x;
    const int base = blockIdx.x * 16;

    for (int it = tid; it < 3 * 16 * 32; it += 256) {
        int mat = it >> 9;
        int rem = it & 511;
        int r   = rem >> 5;
        int i   = rem & 31;
        float x = coords[(base + r) * 2 + 0];
        float y = coords[(base + r) * 2 + 1];
        const float* Bm = (mat == 0) ? Bq : (mat == 1 ? Bl0 : Bl1);
        float proj = TWO_PI * (x * Bm[i * 2] + y * Bm[i * 2 + 1]);
        float s, c;
        sincosf(proj, &s, &c);
        four[mat][r][i]      = c;
        four[mat][r][i + 32] = s;
    }
    if (tid < 16) {
        float x = coords[(base + tid) * 2 + 0];
        float y = coords[(base + tid) * 2 + 1];
        int row = (int)(x * 16.0f); row = min(max(row, 0), 15);
        int col = (int)(y * 16.0f); col = min(max(col, 0), 15);
        g_t[base + tid] = (float)(row * 16 + col) * (1.0f / 256.0f);
    }
    __syncthreads();

    {
        const int j = tid;
        float acc[16];
#pragma unroll
        for (int r = 0; r < 16; r++) acc[r] = 0.f;
        for (int k = 0; k < 64; k++) {
            float w = qW[k * 256 + j];
#pragma unroll
            for (int r = 0; r < 16; r++) acc[r] = fmaf(four[0][r][k], w, acc[r]);
        }
        float b = qb[j];
#pragma unroll
        for (int r = 0; r < 16; r++) xq[r][j] = fmaxf(acc[r] + b, 0.f);
    }
    __syncthreads();

    {
        const int j    = tid & 127;
        const int half = tid >> 7;
        float acc[8];
#pragma unroll
        for (int r = 0; r < 8; r++) acc[r] = 0.f;
        for (int k = 0; k < 256; k++) {
            float w = toqW[k * 128 + j];
#pragma unroll
            for (int r = 0; r < 8; r++) acc[r] = fmaf(xq[half * 8 + r][k], w, acc[r]);
        }
#pragma unroll
        for (int r = 0; r < 8; r++) g_q[(base + half * 8 + r) * 128 + j] = acc[r];
    }

    {
        const int j = tid;
        float a0[16], a1[16];
#pragma unroll
        for (int r = 0; r < 16; r++) { a0[r] = 0.f; a1[r] = 0.f; }
        for (int k = 0; k < 64; k++) {
            float w0 = bwW0[k * 256 + j];
            float w1 = bwW1[k * 256 + j];
#pragma unroll
            for (int r = 0; r < 16; r++) {
                a0[r] = fmaf(four[1][r][k], w0, a0[r]);
                a1[r] = fmaf(four[2][r][k], w1, a1[r]);
            }
        }
        float b0 = bwb0[j], b1 = bwb1[j];
#pragma unroll
        for (int r = 0; r < 16; r++) {
            g_h0[(base + r) * 256 + j] = fmaxf(a0[r] + b0, 0.f);
            g_h1[(base + r) * 256 + j] = fmaxf(a1[r] + b1, 0.f);
        }
    }
}

// ============================================================================
// K2: kv = tokens @ tokvW -> per-head k / v.
// ============================================================================
__global__ void k2_kv(const float* __restrict__ tokens,
                      const float* __restrict__ tokvW)
{
    __shared__ float tok[16][256];
    const int tile = blockIdx.x;
    const int b    = blockIdx.y;
    const int tid  = threadIdx.x;

    const float* tb = tokens + (b * MTOK + tile * 16) * 256;
    for (int i = tid; i < 16 * 256; i += 256) tok[i >> 8][i & 255] = tb[i];
    __syncthreads();

    const int j = tid;
    float acc[16];
#pragma unroll
    for (int r = 0; r < 16; r++) acc[r] = 0.f;
    for (int k = 0; k < 256; k++) {
        float w = tokvW[k * 256 + j];
#pragma unroll
        for (int r = 0; r < 16; r++) acc[r] = fmaf(tok[r][k], w, acc[r]);
    }
#pragma unroll
    for (int r = 0; r < 16; r++) {
        int m = tile * 16 + r;
        if (j < 128) {
            int h = j >> 6, d = j & 63;
            g_k[((b * 2 + h) * MTOK + m) * DH + d] = acc[r];
        } else {
            int j2 = j - 128;
            int h = j2 >> 6, d = j2 & 63;
            g_v[((b * 2 + h) * MTOK + m) * DH + d] = acc[r];
        }
    }
}

// ============================================================================
// K3: attention with spatial bias. 256 threads/block, f32x2 math.
// 2 keys per iteration: two independent QK trees + one shared max-update.
// ============================================================================
__global__ void __launch_bounds__(256) k3_attn()
{
    extern __shared__ float sm[];
    float* ks = sm;
    float* vs = sm + MTOK * DH;

    const int h   = blockIdx.y;
    const int b   = blockIdx.z;
    const int tid = threadIdx.x;

    const float* kg = g_k + (b * 2 + h) * MTOK * DH;
    const float* vg = g_v + (b * 2 + h) * MTOK * DH;
    for (int i = tid * 4; i < MTOK * DH; i += 256 * 4) {
        *(float4*)&ks[i] = *(const float4*)&kg[i];
        *(float4*)&vs[i] = *(const float4*)&vg[i];
    }
    __syncthreads();

    const int row = blockIdx.x * 256 + tid;
    u64 q2[32];
    {
        const u64 scale = pack1(0.125f);
        const ulonglong2* qp = (const ulonglong2*)(g_q + row * 128 + h * 64);
#pragma unroll
        for (int i = 0; i < 16; i++) {
            ulonglong2 t = qp[i];
            q2[2*i]   = fmul2(t.x, scale);
            q2[2*i+1] = fmul2(t.y, scale);
        }
    }
    const float tt = g_t[row];

    u64 acc[32];
#pragma unroll
    for (int i = 0; i < 32; i++) acc[i] = 0ULL;
    float Mx = -1e30f, S = 0.f;

    for (int m = 0; m < 256; m += 2) {
        const ulonglong2* kp0 = (const ulonglong2*)&ks[m * 64];
        const ulonglong2* kp1 = (const ulonglong2*)&ks[m * 64 + 64];
        u64 a0 = 0, a1 = 0, a2 = 0, a3 = 0;     // key m
        u64 b0 = 0, b1 = 0, b2 = 0, b3 = 0;     // key m+1
#pragma unroll
        for (int i = 0; i < 16; i += 2) {
            ulonglong2 k00 = kp0[i];
            ulonglong2 k01 = kp0[i + 1];
            ulonglong2 k10 = kp1[i];
            ulonglong2 k11 = kp1[i + 1];
            a0 = ffma2(q2[2*i    ], k00.x, a0);
            b0 = ffma2(q2[2*i    ], k10.x, b0);
            a1 = ffma2(q2[2*i + 1], k00.y, a1);
            b1 = ffma2(q2[2*i + 1], k10.y, b1);
            a2 = ffma2(q2[2*i + 2], k01.x, a2);
            b2 = ffma2(q2[2*i + 2], k11.x, b2);
            a3 = ffma2(q2[2*i + 3], k01.y, a3);
            b3 = ffma2(q2[2*i + 3], k11.y, b3);
        }
        float2 sfa = unpack2(fadd2(fadd2(a0, a1), fadd2(a2, a3)));
        float2 sfb = unpack2(fadd2(fadd2(b0, b1), fadd2(b2, b3)));
        float pos0 = ((float)m + 0.5f) * (1.0f / 256.0f);
        float pos1 = ((float)m + 1.5f) * (1.0f / 256.0f);
        float d0 = tt - pos0;
        float d1 = tt - pos1;
        float s0 = (sfa.x + sfa.y) - 10.0f * d0 * d0;
        float s1 = (sfb.x + sfb.y) - 10.0f * d1 * d1;

        float mn = fmaxf(s0, s1);
        if (mn > Mx) {
            float corr = __expf(Mx - mn);
            S *= corr;
            u64 cp = pack1(corr);
#pragma unroll
            for (int i = 0; i < 32; i++) acc[i] = fmul2(acc[i], cp);
            Mx = mn;
        }
        float p0 = __expf(s0 - Mx);
        float p1 = __expf(s1 - Mx);
        S += p0 + p1;
        u64 pp0 = pack1(p0);
        u64 pp1 = pack1(p1);
        const ulonglong2* vp0 = (const ulonglong2*)&vs[m * 64];
        const ulonglong2* vp1 = (const ulonglong2*)&vs[m * 64 + 64];
#pragma unroll
        for (int i = 0; i < 16; i++) {
            ulonglong2 v0 = vp0[i];
            ulonglong2 v1 = vp1[i];
            acc[2*i    ] = ffma2(pp0, v0.x, acc[2*i    ]);
            acc[2*i + 1] = ffma2(pp0, v0.y, acc[2*i + 1]);
            acc[2*i    ] = ffma2(pp1, v1.x, acc[2*i    ]);
            acc[2*i + 1] = ffma2(pp1, v1.y, acc[2*i + 1]);
        }
    }

    float inv = 1.0f / S;
    float* og = g_o + ((size_t)b * HW + row) * 128 + h * 64;
#pragma unroll
    for (int i = 0; i < 32; i++) {
        float2 f = unpack2(acc[i]);
        float2 o2; o2.x = f.x * inv; o2.y = f.y * inv;
        *(float2*)&og[2 * i] = o2;
    }
}

// ============================================================================
// K5 mma.sync: fused MLP chain via split-bf16 tensor-core GEMMs.
// CTA = 64 rows, 256 threads (8 warps = 2M x 4N). Warp tile 32x32 per N-pass.
// ============================================================================
// smem layout (bytes)
#define SMB_MOD   0          // A buffer: mod (hi 32K @0, lo 32K @32768)
#define SMB_X     65536      // A buffer: o, then m0/x
#define SMB_B     131072     // 2 x 32KB B chunk buffers (hi 16K + lo 16K each)
#define SMB_CONST 196608     // toob|modb0|modb1|hvb0|OW0|OW1 (2560 floats)
#define SMB_PSM   206848     // 64 x 3 fp32 projection accum
#define SMB_TOTAL 207616

__device__ __forceinline__ void run_gemm(char* smem, uint32_t sb, int Aoff,
                                         int mstart, int nch, int pass,
                                         int m0w, int n0p, int tid, int l,
                                         float* acc)
{
    {
        const uint8_t* src = g_WB + ((size_t)mstart * 2 + pass) * 32768;
        char* dst = smem + SMB_B;
#pragma unroll
        for (int it = 0; it < 8; it++) {
            int i = (it * 256 + tid) * 16;
            cpa16(dst + i, src + i);
        }
        CPA_COMMIT();
    }
    for (int c = 0; c < nch; c++) {
        if (c + 1 < nch) {
            const uint8_t* src = g_WB + ((size_t)(mstart + c + 1) * 2 + pass) * 32768;
            char* dst = smem + SMB_B + ((c + 1) & 1) * 32768;
#pragma unroll
            for (int it = 0; it < 8; it++) {
                int i = (it * 256 + tid) * 16;
                cpa16(dst + i, src + i);
            }
            CPA_COMMIT();
            CPA_WAIT1();
        } else {
            CPA_WAIT0();
        }
        __syncthreads();

        const uint32_t bB   = sb + SMB_B + (c & 1) * 32768;
        const uint32_t bAhi = sb + Aoff + c * 8192;
        const uint32_t bAlo = bAhi + 32768;

#pragma unroll
        for (int t4 = 0; t4 < 4; t4++) {
            uint32_t ahi[2][4], alo[2][4];
            const int arow = l & 15;
            const int akb  = t4 * 32 + (l >> 4) * 16;
#pragma unroll
            for (int mt = 0; mt < 2; mt++) {
                int ab = (m0w + mt * 16 + arow) * 128 + akb;
                int sw = swz(ab);
                ldsm4(ahi[mt], bAhi + sw);
                ldsm4(alo[mt], bAlo + sw);
            }
#pragma unroll
            for (int nt = 0; nt < 4; nt++) {
                const int nrow = n0p + nt * 8 + (l & 7);
                int bb = nrow * 128 + t4 * 32 + ((l >> 3) & 1) * 16;
                int sw = swz(bb);
                uint32_t bhi[2], blo[2];
                ldsm2(bhi, bB + sw);
                ldsm2(blo, bB + 16384 + sw);
                float* a0 = acc + (0 * 4 + nt) * 4;
                float* a1 = acc + (1 * 4 + nt) * 4;
                mma16816(a0, ahi[0], bhi);
                mma16816(a1, ahi[1], bhi);
                mma16816(a0, ahi[0], blo);
                mma16816(a1, ahi[1], blo);
                mma16816(a0, alo[0], bhi);
                mma16816(a1, alo[1], bhi);
            }
        }
        __syncthreads();
    }
}

__global__ void __launch_bounds__(256, 1) k5_mma(
    const float* __restrict__ toob,
    const float* __restrict__ modb0, const float* __restrict__ modb1,
    const float* __restrict__ hvb0,
    const float* __restrict__ outW0, const float* __restrict__ outb0,
    const float* __restrict__ outW1, const float* __restrict__ outb1,
    float* __restrict__ out)
{
    extern __shared__ char smem[];
    const uint32_t sb = smem_to_u32(smem);
    const int tid  = threadIdx.x;
    const int w    = tid >> 5;
    const int l    = tid & 31;
    const int m0w  = 32 * (w & 1);
    const int n0p  = 32 * (w >> 1);
    const int base = blockIdx.x * 64;
    const int hb   = base & (HW - 1);

    float* sC    = (float*)(smem + SMB_CONST);
    float* sToob = sC;
    float* sMb0  = sC + 256;
    float* sMb1  = sC + 512;
    float* sHvb  = sC + 768;
    float* sOW0  = sC + 1024;
    float* sOW1  = sC + 1792;
    float* pSM   = (float*)(smem + SMB_PSM);

    for (int i = tid; i < 256; i += 256) {
        sToob[i] = toob[i];
        sMb0[i]  = modb0[i];
        sMb1[i]  = modb1[i];
        sHvb[i]  = hvb0[i];
    }
    for (int i = tid; i < 768; i += 256) {
        sOW0[i] = outW0[i];
        sOW1[i] = outW1[i];
    }
    for (int i = tid; i < 192; i += 256) pSM[i] = 0.f;

    for (int i = tid; i < 64 * 64; i += 256) {
        int r  = i >> 6;
        int kp = i & 63;
        int k  = kp * 2;
        float2 v = *(const float2*)&g_o[((size_t)(base + r)) * 128 + k];
        uint32_t hi, lo;
        split2(v.x, v.y, hi, lo);
        int kc = k >> 6;
        int b  = r * 128 + (k & 63) * 2;
        int sw = swz(b);
        *(uint32_t*)(smem + SMB_X + kc * 8192 + sw)         = hi;
        *(uint32_t*)(smem + SMB_X + 32768 + kc * 8192 + sw) = lo;
    }
    __syncthreads();

    float acc[32];
    float p[12];
#pragma unroll
    for (int i = 0; i < 12; i++) p[i] = 0.f;

    // ================= stage 0: mod = o @ tooW + toob -> SMB_MOD =============
#pragma unroll 1
    for (int pass = 0; pass < 2; pass++) {
#pragma unroll
        for (int i = 0; i < 32; i++) acc[i] = 0.f;
        run_gemm(smem, sb, SMB_X, 0, 2, pass, m0w, n0p, tid, l, acc);
#pragma unroll
        for (int mt = 0; mt < 2; mt++)
#pragma unroll
        for (int nt = 0; nt < 4; nt++) {
            float* a = acc + (mt * 4 + nt) * 4;
            int c0 = pass * 128 + n0p + nt * 8 + (l & 3) * 2;
            int rA = m0w + mt * 16 + (l >> 2);
            float b0 = sToob[c0], b1 = sToob[c0 + 1];
            int kc = c0 >> 6;
            int bby = (c0 & 63) * 2;
            uint32_t hi, lo;
            split2(a[0] + b0, a[1] + b1, hi, lo);
            int sw = swz(rA * 128 + bby);
            *(uint32_t*)(smem + SMB_MOD + kc * 8192 + sw)         = hi;
            *(uint32_t*)(smem + SMB_MOD + 32768 + kc * 8192 + sw) = lo;
            split2(a[2] + b0, a[3] + b1, hi, lo);
            sw = swz((rA + 8) * 128 + bby);
            *(uint32_t*)(smem + SMB_MOD + kc * 8192 + sw)         = hi;
            *(uint32_t*)(smem + SMB_MOD + 32768 + kc * 8192 + sw) = lo;
        }
    }
    __syncthreads();

    // ================= stage 1: m0 = relu(h0 + mod@modW0 + b) -> SMB_X =======
#pragma unroll 1
    for (int pass = 0; pass < 2; pass++) {
#pragma unroll
        for (int i = 0; i < 32; i++) acc[i] = 0.f;
        run_gemm(smem, sb, SMB_MOD, 2, 4, pass, m0w, n0p, tid, l, acc);
#pragma unroll
        for (int mt = 0; mt < 2; mt++)
#pragma unroll
        for (int nt = 0; nt < 4; nt++) {
            float* a = acc + (mt * 4 + nt) * 4;
            int c0 = pass * 128 + n0p + nt * 8 + (l & 3) * 2;
            int rA = m0w + mt * 16 + (l >> 2);
            float b0 = sMb0[c0], b1 = sMb0[c0 + 1];
            int kc = c0 >> 6;
            int bby = (c0 & 63) * 2;
#pragma unroll
            for (int half = 0; half < 2; half++) {
                int r = rA + half * 8;
                float2 h0 = *(const float2*)&g_h0[((size_t)(hb + r)) * 256 + c0];
                float v0 = fmaxf(h0.x + a[half * 2 + 0] + b0, 0.f);
                float v1 = fmaxf(h0.y + a[half * 2 + 1] + b1, 0.f);
                int slot = mt * 2 + half;
                p[slot * 3 + 0] = fmaf(v0, sOW0[c0 * 3 + 0], fmaf(v1, sOW0[c0 * 3 + 3], p[slot * 3 + 0]));
                p[slot * 3 + 1] = fmaf(v0, sOW0[c0 * 3 + 1], fmaf(v1, sOW0[c0 * 3 + 4], p[slot * 3 + 1]));
                p[slot * 3 + 2] = fmaf(v0, sOW0[c0 * 3 + 2], fmaf(v1, sOW0[c0 * 3 + 5], p[slot * 3 + 2]));
                uint32_t hi, lo;
                split2(v0, v1, hi, lo);
                int sw = swz(r * 128 + bby);
                *(uint32_t*)(smem + SMB_X + kc * 8192 + sw)         = hi;
                *(uint32_t*)(smem + SMB_X + 32768 + kc * 8192 + sw) = lo;
            }
        }
    }
    __syncthreads();

    // ================= stage 2: x = m0 + relu(h1 + mod@modW1 + b) -> SMB_X ===
#pragma unroll 1
    for (int pass = 0; pass < 2; pass++) {
#pragma unroll
        for (int i = 0; i < 32; i++) acc[i] = 0.f;
        run_gemm(smem, sb, SMB_MOD, 6, 4, pass, m0w, n0p, tid, l, acc);
#pragma unroll
        for (int mt = 0; mt < 2; mt++)
#pragma unroll
        for (int nt = 0; nt < 4; nt++) {
            float* a = acc + (mt * 4 + nt) * 4;
            int c0 = pass * 128 + n0p + nt * 8 + (l & 3) * 2;
            int rA = m0w + mt * 16 + (l >> 2);
            float b0 = sMb1[c0], b1 = sMb1[c0 + 1];
            int kc = c0 >> 6;
            int bby = (c0 & 63) * 2;
#pragma unroll
            for (int half = 0; half < 2; half++) {
                int r = rA + half * 8;
                float2 h1 = *(const float2*)&g_h1[((size_t)(hb + r)) * 256 + c0];
                float m10 = fmaxf(h1.x + a[half * 2 + 0] + b0, 0.f);
                float m11 = fmaxf(h1.y + a[half * 2 + 1] + b1, 0.f);
                int sw = swz(r * 128 + bby);
                uint32_t mh = *(uint32_t*)(smem + SMB_X + kc * 8192 + sw);
                uint32_t ml = *(uint32_t*)(smem + SMB_X + 32768 + kc * 8192 + sw);
                float x0 = bfu((unsigned short)(mh & 0xffff)) + bfu((unsigned short)(ml & 0xffff)) + m10;
                float x1 = bfu((unsigned short)(mh >> 16))    + bfu((unsigned short)(ml >> 16))    + m11;
                uint32_t hi, lo;
                split2(x0, x1, hi, lo);
                *(uint32_t*)(smem + SMB_X + kc * 8192 + sw)         = hi;
                *(uint32_t*)(smem + SMB_X + 32768 + kc * 8192 + sw) = lo;
            }
        }
    }
    __syncthreads();

    // ================= stage 3: hv1 = relu(x@hvW0 + b); project ===============
#pragma unroll 1
    for (int pass = 0; pass < 2; pass++) {
#pragma unroll
        for (int i = 0; i < 32; i++) acc[i] = 0.f;
        run_gemm(smem, sb, SMB_X, 10, 4, pass, m0w, n0p, tid, l, acc);
#pragma unroll
        for (int mt = 0; mt < 2; mt++)
#pragma unroll
        for (int nt = 0; nt < 4; nt++) {
            float* a = acc + (mt * 4 + nt) * 4;
            int c0 = pass * 128 + n0p + nt * 8 + (l & 3) * 2;
            float b0 = sHvb[c0], b1 = sHvb[c0 + 1];
#pragma unroll
            for (int half = 0; half < 2; half++) {
                float v0 = fmaxf(a[half * 2 + 0] + b0, 0.f);
                float v1 = fmaxf(a[half * 2 + 1] + b1, 0.f);
                int slot = mt * 2 + half;
                p[slot * 3 + 0] = fmaf(v0, sOW1[c0 * 3 + 0], fmaf(v1, sOW1[c0 * 3 + 3], p[slot * 3 + 0]));
                p[slot * 3 + 1] = fmaf(v0, sOW1[c0 * 3 + 1], fmaf(v1, sOW1[c0 * 3 + 4], p[slot * 3 + 1]));
                p[slot * 3 + 2] = fmaf(v0, sOW1[c0 * 3 + 2], fmaf(v1, sOW1[c0 * 3 + 5], p[slot * 3 + 2]));
            }
        }
    }

    // ---- reduce projections: quad shfl, then smem atomics ----
#pragma unroll
    for (int slot = 0; slot < 4; slot++) {
        int r = m0w + (slot >> 1) * 16 + (l >> 2) + (slot & 1) * 8;
#pragma unroll
        for (int j = 0; j < 3; j++) {
            float v = p[slot * 3 + j];
            v += __shfl_xor_sync(0xffffffffu, v, 1);
            v += __shfl_xor_sync(0xffffffffu, v, 2);
            if ((l & 3) == 0) atomicAdd(&pSM[r * 3 + j], v);
        }
    }
    __syncthreads();

    for (int i = tid; i < 192; i += 256) {
        int r = i / 3, j = i - r * 3;
        out[((size_t)(base + r)) * 3 + j] = pSM[i] + outb0[j] + outb1[j];
    }
}

// ============================================================================
extern "C" void kernel_launch(void* const* d_in, const int* in_sizes, int n_in,
                              void* d_out, int out_size)
{
    const float* coords = (const float*)d_in[0];
    const float* tokens = (const float*)d_in[1];
    const float* B_q    = (const float*)d_in[2];
    const float* B_l0   = (const float*)d_in[3];
    const float* B_l1   = (const float*)d_in[4];
    const float* qW     = (const float*)d_in[5];
    const float* qb     = (const float*)d_in[6];
    const float* toqW   = (const float*)d_in[7];
    const float* tokvW  = (const float*)d_in[8];
    const float* tooW   = (const float*)d_in[9];
    const float* toob   = (const float*)d_in[10];
    const float* bwW0   = (const float*)d_in[11];
    const float* bwb0   = (const float*)d_in[12];
    const float* bwW1   = (const float*)d_in[13];
    const float* bwb1   = (const float*)d_in[14];
    const float* modW0  = (const float*)d_in[15];
    const float* modb0  = (const float*)d_in[16];
    const float* modW1  = (const float*)d_in[17];
    const float* modb1  = (const float*)d_in[18];
    const float* hvW0   = (const float*)d_in[19];
    const float* hvb0   = (const float*)d_in[20];
    const float* outW0  = (const float*)d_in[21];
    const float* outb0  = (const float*)d_in[22];
    const float* outW1  = (const float*)d_in[23];
    const float* outb1  = (const float*)d_in[24];
    float* out = (float*)d_out;

    cudaFuncSetAttribute(k3_attn, cudaFuncAttributeMaxDynamicSharedMemorySize, 131072);
    cudaFuncSetAttribute(k5_mma,  cudaFuncAttributeMaxDynamicSharedMemorySize, SMB_TOTAL);

    k0_prepw<<<dim3(256, 4), 256>>>(tooW, modW0, modW1, hvW0);
    k1_grid<<<HW / 16, 256>>>(coords, B_q, B_l0, B_l1, qW, qb, toqW,
                              bwW0, bwb0, bwW1, bwb1);
    k2_kv<<<dim3(MTOK / 16, BATCH), 256>>>(tokens, tokvW);
    k3_attn<<<dim3(HW / 256, 2, BATCH), 256, 131072>>>();
    k5_mma<<<(BATCH * HW) / 64, 256, SMB_TOTAL>>>(toob, modb0, modb1, hvb0,
                                                  outW0, outb0, outW1, outb1,
                                                  out);
}

// round 12
// speedup vs baseline: 1.7592x; 1.3635x over previous
#include <cuda_runtime.h>
#include <cuda_bf16.h>
#include <math.h>
#include <cstdint>

#define HW      16384
#define BATCH   4
#define MTOK    256
#define HD      256
#define INNER   128
#define DH      64

#define TWO_PI 6.2831853071795864769f

typedef unsigned long long u64;

// ---- cp.async helpers ------------------------------------------------------
__device__ __forceinline__ void cpa16(void* dst, const void* src) {
    unsigned d = (unsigned)__cvta_generic_to_shared(dst);
    asm volatile("cp.async.ca.shared.global [%0], [%1], 16;" :: "r"(d), "l"(src));
}
#define CPA_COMMIT() asm volatile("cp.async.commit_group;" ::: "memory")
#define CPA_WAIT0()  asm volatile("cp.async.wait_group 0;"  ::: "memory")
#define CPA_WAIT1()  asm volatile("cp.async.wait_group 1;"  ::: "memory")

// ---- mma.sync / ldmatrix helpers (baseline PTX, sm_80+) --------------------
__device__ __forceinline__ uint32_t smem_to_u32(const void* p) {
    uint32_t a;
    asm("{ .reg .u64 t; cvta.to.shared.u64 t, %1; cvt.u32.u64 %0, t; }" : "=r"(a) : "l"(p));
    return a;
}
__device__ __forceinline__ void ldsm4(uint32_t* r, uint32_t addr) {
    asm volatile("ldmatrix.sync.aligned.m8n8.x4.shared.b16 {%0,%1,%2,%3}, [%4];"
        : "=r"(r[0]), "=r"(r[1]), "=r"(r[2]), "=r"(r[3]) : "r"(addr));
}
__device__ __forceinline__ void ldsm2(uint32_t* r, uint32_t addr) {
    asm volatile("ldmatrix.sync.aligned.m8n8.x2.shared.b16 {%0,%1}, [%2];"
        : "=r"(r[0]), "=r"(r[1]) : "r"(addr));
}
__device__ __forceinline__ void mma16816(float* d, const uint32_t* a, const uint32_t* b) {
    asm volatile("mma.sync.aligned.m16n8k16.row.col.f32.bf16.bf16.f32 "
        "{%0,%1,%2,%3}, {%4,%5,%6,%7}, {%8,%9}, {%0,%1,%2,%3};"
        : "+f"(d[0]), "+f"(d[1]), "+f"(d[2]), "+f"(d[3])
        : "r"(a[0]), "r"(a[1]), "r"(a[2]), "r"(a[3]), "r"(b[0]), "r"(b[1]));
}

__device__ __forceinline__ int swz(int b) { return b ^ ((b >> 3) & 0x70); }

__device__ __forceinline__ void split2(float v0, float v1, uint32_t& hi, uint32_t& lo) {
    __nv_bfloat16 h0 = __float2bfloat16(v0), h1 = __float2bfloat16(v1);
    float r0 = v0 - __bfloat162float(h0);
    float r1 = v1 - __bfloat162float(h1);
    __nv_bfloat16 l0 = __float2bfloat16(r0), l1 = __float2bfloat16(r1);
    hi = ((uint32_t)__bfloat16_as_ushort(h1) << 16) | __bfloat16_as_ushort(h0);
    lo = ((uint32_t)__bfloat16_as_ushort(l1) << 16) | __bfloat16_as_ushort(l0);
}
__device__ __forceinline__ float bfu(unsigned short u) {
    __nv_bfloat16_raw r; r.x = u;
    return __bfloat162float(__nv_bfloat16(r));
}

// ---------------- scratch ---------------------------------------------------
__device__ float g_h0 [HW * HD];
__device__ float g_h1 [HW * HD];
__device__ float g_t  [HW];
__device__ float g_o  [BATCH * HW * INNER];
// pre-split, pre-swizzled bf16 weight images (k5)
__device__ __align__(128) uint8_t g_WB[14 * 2 * 32768];
// attention images: q (x0.125) per (h, 128-row tile): hi 16K + lo 16K
__device__ __align__(128) uint8_t g_qb[2 * 128 * 32768];
// k per (b,h): [256 key][64 dh] hi 32K + lo 32K
__device__ __align__(128) uint8_t g_kb[8 * 65536];
// v^T per (b,h): 4 key-chunks x [64 dh][64 key] hi 32K total + lo 32K
__device__ __align__(128) uint8_t g_vb[8 * 65536];

// ============================================================================
// K0: prep weights -> split bf16 [n][k] chunk images with SW128 swizzle.
// ============================================================================
__global__ void k0_prepw(const float* __restrict__ tooW,
                         const float* __restrict__ modW0,
                         const float* __restrict__ modW1,
                         const float* __restrict__ hvW0)
{
    int m = blockIdx.y;
    int k = blockIdx.x;
    int n = threadIdx.x;
    int Km = (m == 0) ? 128 : 256;
    if (k >= Km) return;
    const float* W = (m == 0) ? tooW : (m == 1) ? modW0 : (m == 2) ? modW1 : hvW0;
    float v = W[k * 256 + n];
    __nv_bfloat16 h = __float2bfloat16(v);
    float rres = v - __bfloat162float(h);
    __nv_bfloat16 l = __float2bfloat16(rres);
    const int mstart = (m == 0) ? 0 : (m == 1) ? 2 : (m == 2) ? 6 : 10;
    uint8_t* img = g_WB + ((size_t)(mstart + (k >> 6)) * 2 + (n >> 7)) * 32768;
    int b  = (n & 127) * 128 + (k & 63) * 2;
    int sw = swz(b);
    *(__nv_bfloat16*)(img + sw)         = h;
    *(__nv_bfloat16*)(img + 16384 + sw) = l;
}

// ============================================================================
// K1: grid-shared features. 16 rows / block, 256 threads.
// q written as split-bf16 swizzled image (pre-scaled by 1/8).
// ============================================================================
__global__ void k1_grid(const float* __restrict__ coords,
                        const float* __restrict__ Bq,
                        const float* __restrict__ Bl0,
                        const float* __restrict__ Bl1,
                        const float* __restrict__ qW,  const float* __restrict__ qb,
                        const float* __restrict__ toqW,
                        const float* __restrict__ bwW0, const float* __restrict__ bwb0,
                        const float* __restrict__ bwW1, const float* __restrict__ bwb1)
{
    __shared__ float four[3][16][64];
    __shared__ float xq[16][256];
    const int tid  = threadIdx.x;
    const int base = blockIdx.x * 16;

    for (int it = tid; it < 3 * 16 * 32; it += 256) {
        int mat = it >> 9;
        int rem = it & 511;
        int r   = rem >> 5;
        int i   = rem & 31;
        float x = coords[(base + r) * 2 + 0];
        float y = coords[(base + r) * 2 + 1];
        const float* Bm = (mat == 0) ? Bq : (mat == 1 ? Bl0 : Bl1);
        float proj = TWO_PI * (x * Bm[i * 2] + y * Bm[i * 2 + 1]);
        float s, c;
        sincosf(proj, &s, &c);
        four[mat][r][i]      = c;
        four[mat][r][i + 32] = s;
    }
    if (tid < 16) {
        float x = coords[(base + tid) * 2 + 0];
        float y = coords[(base + tid) * 2 + 1];
        int row = (int)(x * 16.0f); row = min(max(row, 0), 15);
        int col = (int)(y * 16.0f); col = min(max(col, 0), 15);
        g_t[base + tid] = (float)(row * 16 + col) * (1.0f / 256.0f);
    }
    __syncthreads();

    {
        const int j = tid;
        float acc[16];
#pragma unroll
        for (int r = 0; r < 16; r++) acc[r] = 0.f;
        for (int k = 0; k < 64; k++) {
            float w = qW[k * 256 + j];
#pragma unroll
            for (int r = 0; r < 16; r++) acc[r] = fmaf(four[0][r][k], w, acc[r]);
        }
        float b = qb[j];
#pragma unroll
        for (int r = 0; r < 16; r++) xq[r][j] = fmaxf(acc[r] + b, 0.f);
    }
    __syncthreads();

    {
        const int j    = tid & 127;
        const int half = tid >> 7;
        float acc[8];
#pragma unroll
        for (int r = 0; r < 8; r++) acc[r] = 0.f;
        for (int k = 0; k < 256; k++) {
            float w = toqW[k * 128 + j];
#pragma unroll
            for (int r = 0; r < 8; r++) acc[r] = fmaf(xq[half * 8 + r][k], w, acc[r]);
        }
        const int h = j >> 6, d = j & 63;
        uint8_t* img = g_qb + ((size_t)(h * 128 + (base >> 7))) * 32768;
#pragma unroll
        for (int r = 0; r < 8; r++) {
            int rr = (base + half * 8 + r) & 127;
            float v = acc[r] * 0.125f;
            __nv_bfloat16 hb = __float2bfloat16(v);
            float res = v - __bfloat162float(hb);
            __nv_bfloat16 lb = __float2bfloat16(res);
            int sw = swz(rr * 128 + d * 2);
            *(__nv_bfloat16*)(img + sw)         = hb;
            *(__nv_bfloat16*)(img + 16384 + sw) = lb;
        }
    }

    {
        const int j = tid;
        float a0[16], a1[16];
#pragma unroll
        for (int r = 0; r < 16; r++) { a0[r] = 0.f; a1[r] = 0.f; }
        for (int k = 0; k < 64; k++) {
            float w0 = bwW0[k * 256 + j];
            float w1 = bwW1[k * 256 + j];
#pragma unroll
            for (int r = 0; r < 16; r++) {
                a0[r] = fmaf(four[1][r][k], w0, a0[r]);
                a1[r] = fmaf(four[2][r][k], w1, a1[r]);
            }
        }
        float b0 = bwb0[j], b1 = bwb1[j];
#pragma unroll
        for (int r = 0; r < 16; r++) {
            g_h0[(base + r) * 256 + j] = fmaxf(a0[r] + b0, 0.f);
            g_h1[(base + r) * 256 + j] = fmaxf(a1[r] + b1, 0.f);
        }
    }
}

// ============================================================================
// K2: kv = tokens @ tokvW -> split-bf16 swizzled k / v^T images.
// ============================================================================
__global__ void k2_kv(const float* __restrict__ tokens,
                      const float* __restrict__ tokvW)
{
    __shared__ float tok[16][256];
    const int tile = blockIdx.x;
    const int b    = blockIdx.y;
    const int tid  = threadIdx.x;

    const float* tb = tokens + (b * MTOK + tile * 16) * 256;
    for (int i = tid; i < 16 * 256; i += 256) tok[i >> 8][i & 255] = tb[i];
    __syncthreads();

    const int j = tid;
    float acc[16];
#pragma unroll
    for (int r = 0; r < 16; r++) acc[r] = 0.f;
    for (int k = 0; k < 256; k++) {
        float w = tokvW[k * 256 + j];
#pragma unroll
        for (int r = 0; r < 16; r++) acc[r] = fmaf(tok[r][k], w, acc[r]);
    }
#pragma unroll
    for (int r = 0; r < 16; r++) {
        int m = tile * 16 + r;
        float v = acc[r];
        __nv_bfloat16 hb = __float2bfloat16(v);
        float res = v - __bfloat162float(hb);
        __nv_bfloat16 lb = __float2bfloat16(res);
        if (j < 128) {
            int h = j >> 6, d = j & 63;
            uint8_t* img = g_kb + (size_t)(b * 2 + h) * 65536;
            int sw = swz(m * 128 + d * 2);
            *(__nv_bfloat16*)(img + sw)         = hb;
            *(__nv_bfloat16*)(img + 32768 + sw) = lb;
        } else {
            int h = (j - 128) >> 6, d = (j - 128) & 63;
            uint8_t* img = g_vb + (size_t)(b * 2 + h) * 65536;
            int off = (m >> 6) * 8192 + swz(d * 128 + (m & 63) * 2);
            *(__nv_bfloat16*)(img + off)         = hb;
            *(__nv_bfloat16*)(img + 32768 + off) = lb;
        }
    }
}

// ============================================================================
// K3 flash-mma: attention via split-bf16 tensor-core GEMMs.
// CTA = 128 query rows x one (b,h). 256 threads (8 warps x 16 rows).
// 4 key-tiles of 64; online softmax on C-fragments.
// ============================================================================
__global__ void __launch_bounds__(256) k3_fa()
{
    extern __shared__ uint8_t smem[];
    const uint32_t sb = smem_to_u32(smem);
    const int tid = threadIdx.x;
    const int w   = tid >> 5;
    const int l   = tid & 31;
    const int bx  = blockIdx.x;
    const int h   = blockIdx.y;
    const int b   = blockIdx.z;

    // load images: q 32K | k 64K | v 64K
    {
        const uint8_t* qsrc = g_qb + (size_t)(h * 128 + bx) * 32768;
        const uint8_t* ksrc = g_kb + (size_t)(b * 2 + h) * 65536;
        const uint8_t* vsrc = g_vb + (size_t)(b * 2 + h) * 65536;
        for (int i = tid; i < 2048; i += 256) cpa16(smem + i * 16, qsrc + i * 16);
        for (int i = tid; i < 4096; i += 256) cpa16(smem + 32768 + i * 16, ksrc + i * 16);
        for (int i = tid; i < 4096; i += 256) cpa16(smem + 98304 + i * 16, vsrc + i * 16);
        CPA_COMMIT();
        CPA_WAIT0();
        __syncthreads();
    }
    const uint32_t sQh = sb,          sQl = sb + 16384;
    const uint32_t sKh = sb + 32768,  sKl = sb + 65536;
    const uint32_t sVh = sb + 98304,  sVl = sb + 131072;

    const int r0 = bx * 128 + w * 16 + (l >> 2);
    const float tt0 = g_t[r0];
    const float tt1 = g_t[r0 + 8];

    float O[32];
#pragma unroll
    for (int i = 0; i < 32; i++) O[i] = 0.f;
    float Mx0 = -1e30f, Mx1 = -1e30f, S0 = 0.f, S1 = 0.f;

    const int aQrow = (w * 16 + (l & 15)) * 128 + (l >> 4) * 16;

#pragma unroll 1
    for (int t = 0; t < 4; t++) {
        float Sa[32];
#pragma unroll
        for (int i = 0; i < 32; i++) Sa[i] = 0.f;

        // ---- QK^T (split bf16, 3 passes) ----
#pragma unroll
        for (int kk = 0; kk < 4; kk++) {
            int asw = swz(aQrow + kk * 32);      // swizzle AFTER full offset
            uint32_t ahi[4], alo[4];
            ldsm4(ahi, sQh + asw);
            ldsm4(alo, sQl + asw);
#pragma unroll
            for (int nt = 0; nt < 8; nt++) {
                int bsw = swz((t * 64 + nt * 8 + (l & 7)) * 128 + kk * 32 + ((l >> 3) & 1) * 16);
                uint32_t bhi[2], blo[2];
                ldsm2(bhi, sKh + bsw);
                ldsm2(blo, sKl + bsw);
                mma16816(&Sa[nt * 4], ahi, bhi);
                mma16816(&Sa[nt * 4], ahi, blo);
                mma16816(&Sa[nt * 4], alo, bhi);
            }
        }

        // ---- bias + online softmax ----
        float tm0 = -1e30f, tm1 = -1e30f;
#pragma unroll
        for (int nt = 0; nt < 8; nt++) {
            float* a = &Sa[nt * 4];
            float c0 = (float)(t * 64 + nt * 8 + (l & 3) * 2);
            float p0 = (c0 + 0.5f) * (1.0f / 256.0f);
            float p1 = (c0 + 1.5f) * (1.0f / 256.0f);
            float d00 = tt0 - p0, d01 = tt0 - p1;
            float d10 = tt1 - p0, d11 = tt1 - p1;
            a[0] -= 10.f * d00 * d00;
            a[1] -= 10.f * d01 * d01;
            a[2] -= 10.f * d10 * d10;
            a[3] -= 10.f * d11 * d11;
            tm0 = fmaxf(tm0, fmaxf(a[0], a[1]));
            tm1 = fmaxf(tm1, fmaxf(a[2], a[3]));
        }
        tm0 = fmaxf(tm0, __shfl_xor_sync(0xffffffffu, tm0, 1));
        tm0 = fmaxf(tm0, __shfl_xor_sync(0xffffffffu, tm0, 2));
        tm1 = fmaxf(tm1, __shfl_xor_sync(0xffffffffu, tm1, 1));
        tm1 = fmaxf(tm1, __shfl_xor_sync(0xffffffffu, tm1, 2));
        float nM0 = fmaxf(Mx0, tm0), nM1 = fmaxf(Mx1, tm1);
        float cr0 = __expf(Mx0 - nM0), cr1 = __expf(Mx1 - nM1);
        Mx0 = nM0; Mx1 = nM1;
        S0 *= cr0; S1 *= cr1;
#pragma unroll
        for (int nt = 0; nt < 8; nt++) {
            O[nt * 4 + 0] *= cr0; O[nt * 4 + 1] *= cr0;
            O[nt * 4 + 2] *= cr1; O[nt * 4 + 3] *= cr1;
        }
#pragma unroll
        for (int nt = 0; nt < 8; nt++) {
            float* a = &Sa[nt * 4];
            a[0] = __expf(a[0] - Mx0);
            a[1] = __expf(a[1] - Mx0);
            a[2] = __expf(a[2] - Mx1);
            a[3] = __expf(a[3] - Mx1);
            S0 += a[0] + a[1];
            S1 += a[2] + a[3];
        }

        // ---- P @ V (split bf16, 3 passes) ----
#pragma unroll
        for (int kk = 0; kk < 4; kk++) {
            uint32_t phi[4], plo[4];
            float* pA = &Sa[(2 * kk) * 4];
            float* pB = &Sa[(2 * kk + 1) * 4];
            split2(pA[0], pA[1], phi[0], plo[0]);
            split2(pA[2], pA[3], phi[1], plo[1]);
            split2(pB[0], pB[1], phi[2], plo[2]);
            split2(pB[2], pB[3], phi[3], plo[3]);
#pragma unroll
            for (int nt = 0; nt < 8; nt++) {
                int vsw = t * 8192 + swz((nt * 8 + (l & 7)) * 128 + kk * 32 + ((l >> 3) & 1) * 16);
                uint32_t vhi[2], vlo[2];
                ldsm2(vhi, sVh + vsw);
                ldsm2(vlo, sVl + vsw);
                mma16816(&O[nt * 4], phi, vhi);
                mma16816(&O[nt * 4], phi, vlo);
                mma16816(&O[nt * 4], plo, vhi);
            }
        }
    }

    // ---- finalize ----
    S0 += __shfl_xor_sync(0xffffffffu, S0, 1);
    S0 += __shfl_xor_sync(0xffffffffu, S0, 2);
    S1 += __shfl_xor_sync(0xffffffffu, S1, 1);
    S1 += __shfl_xor_sync(0xffffffffu, S1, 2);
    float inv0 = 1.0f / S0, inv1 = 1.0f / S1;
#pragma unroll
    for (int nt = 0; nt < 8; nt++) {
        int col = h * 64 + nt * 8 + (l & 3) * 2;
        float2 o0, o1;
        o0.x = O[nt * 4 + 0] * inv0; o0.y = O[nt * 4 + 1] * inv0;
        o1.x = O[nt * 4 + 2] * inv1; o1.y = O[nt * 4 + 3] * inv1;
        *(float2*)&g_o[((size_t)b * HW + r0) * 128 + col]       = o0;
        *(float2*)&g_o[((size_t)b * HW + r0 + 8) * 128 + col]   = o1;
    }
}

// ============================================================================
// K5 mma.sync: fused MLP chain via split-bf16 tensor-core GEMMs (unchanged).
// ============================================================================
#define SMB_MOD   0
#define SMB_X     65536
#define SMB_B     131072
#define SMB_CONST 196608
#define SMB_PSM   206848
#define SMB_TOTAL 207616

__device__ __forceinline__ void run_gemm(char* smem, uint32_t sb, int Aoff,
                                         int mstart, int nch, int pass,
                                         int m0w, int n0p, int tid, int l,
                                         float* acc)
{
    {
        const uint8_t* src = g_WB + ((size_t)mstart * 2 + pass) * 32768;
        char* dst = smem + SMB_B;
#pragma unroll
        for (int it = 0; it < 8; it++) {
            int i = (it * 256 + tid) * 16;
            cpa16(dst + i, src + i);
        }
        CPA_COMMIT();
    }
    for (int c = 0; c < nch; c++) {
        if (c + 1 < nch) {
            const uint8_t* src = g_WB + ((size_t)(mstart + c + 1) * 2 + pass) * 32768;
            char* dst = smem + SMB_B + ((c + 1) & 1) * 32768;
#pragma unroll
            for (int it = 0; it < 8; it++) {
                int i = (it * 256 + tid) * 16;
                cpa16(dst + i, src + i);
            }
            CPA_COMMIT();
            CPA_WAIT1();
        } else {
            CPA_WAIT0();
        }
        __syncthreads();

        const uint32_t bB   = sb + SMB_B + (c & 1) * 32768;
        const uint32_t bAhi = sb + Aoff + c * 8192;
        const uint32_t bAlo = bAhi + 32768;

#pragma unroll
        for (int t4 = 0; t4 < 4; t4++) {
            uint32_t ahi[2][4], alo[2][4];
            const int arow = l & 15;
            const int akb  = t4 * 32 + (l >> 4) * 16;
#pragma unroll
            for (int mt = 0; mt < 2; mt++) {
                int ab = (m0w + mt * 16 + arow) * 128 + akb;
                int sw = swz(ab);
                ldsm4(ahi[mt], bAhi + sw);
                ldsm4(alo[mt], bAlo + sw);
            }
#pragma unroll
            for (int nt = 0; nt < 4; nt++) {
                const int nrow = n0p + nt * 8 + (l & 7);
                int bb = nrow * 128 + t4 * 32 + ((l >> 3) & 1) * 16;
                int sw = swz(bb);
                uint32_t bhi[2], blo[2];
                ldsm2(bhi, bB + sw);
                ldsm2(blo, bB + 16384 + sw);
                float* a0 = acc + (0 * 4 + nt) * 4;
                float* a1 = acc + (1 * 4 + nt) * 4;
                mma16816(a0, ahi[0], bhi);
                mma16816(a1, ahi[1], bhi);
                mma16816(a0, ahi[0], blo);
                mma16816(a1, ahi[1], blo);
                mma16816(a0, alo[0], bhi);
                mma16816(a1, alo[1], bhi);
            }
        }
        __syncthreads();
    }
}

__global__ void __launch_bounds__(256, 1) k5_mma(
    const float* __restrict__ toob,
    const float* __restrict__ modb0, const float* __restrict__ modb1,
    const float* __restrict__ hvb0,
    const float* __restrict__ outW0, const float* __restrict__ outb0,
    const float* __restrict__ outW1, const float* __restrict__ outb1,
    float* __restrict__ out)
{
    extern __shared__ char smemc[];
    char* smem = smemc;
    const uint32_t sb = smem_to_u32(smem);
    const int tid  = threadIdx.x;
    const int w    = tid >> 5;
    const int l    = tid & 31;
    const int m0w  = 32 * (w & 1);
    const int n0p  = 32 * (w >> 1);
    const int base = blockIdx.x * 64;
    const int hb   = base & (HW - 1);

    float* sC    = (float*)(smem + SMB_CONST);
    float* sToob = sC;
    float* sMb0  = sC + 256;
    float* sMb1  = sC + 512;
    float* sHvb  = sC + 768;
    float* sOW0  = sC + 1024;
    float* sOW1  = sC + 1792;
    float* pSM   = (float*)(smem + SMB_PSM);

    for (int i = tid; i < 256; i += 256) {
        sToob[i] = toob[i];
        sMb0[i]  = modb0[i];
        sMb1[i]  = modb1[i];
        sHvb[i]  = hvb0[i];
    }
    for (int i = tid; i < 768; i += 256) {
        sOW0[i] = outW0[i];
        sOW1[i] = outW1[i];
    }
    for (int i = tid; i < 192; i += 256) pSM[i] = 0.f;

    for (int i = tid; i < 64 * 64; i += 256) {
        int r  = i >> 6;
        int kp = i & 63;
        int k  = kp * 2;
        float2 v = *(const float2*)&g_o[((size_t)(base + r)) * 128 + k];
        uint32_t hi, lo;
        split2(v.x, v.y, hi, lo);
        int kc = k >> 6;
        int bby = r * 128 + (k & 63) * 2;
        int sw = swz(bby);
        *(uint32_t*)(smem + SMB_X + kc * 8192 + sw)         = hi;
        *(uint32_t*)(smem + SMB_X + 32768 + kc * 8192 + sw) = lo;
    }
    __syncthreads();

    float acc[32];
    float p[12];
#pragma unroll
    for (int i = 0; i < 12; i++) p[i] = 0.f;

#pragma unroll 1
    for (int pass = 0; pass < 2; pass++) {
#pragma unroll
        for (int i = 0; i < 32; i++) acc[i] = 0.f;
        run_gemm(smem, sb, SMB_X, 0, 2, pass, m0w, n0p, tid, l, acc);
#pragma unroll
        for (int mt = 0; mt < 2; mt++)
#pragma unroll
        for (int nt = 0; nt < 4; nt++) {
            float* a = acc + (mt * 4 + nt) * 4;
            int c0 = pass * 128 + n0p + nt * 8 + (l & 3) * 2;
            int rA = m0w + mt * 16 + (l >> 2);
            float b0 = sToob[c0], b1 = sToob[c0 + 1];
            int kc = c0 >> 6;
            int bby = (c0 & 63) * 2;
            uint32_t hi, lo;
            split2(a[0] + b0, a[1] + b1, hi, lo);
            int sw = swz(rA * 128 + bby);
            *(uint32_t*)(smem + SMB_MOD + kc * 8192 + sw)         = hi;
            *(uint32_t*)(smem + SMB_MOD + 32768 + kc * 8192 + sw) = lo;
            split2(a[2] + b0, a[3] + b1, hi, lo);
            sw = swz((rA + 8) * 128 + bby);
            *(uint32_t*)(smem + SMB_MOD + kc * 8192 + sw)         = hi;
            *(uint32_t*)(smem + SMB_MOD + 32768 + kc * 8192 + sw) = lo;
        }
    }
    __syncthreads();

#pragma unroll 1
    for (int pass = 0; pass < 2; pass++) {
#pragma unroll
        for (int i = 0; i < 32; i++) acc[i] = 0.f;
        run_gemm(smem, sb, SMB_MOD, 2, 4, pass, m0w, n0p, tid, l, acc);
#pragma unroll
        for (int mt = 0; mt < 2; mt++)
#pragma unroll
        for (int nt = 0; nt < 4; nt++) {
            float* a = acc + (mt * 4 + nt) * 4;
            int c0 = pass * 128 + n0p + nt * 8 + (l & 3) * 2;
            int rA = m0w + mt * 16 + (l >> 2);
            float b0 = sMb0[c0], b1 = sMb0[c0 + 1];
            int kc = c0 >> 6;
            int bby = (c0 & 63) * 2;
#pragma unroll
            for (int half = 0; half < 2; half++) {
                int r = rA + half * 8;
                float2 h0 = *(const float2*)&g_h0[((size_t)(hb + r)) * 256 + c0];
                float v0 = fmaxf(h0.x + a[half * 2 + 0] + b0, 0.f);
                float v1 = fmaxf(h0.y + a[half * 2 + 1] + b1, 0.f);
                int slot = mt * 2 + half;
                p[slot * 3 + 0] = fmaf(v0, sOW0[c0 * 3 + 0], fmaf(v1, sOW0[c0 * 3 + 3], p[slot * 3 + 0]));
                p[slot * 3 + 1] = fmaf(v0, sOW0[c0 * 3 + 1], fmaf(v1, sOW0[c0 * 3 + 4], p[slot * 3 + 1]));
                p[slot * 3 + 2] = fmaf(v0, sOW0[c0 * 3 + 2], fmaf(v1, sOW0[c0 * 3 + 5], p[slot * 3 + 2]));
                uint32_t hi, lo;
                split2(v0, v1, hi, lo);
                int sw = swz(r * 128 + bby);
                *(uint32_t*)(smem + SMB_X + kc * 8192 + sw)         = hi;
                *(uint32_t*)(smem + SMB_X + 32768 + kc * 8192 + sw) = lo;
            }
        }
    }
    __syncthreads();

#pragma unroll 1
    for (int pass = 0; pass < 2; pass++) {
#pragma unroll
        for (int i = 0; i < 32; i++) acc[i] = 0.f;
        run_gemm(smem, sb, SMB_MOD, 6, 4, pass, m0w, n0p, tid, l, acc);
#pragma unroll
        for (int mt = 0; mt < 2; mt++)
#pragma unroll
        for (int nt = 0; nt < 4; nt++) {
            float* a = acc + (mt * 4 + nt) * 4;
            int c0 = pass * 128 + n0p + nt * 8 + (l & 3) * 2;
            int rA = m0w + mt * 16 + (l >> 2);
            float b0 = sMb1[c0], b1 = sMb1[c0 + 1];
            int kc = c0 >> 6;
            int bby = (c0 & 63) * 2;
#pragma unroll
            for (int half = 0; half < 2; half++) {
                int r = rA + half * 8;
                float2 h1 = *(const float2*)&g_h1[((size_t)(hb + r)) * 256 + c0];
                float m10 = fmaxf(h1.x + a[half * 2 + 0] + b0, 0.f);
                float m11 = fmaxf(h1.y + a[half * 2 + 1] + b1, 0.f);
                int sw = swz(r * 128 + bby);
                uint32_t mh = *(uint32_t*)(smem + SMB_X + kc * 8192 + sw);
                uint32_t ml = *(uint32_t*)(smem + SMB_X + 32768 + kc * 8192 + sw);
                float x0 = bfu((unsigned short)(mh & 0xffff)) + bfu((unsigned short)(ml & 0xffff)) + m10;
                float x1 = bfu((unsigned short)(mh >> 16))    + bfu((unsigned short)(ml >> 16))    + m11;
                uint32_t hi, lo;
                split2(x0, x1, hi, lo);
                *(uint32_t*)(smem + SMB_X + kc * 8192 + sw)         = hi;
                *(uint32_t*)(smem + SMB_X + 32768 + kc * 8192 + sw) = lo;
            }
        }
    }
    __syncthreads();

#pragma unroll 1
    for (int pass = 0; pass < 2; pass++) {
#pragma unroll
        for (int i = 0; i < 32; i++) acc[i] = 0.f;
        run_gemm(smem, sb, SMB_X, 10, 4, pass, m0w, n0p, tid, l, acc);
#pragma unroll
        for (int mt = 0; mt < 2; mt++)
#pragma unroll
        for (int nt = 0; nt < 4; nt++) {
            float* a = acc + (mt * 4 + nt) * 4;
            int c0 = pass * 128 + n0p + nt * 8 + (l & 3) * 2;
            float b0 = sHvb[c0], b1 = sHvb[c0 + 1];
#pragma unroll
            for (int half = 0; half < 2; half++) {
                float v0 = fmaxf(a[half * 2 + 0] + b0, 0.f);
                float v1 = fmaxf(a[half * 2 + 1] + b1, 0.f);
                int slot = mt * 2 + half;
                p[slot * 3 + 0] = fmaf(v0, sOW1[c0 * 3 + 0], fmaf(v1, sOW1[c0 * 3 + 3], p[slot * 3 + 0]));
                p[slot * 3 + 1] = fmaf(v0, sOW1[c0 * 3 + 1], fmaf(v1, sOW1[c0 * 3 + 4], p[slot * 3 + 1]));
                p[slot * 3 + 2] = fmaf(v0, sOW1[c0 * 3 + 2], fmaf(v1, sOW1[c0 * 3 + 5], p[slot * 3 + 2]));
            }
        }
    }

#pragma unroll
    for (int slot = 0; slot < 4; slot++) {
        int r = m0w + (slot >> 1) * 16 + (l >> 2) + (slot & 1) * 8;
#pragma unroll
        for (int j = 0; j < 3; j++) {
            float v = p[slot * 3 + j];
            v += __shfl_xor_sync(0xffffffffu, v, 1);
            v += __shfl_xor_sync(0xffffffffu, v, 2);
            if ((l & 3) == 0) atomicAdd(&pSM[r * 3 + j], v);
        }
    }
    __syncthreads();

    for (int i = tid; i < 192; i += 256) {
        int r = i / 3, j = i - r * 3;
        out[((size_t)(base + r)) * 3 + j] = pSM[i] + outb0[j] + outb1[j];
    }
}

// ============================================================================
extern "C" void kernel_launch(void* const* d_in, const int* in_sizes, int n_in,
                              void* d_out, int out_size)
{
    const float* coords = (const float*)d_in[0];
    const float* tokens = (const float*)d_in[1];
    const float* B_q    = (const float*)d_in[2];
    const float* B_l0   = (const float*)d_in[3];
    const float* B_l1   = (const float*)d_in[4];
    const float* qW     = (const float*)d_in[5];
    const float* qb     = (const float*)d_in[6];
    const float* toqW   = (const float*)d_in[7];
    const float* tokvW  = (const float*)d_in[8];
    const float* tooW   = (const float*)d_in[9];
    const float* toob   = (const float*)d_in[10];
    const float* bwW0   = (const float*)d_in[11];
    const float* bwb0   = (const float*)d_in[12];
    const float* bwW1   = (const float*)d_in[13];
    const float* bwb1   = (const float*)d_in[14];
    const float* modW0  = (const float*)d_in[15];
    const float* modb0  = (const float*)d_in[16];
    const float* modW1  = (const float*)d_in[17];
    const float* modb1  = (const float*)d_in[18];
    const float* hvW0   = (const float*)d_in[19];
    const float* hvb0   = (const float*)d_in[20];
    const float* outW0  = (const float*)d_in[21];
    const float* outb0  = (const float*)d_in[22];
    const float* outW1  = (const float*)d_in[23];
    const float* outb1  = (const float*)d_in[24];
    float* out = (float*)d_out;

    cudaFuncSetAttribute(k3_fa,  cudaFuncAttributeMaxDynamicSharedMemorySize, 163840);
    cudaFuncSetAttribute(k5_mma, cudaFuncAttributeMaxDynamicSharedMemorySize, SMB_TOTAL);

    k0_prepw<<<dim3(256, 4), 256>>>(tooW, modW0, modW1, hvW0);
    k1_grid<<<HW / 16, 256>>>(coords, B_q, B_l0, B_l1, qW, qb, toqW,
                              bwW0, bwb0, bwW1, bwb1);
    k2_kv<<<dim3(MTOK / 16, BATCH), 256>>>(tokens, tokvW);
    k3_fa<<<dim3(HW / 128, 2, BATCH), 256, 163840>>>();
    k5_mma<<<(BATCH * HW) / 64, 256, SMB_TOTAL>>>(toob, modb0, modb1, hvb0,
                                                  outW0, outb0, outW1, outb1,
                                                  out);
}

// round 13
// speedup vs baseline: 2.1146x; 1.2020x over previous
#include <cuda_runtime.h>
#include <cuda_bf16.h>
#include <math.h>
#include <cstdint>

#define HW      16384
#define BATCH   4
#define MTOK    256
#define HD      256
#define INNER   128
#define DH      64

#define TWO_PI 6.2831853071795864769f

typedef unsigned long long u64;

// ---- cp.async helpers ------------------------------------------------------
__device__ __forceinline__ void cpa16(void* dst, const void* src) {
    unsigned d = (unsigned)__cvta_generic_to_shared(dst);
    asm volatile("cp.async.ca.shared.global [%0], [%1], 16;" :: "r"(d), "l"(src));
}
#define CPA_COMMIT() asm volatile("cp.async.commit_group;" ::: "memory")
#define CPA_WAIT0()  asm volatile("cp.async.wait_group 0;"  ::: "memory")
#define CPA_WAIT1()  asm volatile("cp.async.wait_group 1;"  ::: "memory")

// ---- mma.sync / ldmatrix helpers (baseline PTX, sm_80+) --------------------
__device__ __forceinline__ uint32_t smem_to_u32(const void* p) {
    uint32_t a;
    asm("{ .reg .u64 t; cvta.to.shared.u64 t, %1; cvt.u32.u64 %0, t; }" : "=r"(a) : "l"(p));
    return a;
}
__device__ __forceinline__ void ldsm4(uint32_t* r, uint32_t addr) {
    asm volatile("ldmatrix.sync.aligned.m8n8.x4.shared.b16 {%0,%1,%2,%3}, [%4];"
        : "=r"(r[0]), "=r"(r[1]), "=r"(r[2]), "=r"(r[3]) : "r"(addr));
}
__device__ __forceinline__ void ldsm2(uint32_t* r, uint32_t addr) {
    asm volatile("ldmatrix.sync.aligned.m8n8.x2.shared.b16 {%0,%1}, [%2];"
        : "=r"(r[0]), "=r"(r[1]) : "r"(addr));
}
__device__ __forceinline__ void mma16816(float* d, const uint32_t* a, const uint32_t* b) {
    asm volatile("mma.sync.aligned.m16n8k16.row.col.f32.bf16.bf16.f32 "
        "{%0,%1,%2,%3}, {%4,%5,%6,%7}, {%8,%9}, {%0,%1,%2,%3};"
        : "+f"(d[0]), "+f"(d[1]), "+f"(d[2]), "+f"(d[3])
        : "r"(a[0]), "r"(a[1]), "r"(a[2]), "r"(a[3]), "r"(b[0]), "r"(b[1]));
}

__device__ __forceinline__ int swz(int b) { return b ^ ((b >> 3) & 0x70); }

__device__ __forceinline__ void split2(float v0, float v1, uint32_t& hi, uint32_t& lo) {
    __nv_bfloat16 h0 = __float2bfloat16(v0), h1 = __float2bfloat16(v1);
    float r0 = v0 - __bfloat162float(h0);
    float r1 = v1 - __bfloat162float(h1);
    __nv_bfloat16 l0 = __float2bfloat16(r0), l1 = __float2bfloat16(r1);
    hi = ((uint32_t)__bfloat16_as_ushort(h1) << 16) | __bfloat16_as_ushort(h0);
    lo = ((uint32_t)__bfloat16_as_ushort(l1) << 16) | __bfloat16_as_ushort(l0);
}
__device__ __forceinline__ float bfu(unsigned short u) {
    __nv_bfloat16_raw r; r.x = u;
    return __bfloat162float(__nv_bfloat16(r));
}

// ---------------- scratch ---------------------------------------------------
__device__ float g_h0 [HW * HD];
__device__ float g_h1 [HW * HD];
__device__ float g_t  [HW];
__device__ float g_o  [BATCH * HW * INNER];
// folded weight images: chunks [0,1]=W0'(=tooW@modW0), [2,3]=W1', [4..7]=hvW0
// each chunk: 2 n-halves x 32KB (hi 16K + lo 16K)
__device__ __align__(128) uint8_t g_WB[8 * 2 * 32768];
__device__ float g_b0p[256];   // toob@modW0 + modb0
__device__ float g_b1p[256];   // toob@modW1 + modb1
// attention images
__device__ __align__(128) uint8_t g_qb[2 * 128 * 32768];
__device__ __align__(128) uint8_t g_kb[8 * 65536];
__device__ __align__(128) uint8_t g_vb[8 * 65536];

// ============================================================================
// K0: fold tooW into modW0/modW1 (exact: no nonlinearity between), prep
// split-bf16 swizzled images for W0', W1', hvW0 + composite biases.
// ============================================================================
__global__ void k0_prepw(const float* __restrict__ tooW,
                         const float* __restrict__ modW0,
                         const float* __restrict__ modW1,
                         const float* __restrict__ hvW0,
                         const float* __restrict__ toob,
                         const float* __restrict__ modb0,
                         const float* __restrict__ modb1)
{
    int m = blockIdx.y;           // 0: W0', 1: W1', 2: hvW0
    int k = blockIdx.x;
    int n = threadIdx.x;
    float v;
    int chunk;
    if (m < 2) {
        if (k >= 128) return;
        const float* modW = (m == 0) ? modW0 : modW1;
        float s = 0.f;
        for (int j = 0; j < 256; j++)
            s = fmaf(tooW[k * 256 + j], modW[j * 256 + n], s);
        v = s;
        chunk = m * 2 + (k >> 6);
        if (k == 0) {   // composite bias
            float bb = 0.f;
            for (int j = 0; j < 256; j++)
                bb = fmaf(toob[j], modW[j * 256 + n], bb);
            if (m == 0) g_b0p[n] = bb + modb0[n];
            else        g_b1p[n] = bb + modb1[n];
        }
    } else {
        v = hvW0[k * 256 + n];
        chunk = 4 + (k >> 6);
    }
    __nv_bfloat16 h = __float2bfloat16(v);
    float rres = v - __bfloat162float(h);
    __nv_bfloat16 l = __float2bfloat16(rres);
    uint8_t* img = g_WB + ((size_t)chunk * 2 + (n >> 7)) * 32768;
    int b  = (n & 127) * 128 + (k & 63) * 2;
    int sw = swz(b);
    *(__nv_bfloat16*)(img + sw)         = h;
    *(__nv_bfloat16*)(img + 16384 + sw) = l;
}

// ============================================================================
// K1: grid-shared features (identical to R12).
// ============================================================================
__global__ void k1_grid(const float* __restrict__ coords,
                        const float* __restrict__ Bq,
                        const float* __restrict__ Bl0,
                        const float* __restrict__ Bl1,
                        const float* __restrict__ qW,  const float* __restrict__ qb,
                        const float* __restrict__ toqW,
                        const float* __restrict__ bwW0, const float* __restrict__ bwb0,
                        const float* __restrict__ bwW1, const float* __restrict__ bwb1)
{
    __shared__ float four[3][16][64];
    __shared__ float xq[16][256];
    const int tid  = threadIdx.x;
    const int base = blockIdx.x * 16;

    for (int it = tid; it < 3 * 16 * 32; it += 256) {
        int mat = it >> 9;
        int rem = it & 511;
        int r   = rem >> 5;
        int i   = rem & 31;
        float x = coords[(base + r) * 2 + 0];
        float y = coords[(base + r) * 2 + 1];
        const float* Bm = (mat == 0) ? Bq : (mat == 1 ? Bl0 : Bl1);
        float proj = TWO_PI * (x * Bm[i * 2] + y * Bm[i * 2 + 1]);
        float s, c;
        sincosf(proj, &s, &c);
        four[mat][r][i]      = c;
        four[mat][r][i + 32] = s;
    }
    if (tid < 16) {
        float x = coords[(base + tid) * 2 + 0];
        float y = coords[(base + tid) * 2 + 1];
        int row = (int)(x * 16.0f); row = min(max(row, 0), 15);
        int col = (int)(y * 16.0f); col = min(max(col, 0), 15);
        g_t[base + tid] = (float)(row * 16 + col) * (1.0f / 256.0f);
    }
    __syncthreads();

    {
        const int j = tid;
        float acc[16];
#pragma unroll
        for (int r = 0; r < 16; r++) acc[r] = 0.f;
        for (int k = 0; k < 64; k++) {
            float w = qW[k * 256 + j];
#pragma unroll
            for (int r = 0; r < 16; r++) acc[r] = fmaf(four[0][r][k], w, acc[r]);
        }
        float b = qb[j];
#pragma unroll
        for (int r = 0; r < 16; r++) xq[r][j] = fmaxf(acc[r] + b, 0.f);
    }
    __syncthreads();

    {
        const int j    = tid & 127;
        const int half = tid >> 7;
        float acc[8];
#pragma unroll
        for (int r = 0; r < 8; r++) acc[r] = 0.f;
        for (int k = 0; k < 256; k++) {
            float w = toqW[k * 128 + j];
#pragma unroll
            for (int r = 0; r < 8; r++) acc[r] = fmaf(xq[half * 8 + r][k], w, acc[r]);
        }
        const int h = j >> 6, d = j & 63;
        uint8_t* img = g_qb + ((size_t)(h * 128 + (base >> 7))) * 32768;
#pragma unroll
        for (int r = 0; r < 8; r++) {
            int rr = (base + half * 8 + r) & 127;
            float v = acc[r] * 0.125f;
            __nv_bfloat16 hb = __float2bfloat16(v);
            float res = v - __bfloat162float(hb);
            __nv_bfloat16 lb = __float2bfloat16(res);
            int sw = swz(rr * 128 + d * 2);
            *(__nv_bfloat16*)(img + sw)         = hb;
            *(__nv_bfloat16*)(img + 16384 + sw) = lb;
        }
    }

    {
        const int j = tid;
        float a0[16], a1[16];
#pragma unroll
        for (int r = 0; r < 16; r++) { a0[r] = 0.f; a1[r] = 0.f; }
        for (int k = 0; k < 64; k++) {
            float w0 = bwW0[k * 256 + j];
            float w1 = bwW1[k * 256 + j];
#pragma unroll
            for (int r = 0; r < 16; r++) {
                a0[r] = fmaf(four[1][r][k], w0, a0[r]);
                a1[r] = fmaf(four[2][r][k], w1, a1[r]);
            }
        }
        float b0 = bwb0[j], b1 = bwb1[j];
#pragma unroll
        for (int r = 0; r < 16; r++) {
            g_h0[(base + r) * 256 + j] = fmaxf(a0[r] + b0, 0.f);
            g_h1[(base + r) * 256 + j] = fmaxf(a1[r] + b1, 0.f);
        }
    }
}

// ============================================================================
// K2: kv = tokens @ tokvW -> split-bf16 swizzled k / v^T images (identical).
// ============================================================================
__global__ void k2_kv(const float* __restrict__ tokens,
                      const float* __restrict__ tokvW)
{
    __shared__ float tok[16][256];
    const int tile = blockIdx.x;
    const int b    = blockIdx.y;
    const int tid  = threadIdx.x;

    const float* tb = tokens + (b * MTOK + tile * 16) * 256;
    for (int i = tid; i < 16 * 256; i += 256) tok[i >> 8][i & 255] = tb[i];
    __syncthreads();

    const int j = tid;
    float acc[16];
#pragma unroll
    for (int r = 0; r < 16; r++) acc[r] = 0.f;
    for (int k = 0; k < 256; k++) {
        float w = tokvW[k * 256 + j];
#pragma unroll
        for (int r = 0; r < 16; r++) acc[r] = fmaf(tok[r][k], w, acc[r]);
    }
#pragma unroll
    for (int r = 0; r < 16; r++) {
        int m = tile * 16 + r;
        float v = acc[r];
        __nv_bfloat16 hb = __float2bfloat16(v);
        float res = v - __bfloat162float(hb);
        __nv_bfloat16 lb = __float2bfloat16(res);
        if (j < 128) {
            int h = j >> 6, d = j & 63;
            uint8_t* img = g_kb + (size_t)(b * 2 + h) * 65536;
            int sw = swz(m * 128 + d * 2);
            *(__nv_bfloat16*)(img + sw)         = hb;
            *(__nv_bfloat16*)(img + 32768 + sw) = lb;
        } else {
            int h = (j - 128) >> 6, d = (j - 128) & 63;
            uint8_t* img = g_vb + (size_t)(b * 2 + h) * 65536;
            int off = (m >> 6) * 8192 + swz(d * 128 + (m & 63) * 2);
            *(__nv_bfloat16*)(img + off)         = hb;
            *(__nv_bfloat16*)(img + 32768 + off) = lb;
        }
    }
}

// ============================================================================
// K3 flash-mma attention (identical to R12).
// ============================================================================
__global__ void __launch_bounds__(256) k3_fa()
{
    extern __shared__ uint8_t smem[];
    const uint32_t sb = smem_to_u32(smem);
    const int tid = threadIdx.x;
    const int w   = tid >> 5;
    const int l   = tid & 31;
    const int bx  = blockIdx.x;
    const int h   = blockIdx.y;
    const int b   = blockIdx.z;

    {
        const uint8_t* qsrc = g_qb + (size_t)(h * 128 + bx) * 32768;
        const uint8_t* ksrc = g_kb + (size_t)(b * 2 + h) * 65536;
        const uint8_t* vsrc = g_vb + (size_t)(b * 2 + h) * 65536;
        for (int i = tid; i < 2048; i += 256) cpa16(smem + i * 16, qsrc + i * 16);
        for (int i = tid; i < 4096; i += 256) cpa16(smem + 32768 + i * 16, ksrc + i * 16);
        for (int i = tid; i < 4096; i += 256) cpa16(smem + 98304 + i * 16, vsrc + i * 16);
        CPA_COMMIT();
        CPA_WAIT0();
        __syncthreads();
    }
    const uint32_t sQh = sb,          sQl = sb + 16384;
    const uint32_t sKh = sb + 32768,  sKl = sb + 65536;
    const uint32_t sVh = sb + 98304,  sVl = sb + 131072;

    const int r0 = bx * 128 + w * 16 + (l >> 2);
    const float tt0 = g_t[r0];
    const float tt1 = g_t[r0 + 8];

    float O[32];
#pragma unroll
    for (int i = 0; i < 32; i++) O[i] = 0.f;
    float Mx0 = -1e30f, Mx1 = -1e30f, S0 = 0.f, S1 = 0.f;

    const int aQrow = (w * 16 + (l & 15)) * 128 + (l >> 4) * 16;

#pragma unroll 1
    for (int t = 0; t < 4; t++) {
        float Sa[32];
#pragma unroll
        for (int i = 0; i < 32; i++) Sa[i] = 0.f;

#pragma unroll
        for (int kk = 0; kk < 4; kk++) {
            int asw = swz(aQrow + kk * 32);
            uint32_t ahi[4], alo[4];
            ldsm4(ahi, sQh + asw);
            ldsm4(alo, sQl + asw);
#pragma unroll
            for (int nt = 0; nt < 8; nt++) {
                int bsw = swz((t * 64 + nt * 8 + (l & 7)) * 128 + kk * 32 + ((l >> 3) & 1) * 16);
                uint32_t bhi[2], blo[2];
                ldsm2(bhi, sKh + bsw);
                ldsm2(blo, sKl + bsw);
                mma16816(&Sa[nt * 4], ahi, bhi);
                mma16816(&Sa[nt * 4], ahi, blo);
                mma16816(&Sa[nt * 4], alo, bhi);
            }
        }

        float tm0 = -1e30f, tm1 = -1e30f;
#pragma unroll
        for (int nt = 0; nt < 8; nt++) {
            float* a = &Sa[nt * 4];
            float c0 = (float)(t * 64 + nt * 8 + (l & 3) * 2);
            float p0 = (c0 + 0.5f) * (1.0f / 256.0f);
            float p1 = (c0 + 1.5f) * (1.0f / 256.0f);
            float d00 = tt0 - p0, d01 = tt0 - p1;
            float d10 = tt1 - p0, d11 = tt1 - p1;
            a[0] -= 10.f * d00 * d00;
            a[1] -= 10.f * d01 * d01;
            a[2] -= 10.f * d10 * d10;
            a[3] -= 10.f * d11 * d11;
            tm0 = fmaxf(tm0, fmaxf(a[0], a[1]));
            tm1 = fmaxf(tm1, fmaxf(a[2], a[3]));
        }
        tm0 = fmaxf(tm0, __shfl_xor_sync(0xffffffffu, tm0, 1));
        tm0 = fmaxf(tm0, __shfl_xor_sync(0xffffffffu, tm0, 2));
        tm1 = fmaxf(tm1, __shfl_xor_sync(0xffffffffu, tm1, 1));
        tm1 = fmaxf(tm1, __shfl_xor_sync(0xffffffffu, tm1, 2));
        float nM0 = fmaxf(Mx0, tm0), nM1 = fmaxf(Mx1, tm1);
        float cr0 = __expf(Mx0 - nM0), cr1 = __expf(Mx1 - nM1);
        Mx0 = nM0; Mx1 = nM1;
        S0 *= cr0; S1 *= cr1;
#pragma unroll
        for (int nt = 0; nt < 8; nt++) {
            O[nt * 4 + 0] *= cr0; O[nt * 4 + 1] *= cr0;
            O[nt * 4 + 2] *= cr1; O[nt * 4 + 3] *= cr1;
        }
#pragma unroll
        for (int nt = 0; nt < 8; nt++) {
            float* a = &Sa[nt * 4];
            a[0] = __expf(a[0] - Mx0);
            a[1] = __expf(a[1] - Mx0);
            a[2] = __expf(a[2] - Mx1);
            a[3] = __expf(a[3] - Mx1);
            S0 += a[0] + a[1];
            S1 += a[2] + a[3];
        }

#pragma unroll
        for (int kk = 0; kk < 4; kk++) {
            uint32_t phi[4], plo[4];
            float* pA = &Sa[(2 * kk) * 4];
            float* pB = &Sa[(2 * kk + 1) * 4];
            split2(pA[0], pA[1], phi[0], plo[0]);
            split2(pA[2], pA[3], phi[1], plo[1]);
            split2(pB[0], pB[1], phi[2], plo[2]);
            split2(pB[2], pB[3], phi[3], plo[3]);
#pragma unroll
            for (int nt = 0; nt < 8; nt++) {
                int vsw = t * 8192 + swz((nt * 8 + (l & 7)) * 128 + kk * 32 + ((l >> 3) & 1) * 16);
                uint32_t vhi[2], vlo[2];
                ldsm2(vhi, sVh + vsw);
                ldsm2(vlo, sVl + vsw);
                mma16816(&O[nt * 4], phi, vhi);
                mma16816(&O[nt * 4], phi, vlo);
                mma16816(&O[nt * 4], plo, vhi);
            }
        }
    }

    S0 += __shfl_xor_sync(0xffffffffu, S0, 1);
    S0 += __shfl_xor_sync(0xffffffffu, S0, 2);
    S1 += __shfl_xor_sync(0xffffffffu, S1, 1);
    S1 += __shfl_xor_sync(0xffffffffu, S1, 2);
    float inv0 = 1.0f / S0, inv1 = 1.0f / S1;
#pragma unroll
    for (int nt = 0; nt < 8; nt++) {
        int col = h * 64 + nt * 8 + (l & 3) * 2;
        float2 o0, o1;
        o0.x = O[nt * 4 + 0] * inv0; o0.y = O[nt * 4 + 1] * inv0;
        o1.x = O[nt * 4 + 2] * inv1; o1.y = O[nt * 4 + 3] * inv1;
        *(float2*)&g_o[((size_t)b * HW + r0) * 128 + col]       = o0;
        *(float2*)&g_o[((size_t)b * HW + r0 + 8) * 128 + col]   = o1;
    }
}

// ============================================================================
// K5 v2 (folded): 3 GEMM stages only.
//  A: m0 = relu(h0 + o@W0' + b0')      (K=128)
//  B: x  = m0 + relu(h1 + o@W1' + b1') (K=128)
//  C: hv1 = relu(x@hvW0 + hvb)         (K=256)
// Output projections folded into epilogues A and C.
// ============================================================================
#define SMB_O     0          // o image: hi 16K + lo 16K = 32K
#define SMB_X     32768      // m0/x image: hi 32K + lo 32K = 64K
#define SMB_B     98304      // 2 x 32K B chunk buffers
#define SMB_CONST 163840     // b0p|b1p|hvb|OW0|OW1 (2304 floats)
#define SMB_PSM   173056     // 64 x 3 fp32
#define SMB_TOTAL 173824

__device__ __forceinline__ void run_gemm(char* smem, uint32_t sb, int Aoff, int loA,
                                         int mstart, int nch, int pass,
                                         int m0w, int n0p, int tid, int l,
                                         float* acc)
{
    {
        const uint8_t* src = g_WB + ((size_t)mstart * 2 + pass) * 32768;
        char* dst = smem + SMB_B;
#pragma unroll
        for (int it = 0; it < 8; it++) {
            int i = (it * 256 + tid) * 16;
            cpa16(dst + i, src + i);
        }
        CPA_COMMIT();
    }
    for (int c = 0; c < nch; c++) {
        if (c + 1 < nch) {
            const uint8_t* src = g_WB + ((size_t)(mstart + c + 1) * 2 + pass) * 32768;
            char* dst = smem + SMB_B + ((c + 1) & 1) * 32768;
#pragma unroll
            for (int it = 0; it < 8; it++) {
                int i = (it * 256 + tid) * 16;
                cpa16(dst + i, src + i);
            }
            CPA_COMMIT();
            CPA_WAIT1();
        } else {
            CPA_WAIT0();
        }
        __syncthreads();

        const uint32_t bB   = sb + SMB_B + (c & 1) * 32768;
        const uint32_t bAhi = sb + Aoff + c * 8192;
        const uint32_t bAlo = bAhi + loA;

#pragma unroll
        for (int t4 = 0; t4 < 4; t4++) {
            uint32_t ahi[2][4], alo[2][4];
            const int arow = l & 15;
            const int akb  = t4 * 32 + (l >> 4) * 16;
#pragma unroll
            for (int mt = 0; mt < 2; mt++) {
                int ab = (m0w + mt * 16 + arow) * 128 + akb;
                int sw = swz(ab);
                ldsm4(ahi[mt], bAhi + sw);
                ldsm4(alo[mt], bAlo + sw);
            }
#pragma unroll
            for (int nt = 0; nt < 4; nt++) {
                const int nrow = n0p + nt * 8 + (l & 7);
                int bb = nrow * 128 + t4 * 32 + ((l >> 3) & 1) * 16;
                int sw = swz(bb);
                uint32_t bhi[2], blo[2];
                ldsm2(bhi, bB + sw);
                ldsm2(blo, bB + 16384 + sw);
                float* a0 = acc + (0 * 4 + nt) * 4;
                float* a1 = acc + (1 * 4 + nt) * 4;
                mma16816(a0, ahi[0], bhi);
                mma16816(a1, ahi[1], bhi);
                mma16816(a0, ahi[0], blo);
                mma16816(a1, ahi[1], blo);
                mma16816(a0, alo[0], bhi);
                mma16816(a1, alo[1], bhi);
            }
        }
        __syncthreads();
    }
}

__global__ void __launch_bounds__(256, 1) k5_mma(
    const float* __restrict__ hvb0,
    const float* __restrict__ outW0, const float* __restrict__ outb0,
    const float* __restrict__ outW1, const float* __restrict__ outb1,
    float* __restrict__ out)
{
    extern __shared__ char smemc[];
    char* smem = smemc;
    const uint32_t sb = smem_to_u32(smem);
    const int tid  = threadIdx.x;
    const int w    = tid >> 5;
    const int l    = tid & 31;
    const int m0w  = 32 * (w & 1);
    const int n0p  = 32 * (w >> 1);
    const int base = blockIdx.x * 64;
    const int hb   = base & (HW - 1);

    float* sC   = (float*)(smem + SMB_CONST);
    float* sB0  = sC;            // 256
    float* sB1  = sC + 256;      // 256
    float* sHvb = sC + 512;      // 256
    float* sOW0 = sC + 768;      // 768
    float* sOW1 = sC + 1536;     // 768
    float* pSM  = (float*)(smem + SMB_PSM);

    for (int i = tid; i < 256; i += 256) {
        sB0[i]  = g_b0p[i];
        sB1[i]  = g_b1p[i];
        sHvb[i] = hvb0[i];
    }
    for (int i = tid; i < 768; i += 256) {
        sOW0[i] = outW0[i];
        sOW1[i] = outW1[i];
    }
    for (int i = tid; i < 192; i += 256) pSM[i] = 0.f;

    // load o (64x128) -> split bf16 image in SMB_O (2 k-chunks, lo at +16384)
    for (int i = tid; i < 64 * 64; i += 256) {
        int r  = i >> 6;
        int kp = i & 63;
        int k  = kp * 2;
        float2 v = *(const float2*)&g_o[((size_t)(base + r)) * 128 + k];
        uint32_t hi, lo;
        split2(v.x, v.y, hi, lo);
        int kc = k >> 6;
        int sw = swz(r * 128 + (k & 63) * 2);
        *(uint32_t*)(smem + SMB_O + kc * 8192 + sw)         = hi;
        *(uint32_t*)(smem + SMB_O + 16384 + kc * 8192 + sw) = lo;
    }
    __syncthreads();

    float acc[32];
    float p[12];
#pragma unroll
    for (int i = 0; i < 12; i++) p[i] = 0.f;

    // ===== stage A: m0 = relu(h0 + o@W0' + b0') -> SMB_X; proj OW0 ==========
#pragma unroll 1
    for (int pass = 0; pass < 2; pass++) {
#pragma unroll
        for (int i = 0; i < 32; i++) acc[i] = 0.f;
        run_gemm(smem, sb, SMB_O, 16384, 0, 2, pass, m0w, n0p, tid, l, acc);
#pragma unroll
        for (int mt = 0; mt < 2; mt++)
#pragma unroll
        for (int nt = 0; nt < 4; nt++) {
            float* a = acc + (mt * 4 + nt) * 4;
            int c0 = pass * 128 + n0p + nt * 8 + (l & 3) * 2;
            int rA = m0w + mt * 16 + (l >> 2);
            float b0 = sB0[c0], b1 = sB0[c0 + 1];
            int kc = c0 >> 6;
            int bby = (c0 & 63) * 2;
#pragma unroll
            for (int half = 0; half < 2; half++) {
                int r = rA + half * 8;
                float2 h0 = *(const float2*)&g_h0[((size_t)(hb + r)) * 256 + c0];
                float v0 = fmaxf(h0.x + a[half * 2 + 0] + b0, 0.f);
                float v1 = fmaxf(h0.y + a[half * 2 + 1] + b1, 0.f);
                int slot = mt * 2 + half;
                p[slot * 3 + 0] = fmaf(v0, sOW0[c0 * 3 + 0], fmaf(v1, sOW0[c0 * 3 + 3], p[slot * 3 + 0]));
                p[slot * 3 + 1] = fmaf(v0, sOW0[c0 * 3 + 1], fmaf(v1, sOW0[c0 * 3 + 4], p[slot * 3 + 1]));
                p[slot * 3 + 2] = fmaf(v0, sOW0[c0 * 3 + 2], fmaf(v1, sOW0[c0 * 3 + 5], p[slot * 3 + 2]));
                uint32_t hi, lo;
                split2(v0, v1, hi, lo);
                int sw = swz(r * 128 + bby);
                *(uint32_t*)(smem + SMB_X + kc * 8192 + sw)         = hi;
                *(uint32_t*)(smem + SMB_X + 32768 + kc * 8192 + sw) = lo;
            }
        }
    }
    __syncthreads();

    // ===== stage B: x = m0 + relu(h1 + o@W1' + b1') -> SMB_X ================
#pragma unroll 1
    for (int pass = 0; pass < 2; pass++) {
#pragma unroll
        for (int i = 0; i < 32; i++) acc[i] = 0.f;
        run_gemm(smem, sb, SMB_O, 16384, 2, 2, pass, m0w, n0p, tid, l, acc);
#pragma unroll
        for (int mt = 0; mt < 2; mt++)
#pragma unroll
        for (int nt = 0; nt < 4; nt++) {
            float* a = acc + (mt * 4 + nt) * 4;
            int c0 = pass * 128 + n0p + nt * 8 + (l & 3) * 2;
            int rA = m0w + mt * 16 + (l >> 2);
            float b0 = sB1[c0], b1 = sB1[c0 + 1];
            int kc = c0 >> 6;
            int bby = (c0 & 63) * 2;
#pragma unroll
            for (int half = 0; half < 2; half++) {
                int r = rA + half * 8;
                float2 h1 = *(const float2*)&g_h1[((size_t)(hb + r)) * 256 + c0];
                float m10 = fmaxf(h1.x + a[half * 2 + 0] + b0, 0.f);
                float m11 = fmaxf(h1.y + a[half * 2 + 1] + b1, 0.f);
                int sw = swz(r * 128 + bby);
                uint32_t mh = *(uint32_t*)(smem + SMB_X + kc * 8192 + sw);
                uint32_t ml = *(uint32_t*)(smem + SMB_X + 32768 + kc * 8192 + sw);
                float x0 = bfu((unsigned short)(mh & 0xffff)) + bfu((unsigned short)(ml & 0xffff)) + m10;
                float x1 = bfu((unsigned short)(mh >> 16))    + bfu((unsigned short)(ml >> 16))    + m11;
                uint32_t hi, lo;
                split2(x0, x1, hi, lo);
                *(uint32_t*)(smem + SMB_X + kc * 8192 + sw)         = hi;
                *(uint32_t*)(smem + SMB_X + 32768 + kc * 8192 + sw) = lo;
            }
        }
    }
    __syncthreads();

    // ===== stage C: hv1 = relu(x@hvW0 + b); proj OW1 ========================
#pragma unroll 1
    for (int pass = 0; pass < 2; pass++) {
#pragma unroll
        for (int i = 0; i < 32; i++) acc[i] = 0.f;
        run_gemm(smem, sb, SMB_X, 32768, 4, 4, pass, m0w, n0p, tid, l, acc);
#pragma unroll
        for (int mt = 0; mt < 2; mt++)
#pragma unroll
        for (int nt = 0; nt < 4; nt++) {
            float* a = acc + (mt * 4 + nt) * 4;
            int c0 = pass * 128 + n0p + nt * 8 + (l & 3) * 2;
            float b0 = sHvb[c0], b1 = sHvb[c0 + 1];
#pragma unroll
            for (int half = 0; half < 2; half++) {
                float v0 = fmaxf(a[half * 2 + 0] + b0, 0.f);
                float v1 = fmaxf(a[half * 2 + 1] + b1, 0.f);
                int slot = mt * 2 + half;
                p[slot * 3 + 0] = fmaf(v0, sOW1[c0 * 3 + 0], fmaf(v1, sOW1[c0 * 3 + 3], p[slot * 3 + 0]));
                p[slot * 3 + 1] = fmaf(v0, sOW1[c0 * 3 + 1], fmaf(v1, sOW1[c0 * 3 + 4], p[slot * 3 + 1]));
                p[slot * 3 + 2] = fmaf(v0, sOW1[c0 * 3 + 2], fmaf(v1, sOW1[c0 * 3 + 5], p[slot * 3 + 2]));
            }
        }
    }

    // ---- reduce projections ----
#pragma unroll
    for (int slot = 0; slot < 4; slot++) {
        int r = m0w + (slot >> 1) * 16 + (l >> 2) + (slot & 1) * 8;
#pragma unroll
        for (int j = 0; j < 3; j++) {
            float v = p[slot * 3 + j];
            v += __shfl_xor_sync(0xffffffffu, v, 1);
            v += __shfl_xor_sync(0xffffffffu, v, 2);
            if ((l & 3) == 0) atomicAdd(&pSM[r * 3 + j], v);
        }
    }
    __syncthreads();

    for (int i = tid; i < 192; i += 256) {
        int r = i / 3, j = i - r * 3;
        out[((size_t)(base + r)) * 3 + j] = pSM[i] + outb0[j] + outb1[j];
    }
}

// ============================================================================
extern "C" void kernel_launch(void* const* d_in, const int* in_sizes, int n_in,
                              void* d_out, int out_size)
{
    const float* coords = (const float*)d_in[0];
    const float* tokens = (const float*)d_in[1];
    const float* B_q    = (const float*)d_in[2];
    const float* B_l0   = (const float*)d_in[3];
    const float* B_l1   = (const float*)d_in[4];
    const float* qW     = (const float*)d_in[5];
    const float* qb     = (const float*)d_in[6];
    const float* toqW   = (const float*)d_in[7];
    const float* tokvW  = (const float*)d_in[8];
    const float* tooW   = (const float*)d_in[9];
    const float* toob   = (const float*)d_in[10];
    const float* bwW0   = (const float*)d_in[11];
    const float* bwb0   = (const float*)d_in[12];
    const float* bwW1   = (const float*)d_in[13];
    const float* bwb1   = (const float*)d_in[14];
    const float* modW0  = (const float*)d_in[15];
    const float* modb0  = (const float*)d_in[16];
    const float* modW1  = (const float*)d_in[17];
    const float* modb1  = (const float*)d_in[18];
    const float* hvW0   = (const float*)d_in[19];
    const float* hvb0   = (const float*)d_in[20];
    const float* outW0  = (const float*)d_in[21];
    const float* outb0  = (const float*)d_in[22];
    const float* outW1  = (const float*)d_in[23];
    const float* outb1  = (const float*)d_in[24];
    float* out = (float*)d_out;

    cudaFuncSetAttribute(k3_fa,  cudaFuncAttributeMaxDynamicSharedMemorySize, 163840);
    cudaFuncSetAttribute(k5_mma, cudaFuncAttributeMaxDynamicSharedMemorySize, SMB_TOTAL);

    k0_prepw<<<dim3(256, 3), 256>>>(tooW, modW0, modW1, hvW0, toob, modb0, modb1);
    k1_grid<<<HW / 16, 256>>>(coords, B_q, B_l0, B_l1, qW, qb, toqW,
                              bwW0, bwb0, bwW1, bwb1);
    k2_kv<<<dim3(MTOK / 16, BATCH), 256>>>(tokens, tokvW);
    k3_fa<<<dim3(HW / 128, 2, BATCH), 256, 163840>>>();
    k5_mma<<<(BATCH * HW) / 64, 256, SMB_TOTAL>>>(hvb0, outW0, outb0, outW1, outb1,
                                                  out);
}

// round 14
// speedup vs baseline: 2.4651x; 1.1657x over previous
#include <cuda_runtime.h>
#include <cuda_bf16.h>
#include <math.h>
#include <cstdint>

#define HW      16384
#define BATCH   4
#define MTOK    256
#define HD      256
#define INNER   128
#define DH      64

#define TWO_PI 6.2831853071795864769f

typedef unsigned long long u64;

// ---- cp.async helpers ------------------------------------------------------
__device__ __forceinline__ void cpa16(void* dst, const void* src) {
    unsigned d = (unsigned)__cvta_generic_to_shared(dst);
    asm volatile("cp.async.ca.shared.global [%0], [%1], 16;" :: "r"(d), "l"(src));
}
#define CPA_COMMIT() asm volatile("cp.async.commit_group;" ::: "memory")
#define CPA_WAIT0()  asm volatile("cp.async.wait_group 0;"  ::: "memory")
#define CPA_WAIT1()  asm volatile("cp.async.wait_group 1;"  ::: "memory")

// ---- mma.sync / ldmatrix helpers (baseline PTX, sm_80+) --------------------
__device__ __forceinline__ uint32_t smem_to_u32(const void* p) {
    uint32_t a;
    asm("{ .reg .u64 t; cvta.to.shared.u64 t, %1; cvt.u32.u64 %0, t; }" : "=r"(a) : "l"(p));
    return a;
}
__device__ __forceinline__ void ldsm4(uint32_t* r, uint32_t addr) {
    asm volatile("ldmatrix.sync.aligned.m8n8.x4.shared.b16 {%0,%1,%2,%3}, [%4];"
        : "=r"(r[0]), "=r"(r[1]), "=r"(r[2]), "=r"(r[3]) : "r"(addr));
}
__device__ __forceinline__ void ldsm2(uint32_t* r, uint32_t addr) {
    asm volatile("ldmatrix.sync.aligned.m8n8.x2.shared.b16 {%0,%1}, [%2];"
        : "=r"(r[0]), "=r"(r[1]) : "r"(addr));
}
__device__ __forceinline__ void mma16816(float* d, const uint32_t* a, const uint32_t* b) {
    asm volatile("mma.sync.aligned.m16n8k16.row.col.f32.bf16.bf16.f32 "
        "{%0,%1,%2,%3}, {%4,%5,%6,%7}, {%8,%9}, {%0,%1,%2,%3};"
        : "+f"(d[0]), "+f"(d[1]), "+f"(d[2]), "+f"(d[3])
        : "r"(a[0]), "r"(a[1]), "r"(a[2]), "r"(a[3]), "r"(b[0]), "r"(b[1]));
}

__device__ __forceinline__ int swz(int b) { return b ^ ((b >> 3) & 0x70); }

__device__ __forceinline__ void split2(float v0, float v1, uint32_t& hi, uint32_t& lo) {
    __nv_bfloat16 h0 = __float2bfloat16(v0), h1 = __float2bfloat16(v1);
    float r0 = v0 - __bfloat162float(h0);
    float r1 = v1 - __bfloat162float(h1);
    __nv_bfloat16 l0 = __float2bfloat16(r0), l1 = __float2bfloat16(r1);
    hi = ((uint32_t)__bfloat16_as_ushort(h1) << 16) | __bfloat16_as_ushort(h0);
    lo = ((uint32_t)__bfloat16_as_ushort(l1) << 16) | __bfloat16_as_ushort(l0);
}
__device__ __forceinline__ void split1(float v, __nv_bfloat16& h, __nv_bfloat16& l) {
    h = __float2bfloat16(v);
    l = __float2bfloat16(v - __bfloat162float(h));
}
__device__ __forceinline__ float bfu(unsigned short u) {
    __nv_bfloat16_raw r; r.x = u;
    return __bfloat162float(__nv_bfloat16(r));
}

// ---------------- scratch ---------------------------------------------------
__device__ float g_h0 [HW * HD];
__device__ float g_h1 [HW * HD];
__device__ float g_t  [HW];
__device__ float g_o  [BATCH * HW * INNER];
// weight images, 32KB packages (hi 16K + lo 16K), index (chunk*2 + nhalf):
//  [0,1]=W0'(tooW@modW0)  [2,3]=W1'  [4..7]=hvW0
//  [8]=qW(K=64)  [9]=bwW0  [10]=bwW1  [11..14]=toqW(256x128, nhalf 0 only)
__device__ __align__(128) uint8_t g_WB[15 * 2 * 32768];
__device__ float g_b0p[256];
__device__ float g_b1p[256];
// attention images
__device__ __align__(128) uint8_t g_qb[2 * 128 * 32768];
__device__ __align__(128) uint8_t g_kb[8 * 65536];
__device__ __align__(128) uint8_t g_vb[8 * 65536];

// ============================================================================
// K0: fold tooW@modW{0,1}; prep all split-bf16 swizzled weight images.
// ============================================================================
__global__ void k0_prepw(const float* __restrict__ tooW,
                         const float* __restrict__ modW0,
                         const float* __restrict__ modW1,
                         const float* __restrict__ hvW0,
                         const float* __restrict__ toob,
                         const float* __restrict__ modb0,
                         const float* __restrict__ modb1,
                         const float* __restrict__ qW,
                         const float* __restrict__ bwW0,
                         const float* __restrict__ bwW1,
                         const float* __restrict__ toqW)
{
    int m = blockIdx.y;           // 0..6
    int k = blockIdx.x;
    int n = threadIdx.x;
    float v;
    int chunk, nh, nrow;
    if (m < 2) {
        if (k >= 128) return;
        const float* modW = (m == 0) ? modW0 : modW1;
        float s = 0.f;
        for (int j = 0; j < 256; j++)
            s = fmaf(tooW[k * 256 + j], modW[j * 256 + n], s);
        v = s;
        chunk = m * 2 + (k >> 6);
        nh = n >> 7; nrow = n & 127;
        if (k == 0) {
            float bb = 0.f;
            for (int j = 0; j < 256; j++)
                bb = fmaf(toob[j], modW[j * 256 + n], bb);
            if (m == 0) g_b0p[n] = bb + modb0[n];
            else        g_b1p[n] = bb + modb1[n];
        }
    } else if (m == 2) {
        v = hvW0[k * 256 + n];
        chunk = 4 + (k >> 6); nh = n >> 7; nrow = n & 127;
    } else if (m == 3) {
        if (k >= 64) return;
        v = qW[k * 256 + n];
        chunk = 8; nh = n >> 7; nrow = n & 127;
    } else if (m == 4) {
        if (k >= 64) return;
        v = bwW0[k * 256 + n];
        chunk = 9; nh = n >> 7; nrow = n & 127;
    } else if (m == 5) {
        if (k >= 64) return;
        v = bwW1[k * 256 + n];
        chunk = 10; nh = n >> 7; nrow = n & 127;
    } else {
        if (n >= 128) return;
        v = toqW[k * 128 + n];
        chunk = 11 + (k >> 6); nh = 0; nrow = n;
    }
    __nv_bfloat16 h, l;
    split1(v, h, l);
    uint8_t* img = g_WB + ((size_t)chunk * 2 + nh) * 32768;
    int sw = swz(nrow * 128 + (k & 63) * 2);
    *(__nv_bfloat16*)(img + sw)         = h;
    *(__nv_bfloat16*)(img + 16384 + sw) = l;
}

// ============================================================================
// shared GEMM step: stream B chunk packages from g_WB, mma split-bf16.
// A image: [row][k] swizzled, k-chunks of 8192 bytes; lo image at +loA.
// ============================================================================
__device__ __forceinline__ void run_gemm(char* smem, uint32_t sb, int Aoff, int loA,
                                         int mstart, int nch, int pass,
                                         int bufOff,
                                         int m0w, int n0p, int tid, int l,
                                         float* acc)
{
    {
        const uint8_t* src = g_WB + ((size_t)mstart * 2 + pass) * 32768;
        char* dst = smem + bufOff;
#pragma unroll
        for (int it = 0; it < 8; it++) {
            int i = (it * 256 + tid) * 16;
            cpa16(dst + i, src + i);
        }
        CPA_COMMIT();
    }
    for (int c = 0; c < nch; c++) {
        if (c + 1 < nch) {
            const uint8_t* src = g_WB + ((size_t)(mstart + c + 1) * 2 + pass) * 32768;
            char* dst = smem + bufOff + ((c + 1) & 1) * 32768;
#pragma unroll
            for (int it = 0; it < 8; it++) {
                int i = (it * 256 + tid) * 16;
                cpa16(dst + i, src + i);
            }
            CPA_COMMIT();
            CPA_WAIT1();
        } else {
            CPA_WAIT0();
        }
        __syncthreads();

        const uint32_t bB   = sb + bufOff + (c & 1) * 32768;
        const uint32_t bAhi = sb + Aoff + c * 8192;
        const uint32_t bAlo = bAhi + loA;

#pragma unroll
        for (int t4 = 0; t4 < 4; t4++) {
            uint32_t ahi[2][4], alo[2][4];
            const int arow = l & 15;
            const int akb  = t4 * 32 + (l >> 4) * 16;
#pragma unroll
            for (int mt = 0; mt < 2; mt++) {
                int ab = (m0w + mt * 16 + arow) * 128 + akb;
                int sw = swz(ab);
                ldsm4(ahi[mt], bAhi + sw);
                ldsm4(alo[mt], bAlo + sw);
            }
#pragma unroll
            for (int nt = 0; nt < 4; nt++) {
                const int nrow = n0p + nt * 8 + (l & 7);
                int bb = nrow * 128 + t4 * 32 + ((l >> 3) & 1) * 16;
                int sw = swz(bb);
                uint32_t bhi[2], blo[2];
                ldsm2(bhi, bB + sw);
                ldsm2(blo, bB + 16384 + sw);
                float* a0 = acc + (0 * 4 + nt) * 4;
                float* a1 = acc + (1 * 4 + nt) * 4;
                mma16816(a0, ahi[0], bhi);
                mma16816(a1, ahi[1], bhi);
                mma16816(a0, ahi[0], blo);
                mma16816(a1, ahi[1], blo);
                mma16816(a0, alo[0], bhi);
                mma16816(a1, alo[1], bhi);
            }
        }
        __syncthreads();
    }
}

// ============================================================================
// K1 mma: grid features on tensor cores. CTA = 64 rows, 256 threads.
//  FOUR images (3 mats, K=64) -> xq = relu(four0@qW+qb) -> q = xq@toqW * 1/8
//  h0/h1 = relu(four{1,2}@bwW{0,1} + b) -> g_h0/g_h1.
// ============================================================================
#define SM1_FOUR  0        // 3 x (hi 8K + lo 8K) = 48K
#define SM1_XQ    49152    // hi 32K + lo 32K = 64K
#define SM1_B     114688   // 2 x 32K
#define SM1_TOTAL 180224

__global__ void __launch_bounds__(256) k1_mma(
    const float* __restrict__ coords,
    const float* __restrict__ Bq,
    const float* __restrict__ Bl0,
    const float* __restrict__ Bl1,
    const float* __restrict__ qb,
    const float* __restrict__ bwb0,
    const float* __restrict__ bwb1)
{
    extern __shared__ uint8_t smemu[];
    char* smem = (char*)smemu;
    const uint32_t sb = smem_to_u32(smem);
    const int tid  = threadIdx.x;
    const int w    = tid >> 5;
    const int l    = tid & 31;
    const int m0w  = 32 * (w & 1);
    const int n0p  = 32 * (w >> 1);
    const int base = blockIdx.x * 64;

    // ---- fourier features -> split-bf16 A images ----
    for (int it = tid; it < 3 * 64 * 32; it += 256) {
        int mat = it >> 11;
        int rem = it & 2047;
        int r   = rem >> 5;
        int f   = rem & 31;
        float x = coords[(base + r) * 2 + 0];
        float y = coords[(base + r) * 2 + 1];
        const float* Bm = (mat == 0) ? Bq : (mat == 1 ? Bl0 : Bl1);
        float proj = TWO_PI * (x * Bm[f * 2] + y * Bm[f * 2 + 1]);
        float s, c;
        sincosf(proj, &s, &c);
        uint8_t* img = (uint8_t*)smem + SM1_FOUR + mat * 16384;
        __nv_bfloat16 hb, lb;
        split1(c, hb, lb);
        int sw = swz(r * 128 + f * 2);
        *(__nv_bfloat16*)(img + sw)        = hb;
        *(__nv_bfloat16*)(img + 8192 + sw) = lb;
        split1(s, hb, lb);
        sw = swz(r * 128 + (f + 32) * 2);
        *(__nv_bfloat16*)(img + sw)        = hb;
        *(__nv_bfloat16*)(img + 8192 + sw) = lb;
    }
    if (tid < 64) {
        float x = coords[(base + tid) * 2 + 0];
        float y = coords[(base + tid) * 2 + 1];
        int row = (int)(x * 16.0f); row = min(max(row, 0), 15);
        int col = (int)(y * 16.0f); col = min(max(col, 0), 15);
        g_t[base + tid] = (float)(row * 16 + col) * (1.0f / 256.0f);
    }
    __syncthreads();

    float acc[32];

    // ---- xq = relu(four0 @ qW + qb) -> XQ image ----
#pragma unroll 1
    for (int pass = 0; pass < 2; pass++) {
#pragma unroll
        for (int i = 0; i < 32; i++) acc[i] = 0.f;
        run_gemm(smem, sb, SM1_FOUR, 8192, 8, 1, pass, SM1_B, m0w, n0p, tid, l, acc);
#pragma unroll
        for (int mt = 0; mt < 2; mt++)
#pragma unroll
        for (int nt = 0; nt < 4; nt++) {
            float* a = acc + (mt * 4 + nt) * 4;
            int c0 = pass * 128 + n0p + nt * 8 + (l & 3) * 2;
            int rA = m0w + mt * 16 + (l >> 2);
            float b0 = qb[c0], b1 = qb[c0 + 1];
            int kc = c0 >> 6;
            int bby = (c0 & 63) * 2;
#pragma unroll
            for (int half = 0; half < 2; half++) {
                int r = rA + half * 8;
                float v0 = fmaxf(a[half * 2 + 0] + b0, 0.f);
                float v1 = fmaxf(a[half * 2 + 1] + b1, 0.f);
                uint32_t hi, lo;
                split2(v0, v1, hi, lo);
                int sw = swz(r * 128 + bby);
                *(uint32_t*)(smem + SM1_XQ + kc * 8192 + sw)         = hi;
                *(uint32_t*)(smem + SM1_XQ + 32768 + kc * 8192 + sw) = lo;
            }
        }
    }
    __syncthreads();

    // ---- q = (xq @ toqW) * 0.125 -> g_qb (single 128-col pass) ----
    {
#pragma unroll
        for (int i = 0; i < 32; i++) acc[i] = 0.f;
        run_gemm(smem, sb, SM1_XQ, 32768, 11, 4, 0, SM1_B, m0w, n0p, tid, l, acc);
        const int tile = base >> 7;
        const int rb   = base & 127;
#pragma unroll
        for (int mt = 0; mt < 2; mt++)
#pragma unroll
        for (int nt = 0; nt < 4; nt++) {
            float* a = acc + (mt * 4 + nt) * 4;
            int c0 = n0p + nt * 8 + (l & 3) * 2;
            int h = c0 >> 6, d = c0 & 63;
            uint8_t* img = g_qb + (size_t)(h * 128 + tile) * 32768;
            int rA = m0w + mt * 16 + (l >> 2);
#pragma unroll
            for (int half = 0; half < 2; half++) {
                int rr = rb + rA + half * 8;
                float v0 = a[half * 2 + 0] * 0.125f;
                float v1 = a[half * 2 + 1] * 0.125f;
                uint32_t hi, lo;
                split2(v0, v1, hi, lo);
                int sw = swz(rr * 128 + d * 2);
                *(uint32_t*)(img + sw)         = hi;
                *(uint32_t*)(img + 16384 + sw) = lo;
            }
        }
    }

    // ---- h0 / h1 = relu(four{1,2} @ bwW{0,1} + b) -> g_h0/g_h1 ----
#pragma unroll 1
    for (int mat = 0; mat < 2; mat++) {
        const float* bw = mat ? bwb1 : bwb0;
        float* gh = mat ? g_h1 : g_h0;
#pragma unroll 1
        for (int pass = 0; pass < 2; pass++) {
#pragma unroll
            for (int i = 0; i < 32; i++) acc[i] = 0.f;
            run_gemm(smem, sb, SM1_FOUR + 16384 + mat * 16384, 8192, 9 + mat, 1, pass,
                     SM1_B, m0w, n0p, tid, l, acc);
#pragma unroll
            for (int mt = 0; mt < 2; mt++)
#pragma unroll
            for (int nt = 0; nt < 4; nt++) {
                float* a = acc + (mt * 4 + nt) * 4;
                int c0 = pass * 128 + n0p + nt * 8 + (l & 3) * 2;
                int rA = m0w + mt * 16 + (l >> 2);
                float b0 = bw[c0], b1 = bw[c0 + 1];
#pragma unroll
                for (int half = 0; half < 2; half++) {
                    int r = rA + half * 8;
                    float2 v;
                    v.x = fmaxf(a[half * 2 + 0] + b0, 0.f);
                    v.y = fmaxf(a[half * 2 + 1] + b1, 0.f);
                    *(float2*)&gh[(size_t)(base + r) * 256 + c0] = v;
                }
            }
        }
    }
}

// ============================================================================
// K2: kv = tokens @ tokvW -> split-bf16 swizzled k / v^T images (unchanged).
// ============================================================================
__global__ void k2_kv(const float* __restrict__ tokens,
                      const float* __restrict__ tokvW)
{
    __shared__ float tok[16][256];
    const int tile = blockIdx.x;
    const int b    = blockIdx.y;
    const int tid  = threadIdx.x;

    const float* tb = tokens + (b * MTOK + tile * 16) * 256;
    for (int i = tid; i < 16 * 256; i += 256) tok[i >> 8][i & 255] = tb[i];
    __syncthreads();

    const int j = tid;
    float acc[16];
#pragma unroll
    for (int r = 0; r < 16; r++) acc[r] = 0.f;
    for (int k = 0; k < 256; k++) {
        float w = tokvW[k * 256 + j];
#pragma unroll
        for (int r = 0; r < 16; r++) acc[r] = fmaf(tok[r][k], w, acc[r]);
    }
#pragma unroll
    for (int r = 0; r < 16; r++) {
        int m = tile * 16 + r;
        float v = acc[r];
        __nv_bfloat16 hb, lb;
        split1(v, hb, lb);
        if (j < 128) {
            int h = j >> 6, d = j & 63;
            uint8_t* img = g_kb + (size_t)(b * 2 + h) * 65536;
            int sw = swz(m * 128 + d * 2);
            *(__nv_bfloat16*)(img + sw)         = hb;
            *(__nv_bfloat16*)(img + 32768 + sw) = lb;
        } else {
            int h = (j - 128) >> 6, d = (j - 128) & 63;
            uint8_t* img = g_vb + (size_t)(b * 2 + h) * 65536;
            int off = (m >> 6) * 8192 + swz(d * 128 + (m & 63) * 2);
            *(__nv_bfloat16*)(img + off)         = hb;
            *(__nv_bfloat16*)(img + 32768 + off) = lb;
        }
    }
}

// ============================================================================
// K3 flash-mma attention (unchanged from R13).
// ============================================================================
__global__ void __launch_bounds__(256) k3_fa()
{
    extern __shared__ uint8_t smem[];
    const uint32_t sb = smem_to_u32(smem);
    const int tid = threadIdx.x;
    const int w   = tid >> 5;
    const int l   = tid & 31;
    const int bx  = blockIdx.x;
    const int h   = blockIdx.y;
    const int b   = blockIdx.z;

    {
        const uint8_t* qsrc = g_qb + (size_t)(h * 128 + bx) * 32768;
        const uint8_t* ksrc = g_kb + (size_t)(b * 2 + h) * 65536;
        const uint8_t* vsrc = g_vb + (size_t)(b * 2 + h) * 65536;
        for (int i = tid; i < 2048; i += 256) cpa16(smem + i * 16, qsrc + i * 16);
        for (int i = tid; i < 4096; i += 256) cpa16(smem + 32768 + i * 16, ksrc + i * 16);
        for (int i = tid; i < 4096; i += 256) cpa16(smem + 98304 + i * 16, vsrc + i * 16);
        CPA_COMMIT();
        CPA_WAIT0();
        __syncthreads();
    }
    const uint32_t sQh = sb,          sQl = sb + 16384;
    const uint32_t sKh = sb + 32768,  sKl = sb + 65536;
    const uint32_t sVh = sb + 98304,  sVl = sb + 131072;

    const int r0 = bx * 128 + w * 16 + (l >> 2);
    const float tt0 = g_t[r0];
    const float tt1 = g_t[r0 + 8];

    float O[32];
#pragma unroll
    for (int i = 0; i < 32; i++) O[i] = 0.f;
    float Mx0 = -1e30f, Mx1 = -1e30f, S0 = 0.f, S1 = 0.f;

    const int aQrow = (w * 16 + (l & 15)) * 128 + (l >> 4) * 16;

#pragma unroll 1
    for (int t = 0; t < 4; t++) {
        float Sa[32];
#pragma unroll
        for (int i = 0; i < 32; i++) Sa[i] = 0.f;

#pragma unroll
        for (int kk = 0; kk < 4; kk++) {
            int asw = swz(aQrow + kk * 32);
            uint32_t ahi[4], alo[4];
            ldsm4(ahi, sQh + asw);
            ldsm4(alo, sQl + asw);
#pragma unroll
            for (int nt = 0; nt < 8; nt++) {
                int bsw = swz((t * 64 + nt * 8 + (l & 7)) * 128 + kk * 32 + ((l >> 3) & 1) * 16);
                uint32_t bhi[2], blo[2];
                ldsm2(bhi, sKh + bsw);
                ldsm2(blo, sKl + bsw);
                mma16816(&Sa[nt * 4], ahi, bhi);
                mma16816(&Sa[nt * 4], ahi, blo);
                mma16816(&Sa[nt * 4], alo, bhi);
            }
        }

        float tm0 = -1e30f, tm1 = -1e30f;
#pragma unroll
        for (int nt = 0; nt < 8; nt++) {
            float* a = &Sa[nt * 4];
            float c0 = (float)(t * 64 + nt * 8 + (l & 3) * 2);
            float p0 = (c0 + 0.5f) * (1.0f / 256.0f);
            float p1 = (c0 + 1.5f) * (1.0f / 256.0f);
            float d00 = tt0 - p0, d01 = tt0 - p1;
            float d10 = tt1 - p0, d11 = tt1 - p1;
            a[0] -= 10.f * d00 * d00;
            a[1] -= 10.f * d01 * d01;
            a[2] -= 10.f * d10 * d10;
            a[3] -= 10.f * d11 * d11;
            tm0 = fmaxf(tm0, fmaxf(a[0], a[1]));
            tm1 = fmaxf(tm1, fmaxf(a[2], a[3]));
        }
        tm0 = fmaxf(tm0, __shfl_xor_sync(0xffffffffu, tm0, 1));
        tm0 = fmaxf(tm0, __shfl_xor_sync(0xffffffffu, tm0, 2));
        tm1 = fmaxf(tm1, __shfl_xor_sync(0xffffffffu, tm1, 1));
        tm1 = fmaxf(tm1, __shfl_xor_sync(0xffffffffu, tm1, 2));
        float nM0 = fmaxf(Mx0, tm0), nM1 = fmaxf(Mx1, tm1);
        float cr0 = __expf(Mx0 - nM0), cr1 = __expf(Mx1 - nM1);
        Mx0 = nM0; Mx1 = nM1;
        S0 *= cr0; S1 *= cr1;
#pragma unroll
        for (int nt = 0; nt < 8; nt++) {
            O[nt * 4 + 0] *= cr0; O[nt * 4 + 1] *= cr0;
            O[nt * 4 + 2] *= cr1; O[nt * 4 + 3] *= cr1;
        }
#pragma unroll
        for (int nt = 0; nt < 8; nt++) {
            float* a = &Sa[nt * 4];
            a[0] = __expf(a[0] - Mx0);
            a[1] = __expf(a[1] - Mx0);
            a[2] = __expf(a[2] - Mx1);
            a[3] = __expf(a[3] - Mx1);
            S0 += a[0] + a[1];
            S1 += a[2] + a[3];
        }

#pragma unroll
        for (int kk = 0; kk < 4; kk++) {
            uint32_t phi[4], plo[4];
            float* pA = &Sa[(2 * kk) * 4];
            float* pB = &Sa[(2 * kk + 1) * 4];
            split2(pA[0], pA[1], phi[0], plo[0]);
            split2(pA[2], pA[3], phi[1], plo[1]);
            split2(pB[0], pB[1], phi[2], plo[2]);
            split2(pB[2], pB[3], phi[3], plo[3]);
#pragma unroll
            for (int nt = 0; nt < 8; nt++) {
                int vsw = t * 8192 + swz((nt * 8 + (l & 7)) * 128 + kk * 32 + ((l >> 3) & 1) * 16);
                uint32_t vhi[2], vlo[2];
                ldsm2(vhi, sVh + vsw);
                ldsm2(vlo, sVl + vsw);
                mma16816(&O[nt * 4], phi, vhi);
                mma16816(&O[nt * 4], phi, vlo);
                mma16816(&O[nt * 4], plo, vhi);
            }
        }
    }

    S0 += __shfl_xor_sync(0xffffffffu, S0, 1);
    S0 += __shfl_xor_sync(0xffffffffu, S0, 2);
    S1 += __shfl_xor_sync(0xffffffffu, S1, 1);
    S1 += __shfl_xor_sync(0xffffffffu, S1, 2);
    float inv0 = 1.0f / S0, inv1 = 1.0f / S1;
#pragma unroll
    for (int nt = 0; nt < 8; nt++) {
        int col = h * 64 + nt * 8 + (l & 3) * 2;
        float2 o0, o1;
        o0.x = O[nt * 4 + 0] * inv0; o0.y = O[nt * 4 + 1] * inv0;
        o1.x = O[nt * 4 + 2] * inv1; o1.y = O[nt * 4 + 3] * inv1;
        *(float2*)&g_o[((size_t)b * HW + r0) * 128 + col]       = o0;
        *(float2*)&g_o[((size_t)b * HW + r0 + 8) * 128 + col]   = o1;
    }
}

// ============================================================================
// K5 (folded, unchanged from R13 except run_gemm bufOff param).
// ============================================================================
#define SMB_O     0
#define SMB_X     32768
#define SMB_B     98304
#define SMB_CONST 163840
#define SMB_PSM   173056
#define SMB_TOTAL 173824

__global__ void __launch_bounds__(256, 1) k5_mma(
    const float* __restrict__ hvb0,
    const float* __restrict__ outW0, const float* __restrict__ outb0,
    const float* __restrict__ outW1, const float* __restrict__ outb1,
    float* __restrict__ out)
{
    extern __shared__ char smemc[];
    char* smem = smemc;
    const uint32_t sb = smem_to_u32(smem);
    const int tid  = threadIdx.x;
    const int w    = tid >> 5;
    const int l    = tid & 31;
    const int m0w  = 32 * (w & 1);
    const int n0p  = 32 * (w >> 1);
    const int base = blockIdx.x * 64;
    const int hb   = base & (HW - 1);

    float* sC   = (float*)(smem + SMB_CONST);
    float* sB0  = sC;
    float* sB1  = sC + 256;
    float* sHvb = sC + 512;
    float* sOW0 = sC + 768;
    float* sOW1 = sC + 1536;
    float* pSM  = (float*)(smem + SMB_PSM);

    for (int i = tid; i < 256; i += 256) {
        sB0[i]  = g_b0p[i];
        sB1[i]  = g_b1p[i];
        sHvb[i] = hvb0[i];
    }
    for (int i = tid; i < 768; i += 256) {
        sOW0[i] = outW0[i];
        sOW1[i] = outW1[i];
    }
    for (int i = tid; i < 192; i += 256) pSM[i] = 0.f;

    for (int i = tid; i < 64 * 64; i += 256) {
        int r  = i >> 6;
        int kp = i & 63;
        int k  = kp * 2;
        float2 v = *(const float2*)&g_o[((size_t)(base + r)) * 128 + k];
        uint32_t hi, lo;
        split2(v.x, v.y, hi, lo);
        int kc = k >> 6;
        int sw = swz(r * 128 + (k & 63) * 2);
        *(uint32_t*)(smem + SMB_O + kc * 8192 + sw)         = hi;
        *(uint32_t*)(smem + SMB_O + 16384 + kc * 8192 + sw) = lo;
    }
    __syncthreads();

    float acc[32];
    float p[12];
#pragma unroll
    for (int i = 0; i < 12; i++) p[i] = 0.f;

    // ===== stage A =====
#pragma unroll 1
    for (int pass = 0; pass < 2; pass++) {
#pragma unroll
        for (int i = 0; i < 32; i++) acc[i] = 0.f;
        run_gemm(smem, sb, SMB_O, 16384, 0, 2, pass, SMB_B, m0w, n0p, tid, l, acc);
#pragma unroll
        for (int mt = 0; mt < 2; mt++)
#pragma unroll
        for (int nt = 0; nt < 4; nt++) {
            float* a = acc + (mt * 4 + nt) * 4;
            int c0 = pass * 128 + n0p + nt * 8 + (l & 3) * 2;
            int rA = m0w + mt * 16 + (l >> 2);
            float b0 = sB0[c0], b1 = sB0[c0 + 1];
            int kc = c0 >> 6;
            int bby = (c0 & 63) * 2;
#pragma unroll
            for (int half = 0; half < 2; half++) {
                int r = rA + half * 8;
                float2 h0 = *(const float2*)&g_h0[((size_t)(hb + r)) * 256 + c0];
                float v0 = fmaxf(h0.x + a[half * 2 + 0] + b0, 0.f);
                float v1 = fmaxf(h0.y + a[half * 2 + 1] + b1, 0.f);
                int slot = mt * 2 + half;
                p[slot * 3 + 0] = fmaf(v0, sOW0[c0 * 3 + 0], fmaf(v1, sOW0[c0 * 3 + 3], p[slot * 3 + 0]));
                p[slot * 3 + 1] = fmaf(v0, sOW0[c0 * 3 + 1], fmaf(v1, sOW0[c0 * 3 + 4], p[slot * 3 + 1]));
                p[slot * 3 + 2] = fmaf(v0, sOW0[c0 * 3 + 2], fmaf(v1, sOW0[c0 * 3 + 5], p[slot * 3 + 2]));
                uint32_t hi, lo;
                split2(v0, v1, hi, lo);
                int sw = swz(r * 128 + bby);
                *(uint32_t*)(smem + SMB_X + kc * 8192 + sw)         = hi;
                *(uint32_t*)(smem + SMB_X + 32768 + kc * 8192 + sw) = lo;
            }
        }
    }
    __syncthreads();

    // ===== stage B =====
#pragma unroll 1
    for (int pass = 0; pass < 2; pass++) {
#pragma unroll
        for (int i = 0; i < 32; i++) acc[i] = 0.f;
        run_gemm(smem, sb, SMB_O, 16384, 2, 2, pass, SMB_B, m0w, n0p, tid, l, acc);
#pragma unroll
        for (int mt = 0; mt < 2; mt++)
#pragma unroll
        for (int nt = 0; nt < 4; nt++) {
            float* a = acc + (mt * 4 + nt) * 4;
            int c0 = pass * 128 + n0p + nt * 8 + (l & 3) * 2;
            int rA = m0w + mt * 16 + (l >> 2);
            float b0 = sB1[c0], b1 = sB1[c0 + 1];
            int kc = c0 >> 6;
            int bby = (c0 & 63) * 2;
#pragma unroll
            for (int half = 0; half < 2; half++) {
                int r = rA + half * 8;
                float2 h1 = *(const float2*)&g_h1[((size_t)(hb + r)) * 256 + c0];
                float m10 = fmaxf(h1.x + a[half * 2 + 0] + b0, 0.f);
                float m11 = fmaxf(h1.y + a[half * 2 + 1] + b1, 0.f);
                int sw = swz(r * 128 + bby);
                uint32_t mh = *(uint32_t*)(smem + SMB_X + kc * 8192 + sw);
                uint32_t ml = *(uint32_t*)(smem + SMB_X + 32768 + kc * 8192 + sw);
                float x0 = bfu((unsigned short)(mh & 0xffff)) + bfu((unsigned short)(ml & 0xffff)) + m10;
                float x1 = bfu((unsigned short)(mh >> 16))    + bfu((unsigned short)(ml >> 16))    + m11;
                uint32_t hi, lo;
                split2(x0, x1, hi, lo);
                *(uint32_t*)(smem + SMB_X + kc * 8192 + sw)         = hi;
                *(uint32_t*)(smem + SMB_X + 32768 + kc * 8192 + sw) = lo;
            }
        }
    }
    __syncthreads();

    // ===== stage C =====
#pragma unroll 1
    for (int pass = 0; pass < 2; pass++) {
#pragma unroll
        for (int i = 0; i < 32; i++) acc[i] = 0.f;
        run_gemm(smem, sb, SMB_X, 32768, 4, 4, pass, SMB_B, m0w, n0p, tid, l, acc);
#pragma unroll
        for (int mt = 0; mt < 2; mt++)
#pragma unroll
        for (int nt = 0; nt < 4; nt++) {
            float* a = acc + (mt * 4 + nt) * 4;
            int c0 = pass * 128 + n0p + nt * 8 + (l & 3) * 2;
            float b0 = sHvb[c0], b1 = sHvb[c0 + 1];
#pragma unroll
            for (int half = 0; half < 2; half++) {
                float v0 = fmaxf(a[half * 2 + 0] + b0, 0.f);
                float v1 = fmaxf(a[half * 2 + 1] + b1, 0.f);
                int slot = mt * 2 + half;
                p[slot * 3 + 0] = fmaf(v0, sOW1[c0 * 3 + 0], fmaf(v1, sOW1[c0 * 3 + 3], p[slot * 3 + 0]));
                p[slot * 3 + 1] = fmaf(v0, sOW1[c0 * 3 + 1], fmaf(v1, sOW1[c0 * 3 + 4], p[slot * 3 + 1]));
                p[slot * 3 + 2] = fmaf(v0, sOW1[c0 * 3 + 2], fmaf(v1, sOW1[c0 * 3 + 5], p[slot * 3 + 2]));
            }
        }
    }

#pragma unroll
    for (int slot = 0; slot < 4; slot++) {
        int r = m0w + (slot >> 1) * 16 + (l >> 2) + (slot & 1) * 8;
#pragma unroll
        for (int j = 0; j < 3; j++) {
            float v = p[slot * 3 + j];
            v += __shfl_xor_sync(0xffffffffu, v, 1);
            v += __shfl_xor_sync(0xffffffffu, v, 2);
            if ((l & 3) == 0) atomicAdd(&pSM[r * 3 + j], v);
        }
    }
    __syncthreads();

    for (int i = tid; i < 192; i += 256) {
        int r = i / 3, j = i - r * 3;
        out[((size_t)(base + r)) * 3 + j] = pSM[i] + outb0[j] + outb1[j];
    }
}

// ============================================================================
extern "C" void kernel_launch(void* const* d_in, const int* in_sizes, int n_in,
                              void* d_out, int out_size)
{
    const float* coords = (const float*)d_in[0];
    const float* tokens = (const float*)d_in[1];
    const float* B_q    = (const float*)d_in[2];
    const float* B_l0   = (const float*)d_in[3];
    const float* B_l1   = (const float*)d_in[4];
    const float* qW     = (const float*)d_in[5];
    const float* qb     = (const float*)d_in[6];
    const float* toqW   = (const float*)d_in[7];
    const float* tokvW  = (const float*)d_in[8];
    const float* tooW   = (const float*)d_in[9];
    const float* toob   = (const float*)d_in[10];
    const float* bwW0   = (const float*)d_in[11];
    const float* bwb0   = (const float*)d_in[12];
    const float* bwW1   = (const float*)d_in[13];
    const float* bwb1   = (const float*)d_in[14];
    const float* modW0  = (const float*)d_in[15];
    const float* modb0  = (const float*)d_in[16];
    const float* modW1  = (const float*)d_in[17];
    const float* modb1  = (const float*)d_in[18];
    const float* hvW0   = (const float*)d_in[19];
    const float* hvb0   = (const float*)d_in[20];
    const float* outW0  = (const float*)d_in[21];
    const float* outb0  = (const float*)d_in[22];
    const float* outW1  = (const float*)d_in[23];
    const float* outb1  = (const float*)d_in[24];
    float* out = (float*)d_out;

    cudaFuncSetAttribute(k1_mma, cudaFuncAttributeMaxDynamicSharedMemorySize, SM1_TOTAL);
    cudaFuncSetAttribute(k3_fa,  cudaFuncAttributeMaxDynamicSharedMemorySize, 163840);
    cudaFuncSetAttribute(k5_mma, cudaFuncAttributeMaxDynamicSharedMemorySize, SMB_TOTAL);

    k0_prepw<<<dim3(256, 7), 256>>>(tooW, modW0, modW1, hvW0, toob, modb0, modb1,
                                    qW, bwW0, bwW1, toqW);
    k1_mma<<<HW / 64, 256, SM1_TOTAL>>>(coords, B_q, B_l0, B_l1, qb, bwb0, bwb1);
    k2_kv<<<dim3(MTOK / 16, BATCH), 256>>>(tokens, tokvW);
    k3_fa<<<dim3(HW / 128, 2, BATCH), 256, 163840>>>();
    k5_mma<<<(BATCH * HW) / 64, 256, SMB_TOTAL>>>(hvb0, outW0, outb0, outW1, outb1,
                                                  out);
}

// round 15
// speedup vs baseline: 2.4705x; 1.0022x over previous
#include <cuda_runtime.h>
#include <cuda_bf16.h>
#include <math.h>
#include <cstdint>

#define HW      16384
#define BATCH   4
#define MTOK    256
#define HD      256
#define INNER   128
#define DH      64

#define TWO_PI 6.2831853071795864769f

typedef unsigned long long u64;

// ---- cp.async helpers ------------------------------------------------------
__device__ __forceinline__ void cpa16(void* dst, const void* src) {
    unsigned d = (unsigned)__cvta_generic_to_shared(dst);
    asm volatile("cp.async.ca.shared.global [%0], [%1], 16;" :: "r"(d), "l"(src));
}
#define CPA_COMMIT() asm volatile("cp.async.commit_group;" ::: "memory")
#define CPA_WAIT0()  asm volatile("cp.async.wait_group 0;"  ::: "memory")
#define CPA_WAIT1()  asm volatile("cp.async.wait_group 1;"  ::: "memory")

// ---- mma.sync / ldmatrix helpers (baseline PTX, sm_80+) --------------------
__device__ __forceinline__ uint32_t smem_to_u32(const void* p) {
    uint32_t a;
    asm("{ .reg .u64 t; cvta.to.shared.u64 t, %1; cvt.u32.u64 %0, t; }" : "=r"(a) : "l"(p));
    return a;
}
__device__ __forceinline__ void ldsm4(uint32_t* r, uint32_t addr) {
    asm volatile("ldmatrix.sync.aligned.m8n8.x4.shared.b16 {%0,%1,%2,%3}, [%4];"
        : "=r"(r[0]), "=r"(r[1]), "=r"(r[2]), "=r"(r[3]) : "r"(addr));
}
__device__ __forceinline__ void ldsm2(uint32_t* r, uint32_t addr) {
    asm volatile("ldmatrix.sync.aligned.m8n8.x2.shared.b16 {%0,%1}, [%2];"
        : "=r"(r[0]), "=r"(r[1]) : "r"(addr));
}
__device__ __forceinline__ void mma16816(float* d, const uint32_t* a, const uint32_t* b) {
    asm volatile("mma.sync.aligned.m16n8k16.row.col.f32.bf16.bf16.f32 "
        "{%0,%1,%2,%3}, {%4,%5,%6,%7}, {%8,%9}, {%0,%1,%2,%3};"
        : "+f"(d[0]), "+f"(d[1]), "+f"(d[2]), "+f"(d[3])
        : "r"(a[0]), "r"(a[1]), "r"(a[2]), "r"(a[3]), "r"(b[0]), "r"(b[1]));
}

__device__ __forceinline__ int swz(int b) { return b ^ ((b >> 3) & 0x70); }

__device__ __forceinline__ void split2(float v0, float v1, uint32_t& hi, uint32_t& lo) {
    __nv_bfloat16 h0 = __float2bfloat16(v0), h1 = __float2bfloat16(v1);
    float r0 = v0 - __bfloat162float(h0);
    float r1 = v1 - __bfloat162float(h1);
    __nv_bfloat16 l0 = __float2bfloat16(r0), l1 = __float2bfloat16(r1);
    hi = ((uint32_t)__bfloat16_as_ushort(h1) << 16) | __bfloat16_as_ushort(h0);
    lo = ((uint32_t)__bfloat16_as_ushort(l1) << 16) | __bfloat16_as_ushort(l0);
}
__device__ __forceinline__ void split1(float v, __nv_bfloat16& h, __nv_bfloat16& l) {
    h = __float2bfloat16(v);
    l = __float2bfloat16(v - __bfloat162float(h));
}
__device__ __forceinline__ float bfu(unsigned short u) {
    __nv_bfloat16_raw r; r.x = u;
    return __bfloat162float(__nv_bfloat16(r));
}

// ---------------- scratch ---------------------------------------------------
__device__ float g_h0 [HW * HD];
__device__ float g_h1 [HW * HD];
__device__ float g_t  [HW];
__device__ float g_o  [BATCH * HW * INNER];
// weight images, 32KB packages (hi 16K + lo 16K), index (chunk*2 + nhalf):
//  [0,1]=W0'(tooW@modW0)  [2,3]=W1'  [4..7]=hvW0
//  [8]=qW(K=64)  [9]=bwW0  [10]=bwW1  [11..14]=toqW(256x128, nhalf 0 only)
__device__ __align__(128) uint8_t g_WB[15 * 2 * 32768];
__device__ float g_b0p[256];
__device__ float g_b1p[256];
// attention images
__device__ __align__(128) uint8_t g_qb[2 * 128 * 32768];
__device__ __align__(128) uint8_t g_kb[8 * 65536];
__device__ __align__(128) uint8_t g_vb[8 * 65536];

// ============================================================================
// K0: fold tooW@modW{0,1}; prep all split-bf16 swizzled weight images.
// ============================================================================
__global__ void k0_prepw(const float* __restrict__ tooW,
                         const float* __restrict__ modW0,
                         const float* __restrict__ modW1,
                         const float* __restrict__ hvW0,
                         const float* __restrict__ toob,
                         const float* __restrict__ modb0,
                         const float* __restrict__ modb1,
                         const float* __restrict__ qW,
                         const float* __restrict__ bwW0,
                         const float* __restrict__ bwW1,
                         const float* __restrict__ toqW)
{
    int m = blockIdx.y;           // 0..6
    int k = blockIdx.x;
    int n = threadIdx.x;
    float v;
    int chunk, nh, nrow;
    if (m < 2) {
        if (k >= 128) return;
        const float* modW = (m == 0) ? modW0 : modW1;
        float s = 0.f;
        for (int j = 0; j < 256; j++)
            s = fmaf(tooW[k * 256 + j], modW[j * 256 + n], s);
        v = s;
        chunk = m * 2 + (k >> 6);
        nh = n >> 7; nrow = n & 127;
        if (k == 0) {
            float bb = 0.f;
            for (int j = 0; j < 256; j++)
                bb = fmaf(toob[j], modW[j * 256 + n], bb);
            if (m == 0) g_b0p[n] = bb + modb0[n];
            else        g_b1p[n] = bb + modb1[n];
        }
    } else if (m == 2) {
        v = hvW0[k * 256 + n];
        chunk = 4 + (k >> 6); nh = n >> 7; nrow = n & 127;
    } else if (m == 3) {
        if (k >= 64) return;
        v = qW[k * 256 + n];
        chunk = 8; nh = n >> 7; nrow = n & 127;
    } else if (m == 4) {
        if (k >= 64) return;
        v = bwW0[k * 256 + n];
        chunk = 9; nh = n >> 7; nrow = n & 127;
    } else if (m == 5) {
        if (k >= 64) return;
        v = bwW1[k * 256 + n];
        chunk = 10; nh = n >> 7; nrow = n & 127;
    } else {
        if (n >= 128) return;
        v = toqW[k * 128 + n];
        chunk = 11 + (k >> 6); nh = 0; nrow = n;
    }
    __nv_bfloat16 h, l;
    split1(v, h, l);
    uint8_t* img = g_WB + ((size_t)chunk * 2 + nh) * 32768;
    int sw = swz(nrow * 128 + (k & 63) * 2);
    *(__nv_bfloat16*)(img + sw)         = h;
    *(__nv_bfloat16*)(img + 16384 + sw) = l;
}

// ============================================================================
// shared GEMM step: stream B chunk packages from g_WB, mma split-bf16.
// ============================================================================
__device__ __forceinline__ void run_gemm(char* smem, uint32_t sb, int Aoff, int loA,
                                         int mstart, int nch, int pass,
                                         int bufOff,
                                         int m0w, int n0p, int tid, int l,
                                         float* acc)
{
    {
        const uint8_t* src = g_WB + ((size_t)mstart * 2 + pass) * 32768;
        char* dst = smem + bufOff;
#pragma unroll
        for (int it = 0; it < 8; it++) {
            int i = (it * 256 + tid) * 16;
            cpa16(dst + i, src + i);
        }
        CPA_COMMIT();
    }
    for (int c = 0; c < nch; c++) {
        if (c + 1 < nch) {
            const uint8_t* src = g_WB + ((size_t)(mstart + c + 1) * 2 + pass) * 32768;
            char* dst = smem + bufOff + ((c + 1) & 1) * 32768;
#pragma unroll
            for (int it = 0; it < 8; it++) {
                int i = (it * 256 + tid) * 16;
                cpa16(dst + i, src + i);
            }
            CPA_COMMIT();
            CPA_WAIT1();
        } else {
            CPA_WAIT0();
        }
        __syncthreads();

        const uint32_t bB   = sb + bufOff + (c & 1) * 32768;
        const uint32_t bAhi = sb + Aoff + c * 8192;
        const uint32_t bAlo = bAhi + loA;

#pragma unroll
        for (int t4 = 0; t4 < 4; t4++) {
            uint32_t ahi[2][4], alo[2][4];
            const int arow = l & 15;
            const int akb  = t4 * 32 + (l >> 4) * 16;
#pragma unroll
            for (int mt = 0; mt < 2; mt++) {
                int ab = (m0w + mt * 16 + arow) * 128 + akb;
                int sw = swz(ab);
                ldsm4(ahi[mt], bAhi + sw);
                ldsm4(alo[mt], bAlo + sw);
            }
#pragma unroll
            for (int nt = 0; nt < 4; nt++) {
                const int nrow = n0p + nt * 8 + (l & 7);
                int bb = nrow * 128 + t4 * 32 + ((l >> 3) & 1) * 16;
                int sw = swz(bb);
                uint32_t bhi[2], blo[2];
                ldsm2(bhi, bB + sw);
                ldsm2(blo, bB + 16384 + sw);
                float* a0 = acc + (0 * 4 + nt) * 4;
                float* a1 = acc + (1 * 4 + nt) * 4;
                mma16816(a0, ahi[0], bhi);
                mma16816(a1, ahi[1], bhi);
                mma16816(a0, ahi[0], blo);
                mma16816(a1, ahi[1], blo);
                mma16816(a0, alo[0], bhi);
                mma16816(a1, alo[1], bhi);
            }
        }
        __syncthreads();
    }
}

// ============================================================================
// K1 mma: grid features on tensor cores (unchanged from R14).
// ============================================================================
#define SM1_FOUR  0
#define SM1_XQ    49152
#define SM1_B     114688
#define SM1_TOTAL 180224

__global__ void __launch_bounds__(256) k1_mma(
    const float* __restrict__ coords,
    const float* __restrict__ Bq,
    const float* __restrict__ Bl0,
    const float* __restrict__ Bl1,
    const float* __restrict__ qb,
    const float* __restrict__ bwb0,
    const float* __restrict__ bwb1)
{
    extern __shared__ uint8_t smemu[];
    char* smem = (char*)smemu;
    const uint32_t sb = smem_to_u32(smem);
    const int tid  = threadIdx.x;
    const int w    = tid >> 5;
    const int l    = tid & 31;
    const int m0w  = 32 * (w & 1);
    const int n0p  = 32 * (w >> 1);
    const int base = blockIdx.x * 64;

    for (int it = tid; it < 3 * 64 * 32; it += 256) {
        int mat = it >> 11;
        int rem = it & 2047;
        int r   = rem >> 5;
        int f   = rem & 31;
        float x = coords[(base + r) * 2 + 0];
        float y = coords[(base + r) * 2 + 1];
        const float* Bm = (mat == 0) ? Bq : (mat == 1 ? Bl0 : Bl1);
        float proj = TWO_PI * (x * Bm[f * 2] + y * Bm[f * 2 + 1]);
        float s, c;
        sincosf(proj, &s, &c);
        uint8_t* img = (uint8_t*)smem + SM1_FOUR + mat * 16384;
        __nv_bfloat16 hb, lb;
        split1(c, hb, lb);
        int sw = swz(r * 128 + f * 2);
        *(__nv_bfloat16*)(img + sw)        = hb;
        *(__nv_bfloat16*)(img + 8192 + sw) = lb;
        split1(s, hb, lb);
        sw = swz(r * 128 + (f + 32) * 2);
        *(__nv_bfloat16*)(img + sw)        = hb;
        *(__nv_bfloat16*)(img + 8192 + sw) = lb;
    }
    if (tid < 64) {
        float x = coords[(base + tid) * 2 + 0];
        float y = coords[(base + tid) * 2 + 1];
        int row = (int)(x * 16.0f); row = min(max(row, 0), 15);
        int col = (int)(y * 16.0f); col = min(max(col, 0), 15);
        g_t[base + tid] = (float)(row * 16 + col) * (1.0f / 256.0f);
    }
    __syncthreads();

    float acc[32];

#pragma unroll 1
    for (int pass = 0; pass < 2; pass++) {
#pragma unroll
        for (int i = 0; i < 32; i++) acc[i] = 0.f;
        run_gemm(smem, sb, SM1_FOUR, 8192, 8, 1, pass, SM1_B, m0w, n0p, tid, l, acc);
#pragma unroll
        for (int mt = 0; mt < 2; mt++)
#pragma unroll
        for (int nt = 0; nt < 4; nt++) {
            float* a = acc + (mt * 4 + nt) * 4;
            int c0 = pass * 128 + n0p + nt * 8 + (l & 3) * 2;
            int rA = m0w + mt * 16 + (l >> 2);
            float b0 = qb[c0], b1 = qb[c0 + 1];
            int kc = c0 >> 6;
            int bby = (c0 & 63) * 2;
#pragma unroll
            for (int half = 0; half < 2; half++) {
                int r = rA + half * 8;
                float v0 = fmaxf(a[half * 2 + 0] + b0, 0.f);
                float v1 = fmaxf(a[half * 2 + 1] + b1, 0.f);
                uint32_t hi, lo;
                split2(v0, v1, hi, lo);
                int sw = swz(r * 128 + bby);
                *(uint32_t*)(smem + SM1_XQ + kc * 8192 + sw)         = hi;
                *(uint32_t*)(smem + SM1_XQ + 32768 + kc * 8192 + sw) = lo;
            }
        }
    }
    __syncthreads();

    {
#pragma unroll
        for (int i = 0; i < 32; i++) acc[i] = 0.f;
        run_gemm(smem, sb, SM1_XQ, 32768, 11, 4, 0, SM1_B, m0w, n0p, tid, l, acc);
        const int tile = base >> 7;
        const int rb   = base & 127;
#pragma unroll
        for (int mt = 0; mt < 2; mt++)
#pragma unroll
        for (int nt = 0; nt < 4; nt++) {
            float* a = acc + (mt * 4 + nt) * 4;
            int c0 = n0p + nt * 8 + (l & 3) * 2;
            int h = c0 >> 6, d = c0 & 63;
            uint8_t* img = g_qb + (size_t)(h * 128 + tile) * 32768;
            int rA = m0w + mt * 16 + (l >> 2);
#pragma unroll
            for (int half = 0; half < 2; half++) {
                int rr = rb + rA + half * 8;
                float v0 = a[half * 2 + 0] * 0.125f;
                float v1 = a[half * 2 + 1] * 0.125f;
                uint32_t hi, lo;
                split2(v0, v1, hi, lo);
                int sw = swz(rr * 128 + d * 2);
                *(uint32_t*)(img + sw)         = hi;
                *(uint32_t*)(img + 16384 + sw) = lo;
            }
        }
    }

#pragma unroll 1
    for (int mat = 0; mat < 2; mat++) {
        const float* bw = mat ? bwb1 : bwb0;
        float* gh = mat ? g_h1 : g_h0;
#pragma unroll 1
        for (int pass = 0; pass < 2; pass++) {
#pragma unroll
            for (int i = 0; i < 32; i++) acc[i] = 0.f;
            run_gemm(smem, sb, SM1_FOUR + 16384 + mat * 16384, 8192, 9 + mat, 1, pass,
                     SM1_B, m0w, n0p, tid, l, acc);
#pragma unroll
            for (int mt = 0; mt < 2; mt++)
#pragma unroll
            for (int nt = 0; nt < 4; nt++) {
                float* a = acc + (mt * 4 + nt) * 4;
                int c0 = pass * 128 + n0p + nt * 8 + (l & 3) * 2;
                int rA = m0w + mt * 16 + (l >> 2);
                float b0 = bw[c0], b1 = bw[c0 + 1];
#pragma unroll
                for (int half = 0; half < 2; half++) {
                    int r = rA + half * 8;
                    float2 v;
                    v.x = fmaxf(a[half * 2 + 0] + b0, 0.f);
                    v.y = fmaxf(a[half * 2 + 1] + b1, 0.f);
                    *(float2*)&gh[(size_t)(base + r) * 256 + c0] = v;
                }
            }
        }
    }
}

// ============================================================================
// K2: kv = tokens @ tokvW -> split-bf16 swizzled k / v^T images (unchanged).
// ============================================================================
__global__ void k2_kv(const float* __restrict__ tokens,
                      const float* __restrict__ tokvW)
{
    __shared__ float tok[16][256];
    const int tile = blockIdx.x;
    const int b    = blockIdx.y;
    const int tid  = threadIdx.x;

    const float* tb = tokens + (b * MTOK + tile * 16) * 256;
    for (int i = tid; i < 16 * 256; i += 256) tok[i >> 8][i & 255] = tb[i];
    __syncthreads();

    const int j = tid;
    float acc[16];
#pragma unroll
    for (int r = 0; r < 16; r++) acc[r] = 0.f;
    for (int k = 0; k < 256; k++) {
        float w = tokvW[k * 256 + j];
#pragma unroll
        for (int r = 0; r < 16; r++) acc[r] = fmaf(tok[r][k], w, acc[r]);
    }
#pragma unroll
    for (int r = 0; r < 16; r++) {
        int m = tile * 16 + r;
        float v = acc[r];
        __nv_bfloat16 hb, lb;
        split1(v, hb, lb);
        if (j < 128) {
            int h = j >> 6, d = j & 63;
            uint8_t* img = g_kb + (size_t)(b * 2 + h) * 65536;
            int sw = swz(m * 128 + d * 2);
            *(__nv_bfloat16*)(img + sw)         = hb;
            *(__nv_bfloat16*)(img + 32768 + sw) = lb;
        } else {
            int h = (j - 128) >> 6, d = (j - 128) & 63;
            uint8_t* img = g_vb + (size_t)(b * 2 + h) * 65536;
            int off = (m >> 6) * 8192 + swz(d * 128 + (m & 63) * 2);
            *(__nv_bfloat16*)(img + off)         = hb;
            *(__nv_bfloat16*)(img + 32768 + off) = lb;
        }
    }
}

// ============================================================================
// K3 flash-mma attention (unchanged from R13).
// ============================================================================
__global__ void __launch_bounds__(256) k3_fa()
{
    extern __shared__ uint8_t smem[];
    const uint32_t sb = smem_to_u32(smem);
    const int tid = threadIdx.x;
    const int w   = tid >> 5;
    const int l   = tid & 31;
    const int bx  = blockIdx.x;
    const int h   = blockIdx.y;
    const int b   = blockIdx.z;

    {
        const uint8_t* qsrc = g_qb + (size_t)(h * 128 + bx) * 32768;
        const uint8_t* ksrc = g_kb + (size_t)(b * 2 + h) * 65536;
        const uint8_t* vsrc = g_vb + (size_t)(b * 2 + h) * 65536;
        for (int i = tid; i < 2048; i += 256) cpa16(smem + i * 16, qsrc + i * 16);
        for (int i = tid; i < 4096; i += 256) cpa16(smem + 32768 + i * 16, ksrc + i * 16);
        for (int i = tid; i < 4096; i += 256) cpa16(smem + 98304 + i * 16, vsrc + i * 16);
        CPA_COMMIT();
        CPA_WAIT0();
        __syncthreads();
    }
    const uint32_t sQh = sb,          sQl = sb + 16384;
    const uint32_t sKh = sb + 32768,  sKl = sb + 65536;
    const uint32_t sVh = sb + 98304,  sVl = sb + 131072;

    const int r0 = bx * 128 + w * 16 + (l >> 2);
    const float tt0 = g_t[r0];
    const float tt1 = g_t[r0 + 8];

    float O[32];
#pragma unroll
    for (int i = 0; i < 32; i++) O[i] = 0.f;
    float Mx0 = -1e30f, Mx1 = -1e30f, S0 = 0.f, S1 = 0.f;

    const int aQrow = (w * 16 + (l & 15)) * 128 + (l >> 4) * 16;

#pragma unroll 1
    for (int t = 0; t < 4; t++) {
        float Sa[32];
#pragma unroll
        for (int i = 0; i < 32; i++) Sa[i] = 0.f;

#pragma unroll
        for (int kk = 0; kk < 4; kk++) {
            int asw = swz(aQrow + kk * 32);
            uint32_t ahi[4], alo[4];
            ldsm4(ahi, sQh + asw);
            ldsm4(alo, sQl + asw);
#pragma unroll
            for (int nt = 0; nt < 8; nt++) {
                int bsw = swz((t * 64 + nt * 8 + (l & 7)) * 128 + kk * 32 + ((l >> 3) & 1) * 16);
                uint32_t bhi[2], blo[2];
                ldsm2(bhi, sKh + bsw);
                ldsm2(blo, sKl + bsw);
                mma16816(&Sa[nt * 4], ahi, bhi);
                mma16816(&Sa[nt * 4], ahi, blo);
                mma16816(&Sa[nt * 4], alo, bhi);
            }
        }

        float tm0 = -1e30f, tm1 = -1e30f;
#pragma unroll
        for (int nt = 0; nt < 8; nt++) {
            float* a = &Sa[nt * 4];
            float c0 = (float)(t * 64 + nt * 8 + (l & 3) * 2);
            float p0 = (c0 + 0.5f) * (1.0f / 256.0f);
            float p1 = (c0 + 1.5f) * (1.0f / 256.0f);
            float d00 = tt0 - p0, d01 = tt0 - p1;
            float d10 = tt1 - p0, d11 = tt1 - p1;
            a[0] -= 10.f * d00 * d00;
            a[1] -= 10.f * d01 * d01;
            a[2] -= 10.f * d10 * d10;
            a[3] -= 10.f * d11 * d11;
            tm0 = fmaxf(tm0, fmaxf(a[0], a[1]));
            tm1 = fmaxf(tm1, fmaxf(a[2], a[3]));
        }
        tm0 = fmaxf(tm0, __shfl_xor_sync(0xffffffffu, tm0, 1));
        tm0 = fmaxf(tm0, __shfl_xor_sync(0xffffffffu, tm0, 2));
        tm1 = fmaxf(tm1, __shfl_xor_sync(0xffffffffu, tm1, 1));
        tm1 = fmaxf(tm1, __shfl_xor_sync(0xffffffffu, tm1, 2));
        float nM0 = fmaxf(Mx0, tm0), nM1 = fmaxf(Mx1, tm1);
        float cr0 = __expf(Mx0 - nM0), cr1 = __expf(Mx1 - nM1);
        Mx0 = nM0; Mx1 = nM1;
        S0 *= cr0; S1 *= cr1;
#pragma unroll
        for (int nt = 0; nt < 8; nt++) {
            O[nt * 4 + 0] *= cr0; O[nt * 4 + 1] *= cr0;
            O[nt * 4 + 2] *= cr1; O[nt * 4 + 3] *= cr1;
        }
#pragma unroll
        for (int nt = 0; nt < 8; nt++) {
            float* a = &Sa[nt * 4];
            a[0] = __expf(a[0] - Mx0);
            a[1] = __expf(a[1] - Mx0);
            a[2] = __expf(a[2] - Mx1);
            a[3] = __expf(a[3] - Mx1);
            S0 += a[0] + a[1];
            S1 += a[2] + a[3];
        }

#pragma unroll
        for (int kk = 0; kk < 4; kk++) {
            uint32_t phi[4], plo[4];
            float* pA = &Sa[(2 * kk) * 4];
            float* pB = &Sa[(2 * kk + 1) * 4];
            split2(pA[0], pA[1], phi[0], plo[0]);
            split2(pA[2], pA[3], phi[1], plo[1]);
            split2(pB[0], pB[1], phi[2], plo[2]);
            split2(pB[2], pB[3], phi[3], plo[3]);
#pragma unroll
            for (int nt = 0; nt < 8; nt++) {
                int vsw = t * 8192 + swz((nt * 8 + (l & 7)) * 128 + kk * 32 + ((l >> 3) & 1) * 16);
                uint32_t vhi[2], vlo[2];
                ldsm2(vhi, sVh + vsw);
                ldsm2(vlo, sVl + vsw);
                mma16816(&O[nt * 4], phi, vhi);
                mma16816(&O[nt * 4], phi, vlo);
                mma16816(&O[nt * 4], plo, vhi);
            }
        }
    }

    S0 += __shfl_xor_sync(0xffffffffu, S0, 1);
    S0 += __shfl_xor_sync(0xffffffffu, S0, 2);
    S1 += __shfl_xor_sync(0xffffffffu, S1, 1);
    S1 += __shfl_xor_sync(0xffffffffu, S1, 2);
    float inv0 = 1.0f / S0, inv1 = 1.0f / S1;
#pragma unroll
    for (int nt = 0; nt < 8; nt++) {
        int col = h * 64 + nt * 8 + (l & 3) * 2;
        float2 o0, o1;
        o0.x = O[nt * 4 + 0] * inv0; o0.y = O[nt * 4 + 1] * inv0;
        o1.x = O[nt * 4 + 2] * inv1; o1.y = O[nt * 4 + 3] * inv1;
        *(float2*)&g_o[((size_t)b * HW + r0) * 128 + col]       = o0;
        *(float2*)&g_o[((size_t)b * HW + r0 + 8) * 128 + col]   = o1;
    }
}

// ============================================================================
// K5 (folded): grid reordered hw-tile-major so the 4 batches sharing the same
// g_h0/g_h1 rows are adjacent in launch order -> L2 reuse (537MB -> ~134MB).
// ============================================================================
#define SMB_O     0
#define SMB_X     32768
#define SMB_B     98304
#define SMB_CONST 163840
#define SMB_PSM   173056
#define SMB_TOTAL 173824

__global__ void __launch_bounds__(256, 1) k5_mma(
    const float* __restrict__ hvb0,
    const float* __restrict__ outW0, const float* __restrict__ outb0,
    const float* __restrict__ outW1, const float* __restrict__ outb1,
    float* __restrict__ out)
{
    extern __shared__ char smemc[];
    char* smem = smemc;
    const uint32_t sb = smem_to_u32(smem);
    const int tid  = threadIdx.x;
    const int w    = tid >> 5;
    const int l    = tid & 31;
    const int m0w  = 32 * (w & 1);
    const int n0p  = 32 * (w >> 1);
    // hw-tile-major ordering: 4 consecutive CTAs share the same h0/h1 rows
    const int tile = blockIdx.x >> 2;
    const int bat  = blockIdx.x & 3;
    const int base = bat * HW + tile * 64;
    const int hb   = tile * 64;

    float* sC   = (float*)(smem + SMB_CONST);
    float* sB0  = sC;
    float* sB1  = sC + 256;
    float* sHvb = sC + 512;
    float* sOW0 = sC + 768;
    float* sOW1 = sC + 1536;
    float* pSM  = (float*)(smem + SMB_PSM);

    for (int i = tid; i < 256; i += 256) {
        sB0[i]  = g_b0p[i];
        sB1[i]  = g_b1p[i];
        sHvb[i] = hvb0[i];
    }
    for (int i = tid; i < 768; i += 256) {
        sOW0[i] = outW0[i];
        sOW1[i] = outW1[i];
    }
    for (int i = tid; i < 192; i += 256) pSM[i] = 0.f;

    for (int i = tid; i < 64 * 64; i += 256) {
        int r  = i >> 6;
        int kp = i & 63;
        int k  = kp * 2;
        float2 v = *(const float2*)&g_o[((size_t)(base + r)) * 128 + k];
        uint32_t hi, lo;
        split2(v.x, v.y, hi, lo);
        int kc = k >> 6;
        int sw = swz(r * 128 + (k & 63) * 2);
        *(uint32_t*)(smem + SMB_O + kc * 8192 + sw)         = hi;
        *(uint32_t*)(smem + SMB_O + 16384 + kc * 8192 + sw) = lo;
    }
    __syncthreads();

    float acc[32];
    float p[12];
#pragma unroll
    for (int i = 0; i < 12; i++) p[i] = 0.f;

    // ===== stage A =====
#pragma unroll 1
    for (int pass = 0; pass < 2; pass++) {
#pragma unroll
        for (int i = 0; i < 32; i++) acc[i] = 0.f;
        run_gemm(smem, sb, SMB_O, 16384, 0, 2, pass, SMB_B, m0w, n0p, tid, l, acc);
#pragma unroll
        for (int mt = 0; mt < 2; mt++)
#pragma unroll
        for (int nt = 0; nt < 4; nt++) {
            float* a = acc + (mt * 4 + nt) * 4;
            int c0 = pass * 128 + n0p + nt * 8 + (l & 3) * 2;
            int rA = m0w + mt * 16 + (l >> 2);
            float b0 = sB0[c0], b1 = sB0[c0 + 1];
            int kc = c0 >> 6;
            int bby = (c0 & 63) * 2;
#pragma unroll
            for (int half = 0; half < 2; half++) {
                int r = rA + half * 8;
                float2 h0 = *(const float2*)&g_h0[((size_t)(hb + r)) * 256 + c0];
                float v0 = fmaxf(h0.x + a[half * 2 + 0] + b0, 0.f);
                float v1 = fmaxf(h0.y + a[half * 2 + 1] + b1, 0.f);
                int slot = mt * 2 + half;
                p[slot * 3 + 0] = fmaf(v0, sOW0[c0 * 3 + 0], fmaf(v1, sOW0[c0 * 3 + 3], p[slot * 3 + 0]));
                p[slot * 3 + 1] = fmaf(v0, sOW0[c0 * 3 + 1], fmaf(v1, sOW0[c0 * 3 + 4], p[slot * 3 + 1]));
                p[slot * 3 + 2] = fmaf(v0, sOW0[c0 * 3 + 2], fmaf(v1, sOW0[c0 * 3 + 5], p[slot * 3 + 2]));
                uint32_t hi, lo;
                split2(v0, v1, hi, lo);
                int sw = swz(r * 128 + bby);
                *(uint32_t*)(smem + SMB_X + kc * 8192 + sw)         = hi;
                *(uint32_t*)(smem + SMB_X + 32768 + kc * 8192 + sw) = lo;
            }
        }
    }
    __syncthreads();

    // ===== stage B =====
#pragma unroll 1
    for (int pass = 0; pass < 2; pass++) {
#pragma unroll
        for (int i = 0; i < 32; i++) acc[i] = 0.f;
        run_gemm(smem, sb, SMB_O, 16384, 2, 2, pass, SMB_B, m0w, n0p, tid, l, acc);
#pragma unroll
        for (int mt = 0; mt < 2; mt++)
#pragma unroll
        for (int nt = 0; nt < 4; nt++) {
            float* a = acc + (mt * 4 + nt) * 4;
            int c0 = pass * 128 + n0p + nt * 8 + (l & 3) * 2;
            int rA = m0w + mt * 16 + (l >> 2);
            float b0 = sB1[c0], b1 = sB1[c0 + 1];
            int kc = c0 >> 6;
            int bby = (c0 & 63) * 2;
#pragma unroll
            for (int half = 0; half < 2; half++) {
                int r = rA + half * 8;
                float2 h1 = *(const float2*)&g_h1[((size_t)(hb + r)) * 256 + c0];
                float m10 = fmaxf(h1.x + a[half * 2 + 0] + b0, 0.f);
                float m11 = fmaxf(h1.y + a[half * 2 + 1] + b1, 0.f);
                int sw = swz(r * 128 + bby);
                uint32_t mh = *(uint32_t*)(smem + SMB_X + kc * 8192 + sw);
                uint32_t ml = *(uint32_t*)(smem + SMB_X + 32768 + kc * 8192 + sw);
                float x0 = bfu((unsigned short)(mh & 0xffff)) + bfu((unsigned short)(ml & 0xffff)) + m10;
                float x1 = bfu((unsigned short)(mh >> 16))    + bfu((unsigned short)(ml >> 16))    + m11;
                uint32_t hi, lo;
                split2(x0, x1, hi, lo);
                *(uint32_t*)(smem + SMB_X + kc * 8192 + sw)         = hi;
                *(uint32_t*)(smem + SMB_X + 32768 + kc * 8192 + sw) = lo;
            }
        }
    }
    __syncthreads();

    // ===== stage C =====
#pragma unroll 1
    for (int pass = 0; pass < 2; pass++) {
#pragma unroll
        for (int i = 0; i < 32; i++) acc[i] = 0.f;
        run_gemm(smem, sb, SMB_X, 32768, 4, 4, pass, SMB_B, m0w, n0p, tid, l, acc);
#pragma unroll
        for (int mt = 0; mt < 2; mt++)
#pragma unroll
        for (int nt = 0; nt < 4; nt++) {
            float* a = acc + (mt * 4 + nt) * 4;
            int c0 = pass * 128 + n0p + nt * 8 + (l & 3) * 2;
            float b0 = sHvb[c0], b1 = sHvb[c0 + 1];
#pragma unroll
            for (int half = 0; half < 2; half++) {
                float v0 = fmaxf(a[half * 2 + 0] + b0, 0.f);
                float v1 = fmaxf(a[half * 2 + 1] + b1, 0.f);
                int slot = mt * 2 + half;
                p[slot * 3 + 0] = fmaf(v0, sOW1[c0 * 3 + 0], fmaf(v1, sOW1[c0 * 3 + 3], p[slot * 3 + 0]));
                p[slot * 3 + 1] = fmaf(v0, sOW1[c0 * 3 + 1], fmaf(v1, sOW1[c0 * 3 + 4], p[slot * 3 + 1]));
                p[slot * 3 + 2] = fmaf(v0, sOW1[c0 * 3 + 2], fmaf(v1, sOW1[c0 * 3 + 5], p[slot * 3 + 2]));
            }
        }
    }

#pragma unroll
    for (int slot = 0; slot < 4; slot++) {
        int r = m0w + (slot >> 1) * 16 + (l >> 2) + (slot & 1) * 8;
#pragma unroll
        for (int j = 0; j < 3; j++) {
            float v = p[slot * 3 + j];
            v += __shfl_xor_sync(0xffffffffu, v, 1);
            v += __shfl_xor_sync(0xffffffffu, v, 2);
            if ((l & 3) == 0) atomicAdd(&pSM[r * 3 + j], v);
        }
    }
    __syncthreads();

    for (int i = tid; i < 192; i += 256) {
        int r = i / 3, j = i - r * 3;
        out[((size_t)(base + r)) * 3 + j] = pSM[i] + outb0[j] + outb1[j];
    }
}

// ============================================================================
extern "C" void kernel_launch(void* const* d_in, const int* in_sizes, int n_in,
                              void* d_out, int out_size)
{
    const float* coords = (const float*)d_in[0];
    const float* tokens = (const float*)d_in[1];
    const float* B_q    = (const float*)d_in[2];
    const float* B_l0   = (const float*)d_in[3];
    const float* B_l1   = (const float*)d_in[4];
    const float* qW     = (const float*)d_in[5];
    const float* qb     = (const float*)d_in[6];
    const float* toqW   = (const float*)d_in[7];
    const float* tokvW  = (const float*)d_in[8];
    const float* tooW   = (const float*)d_in[9];
    const float* toob   = (const float*)d_in[10];
    const float* bwW0   = (const float*)d_in[11];
    const float* bwb0   = (const float*)d_in[12];
    const float* bwW1   = (const float*)d_in[13];
    const float* bwb1   = (const float*)d_in[14];
    const float* modW0  = (const float*)d_in[15];
    const float* modb0  = (const float*)d_in[16];
    const float* modW1  = (const float*)d_in[17];
    const float* modb1  = (const float*)d_in[18];
    const float* hvW0   = (const float*)d_in[19];
    const float* hvb0   = (const float*)d_in[20];
    const float* outW0  = (const float*)d_in[21];
    const float* outb0  = (const float*)d_in[22];
    const float* outW1  = (const float*)d_in[23];
    const float* outb1  = (const float*)d_in[24];
    float* out = (float*)d_out;

    cudaFuncSetAttribute(k1_mma, cudaFuncAttributeMaxDynamicSharedMemorySize, SM1_TOTAL);
    cudaFuncSetAttribute(k3_fa,  cudaFuncAttributeMaxDynamicSharedMemorySize, 163840);
    cudaFuncSetAttribute(k5_mma, cudaFuncAttributeMaxDynamicSharedMemorySize, SMB_TOTAL);

    k0_prepw<<<dim3(256, 7), 256>>>(tooW, modW0, modW1, hvW0, toob, modb0, modb1,
                                    qW, bwW0, bwW1, toqW);
    k1_mma<<<HW / 64, 256, SM1_TOTAL>>>(coords, B_q, B_l0, B_l1, qb, bwb0, bwb1);
    k2_kv<<<dim3(MTOK / 16, BATCH), 256>>>(tokens, tokvW);
    k3_fa<<<dim3(HW / 128, 2, BATCH), 256, 163840>>>();
    k5_mma<<<(BATCH * HW) / 64, 256, SMB_TOTAL>>>(hvb0, outW0, outb0, outW1, outb1,
                                                  out);
}

// round 16
// speedup vs baseline: 2.5359x; 1.0265x over previous
#include <cuda_runtime.h>
#include <cuda_bf16.h>
#include <math.h>
#include <cstdint>

#define HW      16384
#define BATCH   4
#define MTOK    256
#define HD      256
#define INNER   128
#define DH      64

#define TWO_PI 6.2831853071795864769f

typedef unsigned long long u64;

// ---- cp.async helpers ------------------------------------------------------
__device__ __forceinline__ void cpa16(void* dst, const void* src) {
    unsigned d = (unsigned)__cvta_generic_to_shared(dst);
    asm volatile("cp.async.ca.shared.global [%0], [%1], 16;" :: "r"(d), "l"(src));
}
#define CPA_COMMIT() asm volatile("cp.async.commit_group;" ::: "memory")
#define CPA_WAIT0()  asm volatile("cp.async.wait_group 0;"  ::: "memory")
#define CPA_WAIT1()  asm volatile("cp.async.wait_group 1;"  ::: "memory")

// ---- mma.sync / ldmatrix helpers (baseline PTX, sm_80+) --------------------
__device__ __forceinline__ uint32_t smem_to_u32(const void* p) {
    uint32_t a;
    asm("{ .reg .u64 t; cvta.to.shared.u64 t, %1; cvt.u32.u64 %0, t; }" : "=r"(a) : "l"(p));
    return a;
}
__device__ __forceinline__ void ldsm4(uint32_t* r, uint32_t addr) {
    asm volatile("ldmatrix.sync.aligned.m8n8.x4.shared.b16 {%0,%1,%2,%3}, [%4];"
        : "=r"(r[0]), "=r"(r[1]), "=r"(r[2]), "=r"(r[3]) : "r"(addr));
}
__device__ __forceinline__ void ldsm2(uint32_t* r, uint32_t addr) {
    asm volatile("ldmatrix.sync.aligned.m8n8.x2.shared.b16 {%0,%1}, [%2];"
        : "=r"(r[0]), "=r"(r[1]) : "r"(addr));
}
__device__ __forceinline__ void mma16816(float* d, const uint32_t* a, const uint32_t* b) {
    asm volatile("mma.sync.aligned.m16n8k16.row.col.f32.bf16.bf16.f32 "
        "{%0,%1,%2,%3}, {%4,%5,%6,%7}, {%8,%9}, {%0,%1,%2,%3};"
        : "+f"(d[0]), "+f"(d[1]), "+f"(d[2]), "+f"(d[3])
        : "r"(a[0]), "r"(a[1]), "r"(a[2]), "r"(a[3]), "r"(b[0]), "r"(b[1]));
}

__device__ __forceinline__ int swz(int b) { return b ^ ((b >> 3) & 0x70); }

__device__ __forceinline__ void split2(float v0, float v1, uint32_t& hi, uint32_t& lo) {
    __nv_bfloat16 h0 = __float2bfloat16(v0), h1 = __float2bfloat16(v1);
    float r0 = v0 - __bfloat162float(h0);
    float r1 = v1 - __bfloat162float(h1);
    __nv_bfloat16 l0 = __float2bfloat16(r0), l1 = __float2bfloat16(r1);
    hi = ((uint32_t)__bfloat16_as_ushort(h1) << 16) | __bfloat16_as_ushort(h0);
    lo = ((uint32_t)__bfloat16_as_ushort(l1) << 16) | __bfloat16_as_ushort(l0);
}
__device__ __forceinline__ void split1(float v, __nv_bfloat16& h, __nv_bfloat16& l) {
    h = __float2bfloat16(v);
    l = __float2bfloat16(v - __bfloat162float(h));
}
__device__ __forceinline__ float bfu(unsigned short u) {
    __nv_bfloat16_raw r; r.x = u;
    return __bfloat162float(__nv_bfloat16(r));
}

// ---------------- scratch ---------------------------------------------------
__device__ float g_h0 [HW * HD];
__device__ float g_h1 [HW * HD];
__device__ float g_t  [HW];
__device__ float g_o  [BATCH * HW * INNER];
// weight images, 32KB packages (hi 16K + lo 16K), index (chunk*2 + nhalf):
//  [0,1]=W0'(tooW@modW0)  [2,3]=W1'  [4..7]=hvW0
//  [8]=qW(K=64)  [9]=bwW0  [10]=bwW1  [11..14]=toqW(256x128, nhalf 0 only)
__device__ __align__(128) uint8_t g_WB[15 * 2 * 32768];
__device__ float g_b0p[256];
__device__ float g_b1p[256];
// attention images
__device__ __align__(128) uint8_t g_qb[2 * 128 * 32768];
__device__ __align__(128) uint8_t g_kb[8 * 65536];
__device__ __align__(128) uint8_t g_vb[8 * 65536];

// ============================================================================
// K0: fold tooW@modW{0,1}; prep all split-bf16 swizzled weight images.
// ============================================================================
__global__ void k0_prepw(const float* __restrict__ tooW,
                         const float* __restrict__ modW0,
                         const float* __restrict__ modW1,
                         const float* __restrict__ hvW0,
                         const float* __restrict__ toob,
                         const float* __restrict__ modb0,
                         const float* __restrict__ modb1,
                         const float* __restrict__ qW,
                         const float* __restrict__ bwW0,
                         const float* __restrict__ bwW1,
                         const float* __restrict__ toqW)
{
    int m = blockIdx.y;           // 0..6
    int k = blockIdx.x;
    int n = threadIdx.x;
    float v;
    int chunk, nh, nrow;
    if (m < 2) {
        if (k >= 128) return;
        const float* modW = (m == 0) ? modW0 : modW1;
        float s = 0.f;
        for (int j = 0; j < 256; j++)
            s = fmaf(tooW[k * 256 + j], modW[j * 256 + n], s);
        v = s;
        chunk = m * 2 + (k >> 6);
        nh = n >> 7; nrow = n & 127;
        if (k == 0) {
            float bb = 0.f;
            for (int j = 0; j < 256; j++)
                bb = fmaf(toob[j], modW[j * 256 + n], bb);
            if (m == 0) g_b0p[n] = bb + modb0[n];
            else        g_b1p[n] = bb + modb1[n];
        }
    } else if (m == 2) {
        v = hvW0[k * 256 + n];
        chunk = 4 + (k >> 6); nh = n >> 7; nrow = n & 127;
    } else if (m == 3) {
        if (k >= 64) return;
        v = qW[k * 256 + n];
        chunk = 8; nh = n >> 7; nrow = n & 127;
    } else if (m == 4) {
        if (k >= 64) return;
        v = bwW0[k * 256 + n];
        chunk = 9; nh = n >> 7; nrow = n & 127;
    } else if (m == 5) {
        if (k >= 64) return;
        v = bwW1[k * 256 + n];
        chunk = 10; nh = n >> 7; nrow = n & 127;
    } else {
        if (n >= 128) return;
        v = toqW[k * 128 + n];
        chunk = 11 + (k >> 6); nh = 0; nrow = n;
    }
    __nv_bfloat16 h, l;
    split1(v, h, l);
    uint8_t* img = g_WB + ((size_t)chunk * 2 + nh) * 32768;
    int sw = swz(nrow * 128 + (k & 63) * 2);
    *(__nv_bfloat16*)(img + sw)         = h;
    *(__nv_bfloat16*)(img + 16384 + sw) = l;
}

// ============================================================================
// shared GEMM step (single accumulator) — used by k1 and k5 stage C.
// ============================================================================
__device__ __forceinline__ void run_gemm(char* smem, uint32_t sb, int Aoff, int loA,
                                         int mstart, int nch, int pass,
                                         int bufOff,
                                         int m0w, int n0p, int tid, int l,
                                         float* acc)
{
    {
        const uint8_t* src = g_WB + ((size_t)mstart * 2 + pass) * 32768;
        char* dst = smem + bufOff;
#pragma unroll
        for (int it = 0; it < 8; it++) {
            int i = (it * 256 + tid) * 16;
            cpa16(dst + i, src + i);
        }
        CPA_COMMIT();
    }
    for (int c = 0; c < nch; c++) {
        if (c + 1 < nch) {
            const uint8_t* src = g_WB + ((size_t)(mstart + c + 1) * 2 + pass) * 32768;
            char* dst = smem + bufOff + ((c + 1) & 1) * 32768;
#pragma unroll
            for (int it = 0; it < 8; it++) {
                int i = (it * 256 + tid) * 16;
                cpa16(dst + i, src + i);
            }
            CPA_COMMIT();
            CPA_WAIT1();
        } else {
            CPA_WAIT0();
        }
        __syncthreads();

        const uint32_t bB   = sb + bufOff + (c & 1) * 32768;
        const uint32_t bAhi = sb + Aoff + c * 8192;
        const uint32_t bAlo = bAhi + loA;

#pragma unroll
        for (int t4 = 0; t4 < 4; t4++) {
            uint32_t ahi[2][4], alo[2][4];
            const int arow = l & 15;
            const int akb  = t4 * 32 + (l >> 4) * 16;
#pragma unroll
            for (int mt = 0; mt < 2; mt++) {
                int ab = (m0w + mt * 16 + arow) * 128 + akb;
                int sw = swz(ab);
                ldsm4(ahi[mt], bAhi + sw);
                ldsm4(alo[mt], bAlo + sw);
            }
#pragma unroll
            for (int nt = 0; nt < 4; nt++) {
                const int nrow = n0p + nt * 8 + (l & 7);
                int bb = nrow * 128 + t4 * 32 + ((l >> 3) & 1) * 16;
                int sw = swz(bb);
                uint32_t bhi[2], blo[2];
                ldsm2(bhi, bB + sw);
                ldsm2(blo, bB + 16384 + sw);
                float* a0 = acc + (0 * 4 + nt) * 4;
                float* a1 = acc + (1 * 4 + nt) * 4;
                mma16816(a0, ahi[0], bhi);
                mma16816(a1, ahi[1], bhi);
                mma16816(a0, ahi[0], blo);
                mma16816(a1, ahi[1], blo);
                mma16816(a0, alo[0], bhi);
                mma16816(a1, alo[1], bhi);
            }
        }
        __syncthreads();
    }
}

// ============================================================================
// K1 mma: grid features on tensor cores (unchanged from R14).
// ============================================================================
#define SM1_FOUR  0
#define SM1_XQ    49152
#define SM1_B     114688
#define SM1_TOTAL 180224

__global__ void __launch_bounds__(256) k1_mma(
    const float* __restrict__ coords,
    const float* __restrict__ Bq,
    const float* __restrict__ Bl0,
    const float* __restrict__ Bl1,
    const float* __restrict__ qb,
    const float* __restrict__ bwb0,
    const float* __restrict__ bwb1)
{
    extern __shared__ uint8_t smemu[];
    char* smem = (char*)smemu;
    const uint32_t sb = smem_to_u32(smem);
    const int tid  = threadIdx.x;
    const int w    = tid >> 5;
    const int l    = tid & 31;
    const int m0w  = 32 * (w & 1);
    const int n0p  = 32 * (w >> 1);
    const int base = blockIdx.x * 64;

    for (int it = tid; it < 3 * 64 * 32; it += 256) {
        int mat = it >> 11;
        int rem = it & 2047;
        int r   = rem >> 5;
        int f   = rem & 31;
        float x = coords[(base + r) * 2 + 0];
        float y = coords[(base + r) * 2 + 1];
        const float* Bm = (mat == 0) ? Bq : (mat == 1 ? Bl0 : Bl1);
        float proj = TWO_PI * (x * Bm[f * 2] + y * Bm[f * 2 + 1]);
        float s, c;
        sincosf(proj, &s, &c);
        uint8_t* img = (uint8_t*)smem + SM1_FOUR + mat * 16384;
        __nv_bfloat16 hb, lb;
        split1(c, hb, lb);
        int sw = swz(r * 128 + f * 2);
        *(__nv_bfloat16*)(img + sw)        = hb;
        *(__nv_bfloat16*)(img + 8192 + sw) = lb;
        split1(s, hb, lb);
        sw = swz(r * 128 + (f + 32) * 2);
        *(__nv_bfloat16*)(img + sw)        = hb;
        *(__nv_bfloat16*)(img + 8192 + sw) = lb;
    }
    if (tid < 64) {
        float x = coords[(base + tid) * 2 + 0];
        float y = coords[(base + tid) * 2 + 1];
        int row = (int)(x * 16.0f); row = min(max(row, 0), 15);
        int col = (int)(y * 16.0f); col = min(max(col, 0), 15);
        g_t[base + tid] = (float)(row * 16 + col) * (1.0f / 256.0f);
    }
    __syncthreads();

    float acc[32];

#pragma unroll 1
    for (int pass = 0; pass < 2; pass++) {
#pragma unroll
        for (int i = 0; i < 32; i++) acc[i] = 0.f;
        run_gemm(smem, sb, SM1_FOUR, 8192, 8, 1, pass, SM1_B, m0w, n0p, tid, l, acc);
#pragma unroll
        for (int mt = 0; mt < 2; mt++)
#pragma unroll
        for (int nt = 0; nt < 4; nt++) {
            float* a = acc + (mt * 4 + nt) * 4;
            int c0 = pass * 128 + n0p + nt * 8 + (l & 3) * 2;
            int rA = m0w + mt * 16 + (l >> 2);
            float b0 = qb[c0], b1 = qb[c0 + 1];
            int kc = c0 >> 6;
            int bby = (c0 & 63) * 2;
#pragma unroll
            for (int half = 0; half < 2; half++) {
                int r = rA + half * 8;
                float v0 = fmaxf(a[half * 2 + 0] + b0, 0.f);
                float v1 = fmaxf(a[half * 2 + 1] + b1, 0.f);
                uint32_t hi, lo;
                split2(v0, v1, hi, lo);
                int sw = swz(r * 128 + bby);
                *(uint32_t*)(smem + SM1_XQ + kc * 8192 + sw)         = hi;
                *(uint32_t*)(smem + SM1_XQ + 32768 + kc * 8192 + sw) = lo;
            }
        }
    }
    __syncthreads();

    {
#pragma unroll
        for (int i = 0; i < 32; i++) acc[i] = 0.f;
        run_gemm(smem, sb, SM1_XQ, 32768, 11, 4, 0, SM1_B, m0w, n0p, tid, l, acc);
        const int tile = base >> 7;
        const int rb   = base & 127;
#pragma unroll
        for (int mt = 0; mt < 2; mt++)
#pragma unroll
        for (int nt = 0; nt < 4; nt++) {
            float* a = acc + (mt * 4 + nt) * 4;
            int c0 = n0p + nt * 8 + (l & 3) * 2;
            int h = c0 >> 6, d = c0 & 63;
            uint8_t* img = g_qb + (size_t)(h * 128 + tile) * 32768;
            int rA = m0w + mt * 16 + (l >> 2);
#pragma unroll
            for (int half = 0; half < 2; half++) {
                int rr = rb + rA + half * 8;
                float v0 = a[half * 2 + 0] * 0.125f;
                float v1 = a[half * 2 + 1] * 0.125f;
                uint32_t hi, lo;
                split2(v0, v1, hi, lo);
                int sw = swz(rr * 128 + d * 2);
                *(uint32_t*)(img + sw)         = hi;
                *(uint32_t*)(img + 16384 + sw) = lo;
            }
        }
    }

#pragma unroll 1
    for (int mat = 0; mat < 2; mat++) {
        const float* bw = mat ? bwb1 : bwb0;
        float* gh = mat ? g_h1 : g_h0;
#pragma unroll 1
        for (int pass = 0; pass < 2; pass++) {
#pragma unroll
            for (int i = 0; i < 32; i++) acc[i] = 0.f;
            run_gemm(smem, sb, SM1_FOUR + 16384 + mat * 16384, 8192, 9 + mat, 1, pass,
                     SM1_B, m0w, n0p, tid, l, acc);
#pragma unroll
            for (int mt = 0; mt < 2; mt++)
#pragma unroll
            for (int nt = 0; nt < 4; nt++) {
                float* a = acc + (mt * 4 + nt) * 4;
                int c0 = pass * 128 + n0p + nt * 8 + (l & 3) * 2;
                int rA = m0w + mt * 16 + (l >> 2);
                float b0 = bw[c0], b1 = bw[c0 + 1];
#pragma unroll
                for (int half = 0; half < 2; half++) {
                    int r = rA + half * 8;
                    float2 v;
                    v.x = fmaxf(a[half * 2 + 0] + b0, 0.f);
                    v.y = fmaxf(a[half * 2 + 1] + b1, 0.f);
                    *(float2*)&gh[(size_t)(base + r) * 256 + c0] = v;
                }
            }
        }
    }
}

// ============================================================================
// K2: kv = tokens @ tokvW -> split-bf16 swizzled k / v^T images (unchanged).
// ============================================================================
__global__ void k2_kv(const float* __restrict__ tokens,
                      const float* __restrict__ tokvW)
{
    __shared__ float tok[16][256];
    const int tile = blockIdx.x;
    const int b    = blockIdx.y;
    const int tid  = threadIdx.x;

    const float* tb = tokens + (b * MTOK + tile * 16) * 256;
    for (int i = tid; i < 16 * 256; i += 256) tok[i >> 8][i & 255] = tb[i];
    __syncthreads();

    const int j = tid;
    float acc[16];
#pragma unroll
    for (int r = 0; r < 16; r++) acc[r] = 0.f;
    for (int k = 0; k < 256; k++) {
        float w = tokvW[k * 256 + j];
#pragma unroll
        for (int r = 0; r < 16; r++) acc[r] = fmaf(tok[r][k], w, acc[r]);
    }
#pragma unroll
    for (int r = 0; r < 16; r++) {
        int m = tile * 16 + r;
        float v = acc[r];
        __nv_bfloat16 hb, lb;
        split1(v, hb, lb);
        if (j < 128) {
            int h = j >> 6, d = j & 63;
            uint8_t* img = g_kb + (size_t)(b * 2 + h) * 65536;
            int sw = swz(m * 128 + d * 2);
            *(__nv_bfloat16*)(img + sw)         = hb;
            *(__nv_bfloat16*)(img + 32768 + sw) = lb;
        } else {
            int h = (j - 128) >> 6, d = (j - 128) & 63;
            uint8_t* img = g_vb + (size_t)(b * 2 + h) * 65536;
            int off = (m >> 6) * 8192 + swz(d * 128 + (m & 63) * 2);
            *(__nv_bfloat16*)(img + off)         = hb;
            *(__nv_bfloat16*)(img + 32768 + off) = lb;
        }
    }
}

// ============================================================================
// K3 flash-mma attention (unchanged from R13).
// ============================================================================
__global__ void __launch_bounds__(256) k3_fa()
{
    extern __shared__ uint8_t smem[];
    const uint32_t sb = smem_to_u32(smem);
    const int tid = threadIdx.x;
    const int w   = tid >> 5;
    const int l   = tid & 31;
    const int bx  = blockIdx.x;
    const int h   = blockIdx.y;
    const int b   = blockIdx.z;

    {
        const uint8_t* qsrc = g_qb + (size_t)(h * 128 + bx) * 32768;
        const uint8_t* ksrc = g_kb + (size_t)(b * 2 + h) * 65536;
        const uint8_t* vsrc = g_vb + (size_t)(b * 2 + h) * 65536;
        for (int i = tid; i < 2048; i += 256) cpa16(smem + i * 16, qsrc + i * 16);
        for (int i = tid; i < 4096; i += 256) cpa16(smem + 32768 + i * 16, ksrc + i * 16);
        for (int i = tid; i < 4096; i += 256) cpa16(smem + 98304 + i * 16, vsrc + i * 16);
        CPA_COMMIT();
        CPA_WAIT0();
        __syncthreads();
    }
    const uint32_t sQh = sb,          sQl = sb + 16384;
    const uint32_t sKh = sb + 32768,  sKl = sb + 65536;
    const uint32_t sVh = sb + 98304,  sVl = sb + 131072;

    const int r0 = bx * 128 + w * 16 + (l >> 2);
    const float tt0 = g_t[r0];
    const float tt1 = g_t[r0 + 8];

    float O[32];
#pragma unroll
    for (int i = 0; i < 32; i++) O[i] = 0.f;
    float Mx0 = -1e30f, Mx1 = -1e30f, S0 = 0.f, S1 = 0.f;

    const int aQrow = (w * 16 + (l & 15)) * 128 + (l >> 4) * 16;

#pragma unroll 1
    for (int t = 0; t < 4; t++) {
        float Sa[32];
#pragma unroll
        for (int i = 0; i < 32; i++) Sa[i] = 0.f;

#pragma unroll
        for (int kk = 0; kk < 4; kk++) {
            int asw = swz(aQrow + kk * 32);
            uint32_t ahi[4], alo[4];
            ldsm4(ahi, sQh + asw);
            ldsm4(alo, sQl + asw);
#pragma unroll
            for (int nt = 0; nt < 8; nt++) {
                int bsw = swz((t * 64 + nt * 8 + (l & 7)) * 128 + kk * 32 + ((l >> 3) & 1) * 16);
                uint32_t bhi[2], blo[2];
                ldsm2(bhi, sKh + bsw);
                ldsm2(blo, sKl + bsw);
                mma16816(&Sa[nt * 4], ahi, bhi);
                mma16816(&Sa[nt * 4], ahi, blo);
                mma16816(&Sa[nt * 4], alo, bhi);
            }
        }

        float tm0 = -1e30f, tm1 = -1e30f;
#pragma unroll
        for (int nt = 0; nt < 8; nt++) {
            float* a = &Sa[nt * 4];
            float c0 = (float)(t * 64 + nt * 8 + (l & 3) * 2);
            float p0 = (c0 + 0.5f) * (1.0f / 256.0f);
            float p1 = (c0 + 1.5f) * (1.0f / 256.0f);
            float d00 = tt0 - p0, d01 = tt0 - p1;
            float d10 = tt1 - p0, d11 = tt1 - p1;
            a[0] -= 10.f * d00 * d00;
            a[1] -= 10.f * d01 * d01;
            a[2] -= 10.f * d10 * d10;
            a[3] -= 10.f * d11 * d11;
            tm0 = fmaxf(tm0, fmaxf(a[0], a[1]));
            tm1 = fmaxf(tm1, fmaxf(a[2], a[3]));
        }
        tm0 = fmaxf(tm0, __shfl_xor_sync(0xffffffffu, tm0, 1));
        tm0 = fmaxf(tm0, __shfl_xor_sync(0xffffffffu, tm0, 2));
        tm1 = fmaxf(tm1, __shfl_xor_sync(0xffffffffu, tm1, 1));
        tm1 = fmaxf(tm1, __shfl_xor_sync(0xffffffffu, tm1, 2));
        float nM0 = fmaxf(Mx0, tm0), nM1 = fmaxf(Mx1, tm1);
        float cr0 = __expf(Mx0 - nM0), cr1 = __expf(Mx1 - nM1);
        Mx0 = nM0; Mx1 = nM1;
        S0 *= cr0; S1 *= cr1;
#pragma unroll
        for (int nt = 0; nt < 8; nt++) {
            O[nt * 4 + 0] *= cr0; O[nt * 4 + 1] *= cr0;
            O[nt * 4 + 2] *= cr1; O[nt * 4 + 3] *= cr1;
        }
#pragma unroll
        for (int nt = 0; nt < 8; nt++) {
            float* a = &Sa[nt * 4];
            a[0] = __expf(a[0] - Mx0);
            a[1] = __expf(a[1] - Mx0);
            a[2] = __expf(a[2] - Mx1);
            a[3] = __expf(a[3] - Mx1);
            S0 += a[0] + a[1];
            S1 += a[2] + a[3];
        }

#pragma unroll
        for (int kk = 0; kk < 4; kk++) {
            uint32_t phi[4], plo[4];
            float* pA = &Sa[(2 * kk) * 4];
            float* pB = &Sa[(2 * kk + 1) * 4];
            split2(pA[0], pA[1], phi[0], plo[0]);
            split2(pA[2], pA[3], phi[1], plo[1]);
            split2(pB[0], pB[1], phi[2], plo[2]);
            split2(pB[2], pB[3], phi[3], plo[3]);
#pragma unroll
            for (int nt = 0; nt < 8; nt++) {
                int vsw = t * 8192 + swz((nt * 8 + (l & 7)) * 128 + kk * 32 + ((l >> 3) & 1) * 16);
                uint32_t vhi[2], vlo[2];
                ldsm2(vhi, sVh + vsw);
                ldsm2(vlo, sVl + vsw);
                mma16816(&O[nt * 4], phi, vhi);
                mma16816(&O[nt * 4], phi, vlo);
                mma16816(&O[nt * 4], plo, vhi);
            }
        }
    }

    S0 += __shfl_xor_sync(0xffffffffu, S0, 1);
    S0 += __shfl_xor_sync(0xffffffffu, S0, 2);
    S1 += __shfl_xor_sync(0xffffffffu, S1, 1);
    S1 += __shfl_xor_sync(0xffffffffu, S1, 2);
    float inv0 = 1.0f / S0, inv1 = 1.0f / S1;
#pragma unroll
    for (int nt = 0; nt < 8; nt++) {
        int col = h * 64 + nt * 8 + (l & 3) * 2;
        float2 o0, o1;
        o0.x = O[nt * 4 + 0] * inv0; o0.y = O[nt * 4 + 1] * inv0;
        o1.x = O[nt * 4 + 2] * inv1; o1.y = O[nt * 4 + 3] * inv1;
        *(float2*)&g_o[((size_t)b * HW + r0) * 128 + col]       = o0;
        *(float2*)&g_o[((size_t)b * HW + r0 + 8) * 128 + col]   = o1;
    }
}

// ============================================================================
// K5 v3: fused dual stage A+B (one pass over o computes both m0-pre and
// m1-pre; x = m0+m1 computed in registers), then stage C. Output projections
// folded into the fused epilogue and stage C epilogue.
// ============================================================================
#define SMB_O     0
#define SMB_X     32768
#define SMB_B     98304
#define SMB_CONST 163840
#define SMB_PSM   173056
#define SMB_TOTAL 173824

__global__ void __launch_bounds__(256, 1) k5_mma(
    const float* __restrict__ hvb0,
    const float* __restrict__ outW0, const float* __restrict__ outb0,
    const float* __restrict__ outW1, const float* __restrict__ outb1,
    float* __restrict__ out)
{
    extern __shared__ char smemc[];
    char* smem = smemc;
    const uint32_t sb = smem_to_u32(smem);
    const int tid  = threadIdx.x;
    const int w    = tid >> 5;
    const int l    = tid & 31;
    const int m0w  = 32 * (w & 1);
    const int n0p  = 32 * (w >> 1);
    const int tile = blockIdx.x >> 2;
    const int bat  = blockIdx.x & 3;
    const int base = bat * HW + tile * 64;
    const int hb   = tile * 64;

    float* sC   = (float*)(smem + SMB_CONST);
    float* sB0  = sC;
    float* sB1  = sC + 256;
    float* sHvb = sC + 512;
    float* sOW0 = sC + 768;
    float* sOW1 = sC + 1536;
    float* pSM  = (float*)(smem + SMB_PSM);

    for (int i = tid; i < 256; i += 256) {
        sB0[i]  = g_b0p[i];
        sB1[i]  = g_b1p[i];
        sHvb[i] = hvb0[i];
    }
    for (int i = tid; i < 768; i += 256) {
        sOW0[i] = outW0[i];
        sOW1[i] = outW1[i];
    }
    for (int i = tid; i < 192; i += 256) pSM[i] = 0.f;

    for (int i = tid; i < 64 * 64; i += 256) {
        int r  = i >> 6;
        int kp = i & 63;
        int k  = kp * 2;
        float2 v = *(const float2*)&g_o[((size_t)(base + r)) * 128 + k];
        uint32_t hi, lo;
        split2(v.x, v.y, hi, lo);
        int kc = k >> 6;
        int sw = swz(r * 128 + (k & 63) * 2);
        *(uint32_t*)(smem + SMB_O + kc * 8192 + sw)         = hi;
        *(uint32_t*)(smem + SMB_O + 16384 + kc * 8192 + sw) = lo;
    }
    __syncthreads();

    float p[12];
#pragma unroll
    for (int i = 0; i < 12; i++) p[i] = 0.f;

    // ===== fused stage A+B: acc0 = o@W0', acc1 = o@W1' (shared A frags) =====
#pragma unroll 1
    for (int pass = 0; pass < 2; pass++) {
        float a0[32], a1[32];
#pragma unroll
        for (int i = 0; i < 32; i++) { a0[i] = 0.f; a1[i] = 0.f; }

#pragma unroll 1
        for (int c = 0; c < 2; c++) {
            // load W0' chunk c into SMB_B, W1' chunk c into SMB_B+32768
            {
                const uint8_t* s0 = g_WB + ((size_t)(0 + c) * 2 + pass) * 32768;
                const uint8_t* s1 = g_WB + ((size_t)(2 + c) * 2 + pass) * 32768;
#pragma unroll
                for (int it = 0; it < 8; it++) {
                    int i = (it * 256 + tid) * 16;
                    cpa16(smem + SMB_B + i, s0 + i);
                    cpa16(smem + SMB_B + 32768 + i, s1 + i);
                }
                CPA_COMMIT();
                CPA_WAIT0();
                __syncthreads();
            }
            const uint32_t bB0  = sb + SMB_B;
            const uint32_t bB1  = sb + SMB_B + 32768;
            const uint32_t bAhi = sb + SMB_O + c * 8192;
            const uint32_t bAlo = bAhi + 16384;

#pragma unroll
            for (int t4 = 0; t4 < 4; t4++) {
                uint32_t ahi[2][4], alo[2][4];
                const int arow = l & 15;
                const int akb  = t4 * 32 + (l >> 4) * 16;
#pragma unroll
                for (int mt = 0; mt < 2; mt++) {
                    int sw = swz((m0w + mt * 16 + arow) * 128 + akb);
                    ldsm4(ahi[mt], bAhi + sw);
                    ldsm4(alo[mt], bAlo + sw);
                }
#pragma unroll
                for (int nt = 0; nt < 4; nt++) {
                    const int nrow = n0p + nt * 8 + (l & 7);
                    int sw = swz(nrow * 128 + t4 * 32 + ((l >> 3) & 1) * 16);
                    uint32_t bhi[2], blo[2];
                    // W0'
                    ldsm2(bhi, bB0 + sw);
                    ldsm2(blo, bB0 + 16384 + sw);
                    float* q0 = a0 + (0 * 4 + nt) * 4;
                    float* q1 = a0 + (1 * 4 + nt) * 4;
                    mma16816(q0, ahi[0], bhi);
                    mma16816(q1, ahi[1], bhi);
                    mma16816(q0, ahi[0], blo);
                    mma16816(q1, ahi[1], blo);
                    mma16816(q0, alo[0], bhi);
                    mma16816(q1, alo[1], bhi);
                    // W1'
                    ldsm2(bhi, bB1 + sw);
                    ldsm2(blo, bB1 + 16384 + sw);
                    q0 = a1 + (0 * 4 + nt) * 4;
                    q1 = a1 + (1 * 4 + nt) * 4;
                    mma16816(q0, ahi[0], bhi);
                    mma16816(q1, ahi[1], bhi);
                    mma16816(q0, ahi[0], blo);
                    mma16816(q1, ahi[1], blo);
                    mma16816(q0, alo[0], bhi);
                    mma16816(q1, alo[1], bhi);
                }
            }
            __syncthreads();
        }

        // fused epilogue: m0, m1 in regs; x = m0+m1 -> SMB_X; proj OW0 on m0
#pragma unroll
        for (int mt = 0; mt < 2; mt++)
#pragma unroll
        for (int nt = 0; nt < 4; nt++) {
            float* qa = a0 + (mt * 4 + nt) * 4;
            float* qb2 = a1 + (mt * 4 + nt) * 4;
            int c0 = pass * 128 + n0p + nt * 8 + (l & 3) * 2;
            int rA = m0w + mt * 16 + (l >> 2);
            float b00 = sB0[c0], b01 = sB0[c0 + 1];
            float b10 = sB1[c0], b11 = sB1[c0 + 1];
            int kc = c0 >> 6;
            int bby = (c0 & 63) * 2;
#pragma unroll
            for (int half = 0; half < 2; half++) {
                int r = rA + half * 8;
                float2 h0 = *(const float2*)&g_h0[((size_t)(hb + r)) * 256 + c0];
                float2 h1 = *(const float2*)&g_h1[((size_t)(hb + r)) * 256 + c0];
                float m00 = fmaxf(h0.x + qa[half * 2 + 0] + b00, 0.f);
                float m01 = fmaxf(h0.y + qa[half * 2 + 1] + b01, 0.f);
                float m10 = fmaxf(h1.x + qb2[half * 2 + 0] + b10, 0.f);
                float m11 = fmaxf(h1.y + qb2[half * 2 + 1] + b11, 0.f);
                int slot = mt * 2 + half;
                p[slot * 3 + 0] = fmaf(m00, sOW0[c0 * 3 + 0], fmaf(m01, sOW0[c0 * 3 + 3], p[slot * 3 + 0]));
                p[slot * 3 + 1] = fmaf(m00, sOW0[c0 * 3 + 1], fmaf(m01, sOW0[c0 * 3 + 4], p[slot * 3 + 1]));
                p[slot * 3 + 2] = fmaf(m00, sOW0[c0 * 3 + 2], fmaf(m01, sOW0[c0 * 3 + 5], p[slot * 3 + 2]));
                float x0 = m00 + m10;
                float x1 = m01 + m11;
                uint32_t hi, lo;
                split2(x0, x1, hi, lo);
                int sw = swz(r * 128 + bby);
                *(uint32_t*)(smem + SMB_X + kc * 8192 + sw)         = hi;
                *(uint32_t*)(smem + SMB_X + 32768 + kc * 8192 + sw) = lo;
            }
        }
        __syncthreads();
    }

    // ===== stage C: hv1 = relu(x@hvW0 + b); proj OW1 ========================
    float acc[32];
#pragma unroll 1
    for (int pass = 0; pass < 2; pass++) {
#pragma unroll
        for (int i = 0; i < 32; i++) acc[i] = 0.f;
        run_gemm(smem, sb, SMB_X, 32768, 4, 4, pass, SMB_B, m0w, n0p, tid, l, acc);
#pragma unroll
        for (int mt = 0; mt < 2; mt++)
#pragma unroll
        for (int nt = 0; nt < 4; nt++) {
            float* a = acc + (mt * 4 + nt) * 4;
            int c0 = pass * 128 + n0p + nt * 8 + (l & 3) * 2;
            float b0 = sHvb[c0], b1 = sHvb[c0 + 1];
#pragma unroll
            for (int half = 0; half < 2; half++) {
                float v0 = fmaxf(a[half * 2 + 0] + b0, 0.f);
                float v1 = fmaxf(a[half * 2 + 1] + b1, 0.f);
                int slot = mt * 2 + half;
                p[slot * 3 + 0] = fmaf(v0, sOW1[c0 * 3 + 0], fmaf(v1, sOW1[c0 * 3 + 3], p[slot * 3 + 0]));
                p[slot * 3 + 1] = fmaf(v0, sOW1[c0 * 3 + 1], fmaf(v1, sOW1[c0 * 3 + 4], p[slot * 3 + 1]));
                p[slot * 3 + 2] = fmaf(v0, sOW1[c0 * 3 + 2], fmaf(v1, sOW1[c0 * 3 + 5], p[slot * 3 + 2]));
            }
        }
    }

#pragma unroll
    for (int slot = 0; slot < 4; slot++) {
        int r = m0w + (slot >> 1) * 16 + (l >> 2) + (slot & 1) * 8;
#pragma unroll
        for (int j = 0; j < 3; j++) {
            float v = p[slot * 3 + j];
            v += __shfl_xor_sync(0xffffffffu, v, 1);
            v += __shfl_xor_sync(0xffffffffu, v, 2);
            if ((l & 3) == 0) atomicAdd(&pSM[r * 3 + j], v);
        }
    }
    __syncthreads();

    for (int i = tid; i < 192; i += 256) {
        int r = i / 3, j = i - r * 3;
        out[((size_t)(base + r)) * 3 + j] = pSM[i] + outb0[j] + outb1[j];
    }
}

// ============================================================================
extern "C" void kernel_launch(void* const* d_in, const int* in_sizes, int n_in,
                              void* d_out, int out_size)
{
    const float* coords = (const float*)d_in[0];
    const float* tokens = (const float*)d_in[1];
    const float* B_q    = (const float*)d_in[2];
    const float* B_l0   = (const float*)d_in[3];
    const float* B_l1   = (const float*)d_in[4];
    const float* qW     = (const float*)d_in[5];
    const float* qb     = (const float*)d_in[6];
    const float* toqW   = (const float*)d_in[7];
    const float* tokvW  = (const float*)d_in[8];
    const float* tooW   = (const float*)d_in[9];
    const float* toob   = (const float*)d_in[10];
    const float* bwW0   = (const float*)d_in[11];
    const float* bwb0   = (const float*)d_in[12];
    const float* bwW1   = (const float*)d_in[13];
    const float* bwb1   = (const float*)d_in[14];
    const float* modW0  = (const float*)d_in[15];
    const float* modb0  = (const float*)d_in[16];
    const float* modW1  = (const float*)d_in[17];
    const float* modb1  = (const float*)d_in[18];
    const float* hvW0   = (const float*)d_in[19];
    const float* hvb0   = (const float*)d_in[20];
    const float* outW0  = (const float*)d_in[21];
    const float* outb0  = (const float*)d_in[22];
    const float* outW1  = (const float*)d_in[23];
    const float* outb1  = (const float*)d_in[24];
    float* out = (float*)d_out;

    cudaFuncSetAttribute(k1_mma, cudaFuncAttributeMaxDynamicSharedMemorySize, SM1_TOTAL);
    cudaFuncSetAttribute(k3_fa,  cudaFuncAttributeMaxDynamicSharedMemorySize, 163840);
    cudaFuncSetAttribute(k5_mma, cudaFuncAttributeMaxDynamicSharedMemorySize, SMB_TOTAL);

    k0_prepw<<<dim3(256, 7), 256>>>(tooW, modW0, modW1, hvW0, toob, modb0, modb1,
                                    qW, bwW0, bwW1, toqW);
    k1_mma<<<HW / 64, 256, SM1_TOTAL>>>(coords, B_q, B_l0, B_l1, qb, bwb0, bwb1);
    k2_kv<<<dim3(MTOK / 16, BATCH), 256>>>(tokens, tokvW);
    k3_fa<<<dim3(HW / 128, 2, BATCH), 256, 163840>>>();
    k5_mma<<<(BATCH * HW) / 64, 256, SMB_TOTAL>>>(hvb0, outW0, outb0, outW1, outb1,
                                                  out);
}